// round 6
// baseline (speedup 1.0000x reference)
#include <cuda_runtime.h>
#include <cuda_bf16.h>
#include <math.h>
#include <cstdint>

#define BATCH 4
#define CH    96
#define HRES  256
#define WRES  256
#define HW    65536
#define HEADS 3
#define HD    32
#define NPOS  64
#define NWIN  4096
#define QSCALE 0.17677669529663687f
#define WPAD  104   // padded row length (bf16) -> 208B stride, ldmatrix conflict-free

// ---------------- mma.sync / ldmatrix helpers (sm_80+ PTX, valid on compute_103)
#define LDM_X4(r, addr) \
    asm volatile("ldmatrix.sync.aligned.m8n8.x4.shared.b16 {%0,%1,%2,%3}, [%4];" \
        : "=r"((r)[0]), "=r"((r)[1]), "=r"((r)[2]), "=r"((r)[3]) : "r"(addr))
#define LDM_X2(r, addr) \
    asm volatile("ldmatrix.sync.aligned.m8n8.x2.shared.b16 {%0,%1}, [%2];" \
        : "=r"((r)[0]), "=r"((r)[1]) : "r"(addr))
#define MMA_BF16(d, a, b) \
    asm volatile("mma.sync.aligned.m16n8k16.row.col.f32.bf16.bf16.f32 " \
        "{%0,%1,%2,%3}, {%4,%5,%6,%7}, {%8,%9}, {%0,%1,%2,%3};" \
        : "+f"((d)[0]), "+f"((d)[1]), "+f"((d)[2]), "+f"((d)[3]) \
        : "r"((a)[0]), "r"((a)[1]), "r"((a)[2]), "r"((a)[3]), \
          "r"((b)[0]), "r"((b)[1]))

__device__ __forceinline__ uint32_t smem_u32(const void* p) {
    uint32_t a;
    asm("{ .reg .u64 t; cvta.to.shared.u64 t, %1; cvt.u32.u64 %0, t; }"
        : "=r"(a) : "l"(p));
    return a;
}

// ---------------- scratch (device globals; no runtime allocation) ----------
__device__ float g_V   [BATCH*CH*HW];
__device__ float g_conv[BATCH*CH*HW];
__device__ float g_q   [NWIN*HEADS*HD*NPOS];   // [win][head][d][n]
__device__ float g_k   [NWIN*HEADS*HD*NPOS];   // [win][head][d][m]
__device__ float g_v   [NWIN*HEADS*NPOS*HD];   // [win][head][m][d]
__device__ float g_att [BATCH*HW*CH];
__device__ float g_bias[HEADS*NPOS*NPOS];      // [head][n][m]
__device__ __align__(16) __nv_bfloat16 g_Whi[288*WPAD];
__device__ __align__(16) __nv_bfloat16 g_Wlo[288*WPAD];

// ---------------- kernel P: split W into bf16 hi/lo padded blobs -----------
__global__ void prep_kernel(const float* __restrict__ Wqk,
                            const float* __restrict__ Wv)
{
    int idx = blockIdx.x * 256 + threadIdx.x;
    if (idx >= 288*WPAD) return;
    int o = idx / WPAD, k = idx % WPAD;
    float w = 0.f;
    if (k < 96) {
        if (o < 96)        w = Wqk[o*96 + k] * QSCALE;   // fold Q scale
        else if (o < 192)  w = Wqk[o*96 + k];
        else               w = Wv[(o - 192)*96 + k];
    }
    __nv_bfloat16 hi = __float2bfloat16_rn(w);
    __nv_bfloat16 lo = __float2bfloat16_rn(w - __bfloat162float(hi));
    g_Whi[idx] = hi;
    g_Wlo[idx] = lo;
}

// ---------------- kernel B: bias MLP table ---------------------------------
__global__ void bias_kernel(const float* __restrict__ Wm1, const float* __restrict__ bm1,
                            const float* __restrict__ Wm2, const float* __restrict__ bm2)
{
    int gid = blockIdx.x * 256 + threadIdx.x;
    int n = gid >> 6, m = gid & 63;
    float r0 = (float)((n >> 3) - (m >> 3));
    float r1 = (float)((n & 7)  - (m & 7));
    r0 = copysignf(log1pf(fabsf(r0)), r0);
    r1 = copysignf(log1pf(fabsf(r1)), r1);
    float a0 = bm2[0], a1 = bm2[1], a2 = bm2[2];
    for (int j = 0; j < 256; j++) {
        float h = fmaf(r0, Wm1[j], fmaf(r1, Wm1[256 + j], bm1[j]));
        h = fmaxf(h, 0.f);
        a0 = fmaf(h, Wm2[j*3 + 0], a0);
        a1 = fmaf(h, Wm2[j*3 + 1], a1);
        a2 = fmaf(h, Wm2[j*3 + 2], a2);
    }
    g_bias[0*4096 + gid] = a0;
    g_bias[1*4096 + gid] = a1;
    g_bias[2*4096 + gid] = a2;
}

// ---------------- kernel A: QKV GEMM via mma.sync bf16 3-term split --------
// Block = 128 px x 288 outs. 8 warps; warp owns 16 px. N processed as 3
// chunks of 96 (Q, K, V). A frags held in regs across chunks.
__global__ __launch_bounds__(256) void qkv_mma_kernel(
    const float* __restrict__ x,
    const float* __restrict__ bqk, const float* __restrict__ bv)
{
    extern __shared__ __align__(16) unsigned char dsm[];
    __nv_bfloat16* whi_s = (__nv_bfloat16*)dsm;            // [288*WPAD]
    __nv_bfloat16* wlo_s = whi_s + 288*WPAD;
    __nv_bfloat16* xhi_s = wlo_s + 288*WPAD;               // [128*WPAD]
    __nv_bfloat16* xlo_s = xhi_s + 128*WPAD;
    float* out_s = (float*)(wlo_s + 288*WPAD);             // overlays x area [128][97]

    int tid  = threadIdx.x;
    int warp = tid >> 5, lane = tid & 31;
    int blk  = blockIdx.x;
    int b    = blk >> 9;
    int hw0  = (blk & 511) << 7;     // 128 consecutive px in one row

    // cooperative load of pre-split W blobs (flat uint4 copy)
    {
        const uint4* s1 = (const uint4*)g_Whi; uint4* d1 = (uint4*)whi_s;
        const uint4* s2 = (const uint4*)g_Wlo; uint4* d2 = (uint4*)wlo_s;
        #pragma unroll 4
        for (int i = tid; i < 288*WPAD*2/16; i += 256) { d1[i] = s1[i]; d2[i] = s2[i]; }
    }
    // load X (coalesced float4), split hi/lo, store [px][k] padded
    for (int idx = tid; idx < 96*32; idx += 256) {
        int k = idx >> 5, pq = idx & 31;
        float4 v = *(const float4*)&x[(b*96 + k)*HW + hw0 + pq*4];
        float vf[4] = {v.x, v.y, v.z, v.w};
        #pragma unroll
        for (int j = 0; j < 4; j++) {
            int px = pq*4 + j;
            __nv_bfloat16 hi = __float2bfloat16_rn(vf[j]);
            __nv_bfloat16 lo = __float2bfloat16_rn(vf[j] - __bfloat162float(hi));
            xhi_s[px*WPAD + k] = hi;
            xlo_s[px*WPAD + k] = lo;
        }
    }
    __syncthreads();

    // A fragments: warp's 16 px x K=96 (6 k-steps), hi + lo
    uint32_t ahi[6][4], alo[6][4];
    {
        int idx8 = lane & 7, quad = lane >> 3;
        int arow = warp*16 + (quad & 1)*8 + idx8;
        int acol = (quad >> 1)*8;
        #pragma unroll
        for (int ks = 0; ks < 6; ks++) {
            uint32_t ah = smem_u32(&xhi_s[arow*WPAD + ks*16 + acol]);
            uint32_t al = smem_u32(&xlo_s[arow*WPAD + ks*16 + acol]);
            LDM_X4(ahi[ks], ah);
            LDM_X4(alo[ks], al);
        }
    }
    __syncthreads();   // x area free -> reusable as out_s

    // writeout coords (computed once)
    int pq  = tid & 31;
    int p0  = pq*4;
    int hwp = hw0 + p0;
    int h_  = hwp >> 8, w_ = hwp & 255;
    int hp  = (h_ + 252) & 255;
    int wp  = (w_ + 252) & 255;
    int wh  = hp >> 3, ww = wp >> 3;
    int win = b*1024 + wh*32 + ww;
    int n   = (hp & 7)*8 + (wp & 7);
    int c0  = tid >> 5;
    int whn = win*3;

    int brow = lane & 7;
    int bcol = ((lane >> 3) & 1)*8;

    #pragma unroll 1
    for (int g = 0; g < 3; g++) {
        float acc[12][4];
        #pragma unroll
        for (int nt = 0; nt < 12; nt++)
            #pragma unroll
            for (int j = 0; j < 4; j++) acc[nt][j] = 0.f;

        int n_base = g*96;
        #pragma unroll 1
        for (int ks = 0; ks < 6; ks++) {
            uint32_t bh[12][2];
            #pragma unroll
            for (int nt = 0; nt < 12; nt++) {
                uint32_t ad = smem_u32(&whi_s[(n_base + nt*8 + brow)*WPAD + ks*16 + bcol]);
                LDM_X2(bh[nt], ad);
            }
            #pragma unroll
            for (int nt = 0; nt < 12; nt++) {
                MMA_BF16(acc[nt], ahi[ks], bh[nt]);   // hi*hi
                MMA_BF16(acc[nt], alo[ks], bh[nt]);   // lo*hi
            }
            #pragma unroll
            for (int nt = 0; nt < 12; nt++) {
                uint32_t bl[2];
                uint32_t ad = smem_u32(&wlo_s[(n_base + nt*8 + brow)*WPAD + ks*16 + bcol]);
                LDM_X2(bl, ad);
                MMA_BF16(acc[nt], ahi[ks], bl);       // hi*lo
            }
        }

        // stage accum -> out_s [px][97]
        {
            int orow = warp*16 + (lane >> 2);
            int oc   = (lane & 3)*2;
            #pragma unroll
            for (int nt = 0; nt < 12; nt++) {
                out_s[orow*97 + nt*8 + oc]         = acc[nt][0];
                out_s[orow*97 + nt*8 + oc + 1]     = acc[nt][1];
                out_s[(orow+8)*97 + nt*8 + oc]     = acc[nt][2];
                out_s[(orow+8)*97 + nt*8 + oc + 1] = acc[nt][3];
            }
        }
        __syncthreads();

        // cooperative coalesced writeout
        #pragma unroll 1
        for (int j = 0; j < 12; j++) {
            int c = c0 + j*8;
            int head = c >> 5, d = c & 31;
            float v0 = out_s[(p0    )*97 + c];
            float v1 = out_s[(p0 + 1)*97 + c];
            float v2 = out_s[(p0 + 2)*97 + c];
            float v3 = out_s[(p0 + 3)*97 + c];
            if (g == 0) {
                float bia = bqk[c] * QSCALE;
                int qi = ((whn + head)*32 + d)*64 + n;
                *(float4*)&g_q[qi] = make_float4(v0+bia, v1+bia, v2+bia, v3+bia);
            } else if (g == 1) {
                float bia = bqk[96 + c];
                int ki = ((whn + head)*32 + d)*64 + n;
                *(float4*)&g_k[ki] = make_float4(v0+bia, v1+bia, v2+bia, v3+bia);
            } else {
                float bia = bv[c];
                int vi = ((whn + head)*64 + n)*32 + d;
                g_v[vi]      = v0 + bia;
                g_v[vi + 32] = v1 + bia;
                g_v[vi + 64] = v2 + bia;
                g_v[vi + 96] = v3 + bia;
                *(float4*)&g_V[(b*96 + c)*HW + hwp] =
                    make_float4(v0+bia, v1+bia, v2+bia, v3+bia);
            }
        }
        __syncthreads();
    }
}

// ---------------- kernel DW: depthwise 5x5, reflect, smem halo -------------
__global__ __launch_bounds__(256) void dw_kernel(const float* __restrict__ Wdw,
                                                 const float* __restrict__ bdw)
{
    __shared__ float s[36][37];
    __shared__ float wk[25];

    int blk  = blockIdx.x;
    int img  = blk >> 6;
    int tile = blk & 63;
    int c    = img % 96;
    int h0   = (tile >> 3) << 5, w0 = (tile & 7) << 5;
    int tid  = threadIdx.x;

    if (tid < 25) wk[tid] = Wdw[c*25 + tid];
    const float* vimg = g_V + (size_t)img * HW;
    for (int idx = tid; idx < 36*36; idx += 256) {
        int r  = idx / 36, cc = idx % 36;
        int hh = h0 - 2 + r;  hh = (hh < 0) ? -hh : ((hh > 255) ? 510 - hh : hh);
        int wq = w0 - 2 + cc; wq = (wq < 0) ? -wq : ((wq > 255) ? 510 - wq : wq);
        s[r][cc] = vimg[hh*256 + wq];
    }
    __syncthreads();

    float b0 = bdw[c];
    #pragma unroll
    for (int kq = 0; kq < 4; kq++) {
        int px = tid + kq*256;
        int y = px >> 5, xq = px & 31;
        float acc = b0;
        #pragma unroll
        for (int i = 0; i < 5; i++)
            #pragma unroll
            for (int j = 0; j < 5; j++)
                acc = fmaf(s[y + i][xq + j], wk[i*5 + j], acc);
        g_conv[(size_t)img*HW + (h0 + y)*256 + (w0 + xq)] = acc;
    }
}

// ---------------- kernel C: attention, register-blocked GEMMs --------------
__device__ __forceinline__ int swin_label(int wh, int ww, int idx) {
    int rh = (wh == 31) ? (1 + (((idx >> 3) >= 4) ? 1 : 0)) : 0;
    int rw = (ww == 31) ? (1 + (((idx & 7)  >= 4) ? 1 : 0)) : 0;
    return rh*3 + rw;
}

__global__ __launch_bounds__(64) void attn_kernel()
{
    __shared__ __align__(16) float q_s[32][64];
    __shared__ __align__(16) float k_s[32][64];
    __shared__ __align__(16) float v_s[64][36];
    __shared__ __align__(16) float p_s[64][64];
    __shared__ float psum_s[64][9];

    int win  = blockIdx.x;
    int head = blockIdx.y;
    int tid  = threadIdx.x;
    int tn   = tid & 7;
    int tm   = tid >> 3;
    int n0   = tn*8, m0 = tm*8, d0 = tm*4;
    size_t base = (size_t)(win*3 + head) * 2048;

    const float4* qg = (const float4*)(g_q + base);
    const float4* kg = (const float4*)(g_k + base);
    const float4* vg = (const float4*)(g_v + base);
    for (int i = tid; i < 512; i += 64) {
        ((float4*)q_s)[i] = qg[i];
        ((float4*)k_s)[i] = kg[i];
        int m = i >> 3, dq = i & 7;
        *(float4*)&v_s[m][dq*4] = vg[i];
    }
    __syncthreads();

    float acc[8][8];
    #pragma unroll
    for (int i = 0; i < 8; i++)
        #pragma unroll
        for (int j = 0; j < 8; j++) acc[i][j] = 0.f;

    #pragma unroll 4
    for (int d = 0; d < 32; d++) {
        float4 qa = *(const float4*)&q_s[d][n0];
        float4 qb = *(const float4*)&q_s[d][n0 + 4];
        float4 ka = *(const float4*)&k_s[d][m0];
        float4 kb = *(const float4*)&k_s[d][m0 + 4];
        float qv[8] = {qa.x, qa.y, qa.z, qa.w, qb.x, qb.y, qb.z, qb.w};
        float kv[8] = {ka.x, ka.y, ka.z, ka.w, kb.x, kb.y, kb.z, kb.w};
        #pragma unroll
        for (int i = 0; i < 8; i++)
            #pragma unroll
            for (int j = 0; j < 8; j++)
                acc[i][j] = fmaf(qv[i], kv[j], acc[i][j]);
    }

    int wloc = win & 1023;
    int wh = wloc >> 5, ww = wloc & 31;
    bool masked = (wh == 31) || (ww == 31);
    int labn[8], labm[8];
    if (masked) {
        #pragma unroll
        for (int i = 0; i < 8; i++) {
            labn[i] = swin_label(wh, ww, n0 + i);
            labm[i] = swin_label(wh, ww, m0 + i);
        }
    }
    const float* bb = g_bias + head*4096;
    float lpart[8];
    #pragma unroll
    for (int i = 0; i < 8; i++) {
        float4 b0 = *(const float4*)&bb[(n0 + i)*64 + m0];
        float4 b1 = *(const float4*)&bb[(n0 + i)*64 + m0 + 4];
        float bv[8] = {b0.x, b0.y, b0.z, b0.w, b1.x, b1.y, b1.z, b1.w};
        float lp = 0.f;
        #pragma unroll
        for (int j = 0; j < 8; j++) {
            float p = __expf(acc[i][j] + bv[j]);
            if (masked && labm[j] != labn[i]) p = 0.f;
            acc[i][j] = p;
            lp += p;
        }
        lpart[i] = lp;
    }
    #pragma unroll
    for (int j = 0; j < 8; j++) {
        *(float4*)&p_s[m0 + j][n0] =
            make_float4(acc[0][j], acc[1][j], acc[2][j], acc[3][j]);
        *(float4*)&p_s[m0 + j][n0 + 4] =
            make_float4(acc[4][j], acc[5][j], acc[6][j], acc[7][j]);
    }
    #pragma unroll
    for (int i = 0; i < 8; i++) psum_s[n0 + i][tm] = lpart[i];
    __syncthreads();

    float out[8][4];
    #pragma unroll
    for (int i = 0; i < 8; i++)
        #pragma unroll
        for (int c = 0; c < 4; c++) out[i][c] = 0.f;

    #pragma unroll 4
    for (int m = 0; m < 64; m++) {
        float4 pa = *(const float4*)&p_s[m][n0];
        float4 pb = *(const float4*)&p_s[m][n0 + 4];
        float4 vv = *(const float4*)&v_s[m][d0];
        float pv[8] = {pa.x, pa.y, pa.z, pa.w, pb.x, pb.y, pb.z, pb.w};
        #pragma unroll
        for (int i = 0; i < 8; i++) {
            out[i][0] = fmaf(pv[i], vv.x, out[i][0]);
            out[i][1] = fmaf(pv[i], vv.y, out[i][1]);
            out[i][2] = fmaf(pv[i], vv.z, out[i][2]);
            out[i][3] = fmaf(pv[i], vv.w, out[i][3]);
        }
    }

    int b = win >> 10;
    #pragma unroll
    for (int i = 0; i < 8; i++) {
        float l = 0.f;
        #pragma unroll
        for (int j = 0; j < 8; j++) l += psum_s[n0 + i][j];
        float inv = 1.f / l;
        int n = n0 + i;
        int r = n >> 3, c = n & 7;
        int h = ((wh << 3) + r + 4) & 255;
        int w = ((ww << 3) + c + 4) & 255;
        float* ap = g_att + ((size_t)(b*256 + h)*256 + w)*96 + head*32 + d0;
        *(float4*)ap = make_float4(out[i][0]*inv, out[i][1]*inv,
                                   out[i][2]*inv, out[i][3]*inv);
    }
}

// ---------------- kernel D: add (conv + attn), final 96x96 GEMM ------------
__global__ __launch_bounds__(256) void final_kernel(
    const float* __restrict__ Wp, const float* __restrict__ bp,
    float* __restrict__ outp)
{
    __shared__ float t_s[64][97];
    __shared__ float w_s[32][97];

    int t   = blockIdx.x;
    int b   = t >> 10;
    int hw0 = (t & 1023) << 6;
    int h   = hw0 >> 8;
    int tid = threadIdx.x;

    for (int idx = tid; idx < 96*16; idx += 256) {
        int c = idx >> 4, pq = idx & 15;
        float4 v4 = *(const float4*)&g_conv[((size_t)b*96 + c)*HW + hw0 + pq*4];
        t_s[pq*4 + 0][c] = v4.x;
        t_s[pq*4 + 1][c] = v4.y;
        t_s[pq*4 + 2][c] = v4.z;
        t_s[pq*4 + 3][c] = v4.w;
    }
    __syncthreads();

    const float* ab = g_att + ((size_t)(b*256 + h)*256 + (hw0 & 255))*96;
    for (int idx = tid; idx < 64*24; idx += 256) {
        int f4 = idx % 24, p = idx / 24;
        float4 a4 = *(const float4*)&ab[p*96 + f4*4];
        int c = f4*4;
        t_s[p][c]     += a4.x;
        t_s[p][c + 1] += a4.y;
        t_s[p][c + 2] += a4.z;
        t_s[p][c + 3] += a4.w;
    }
    __syncthreads();

    int pxg = tid & 15, chg = tid >> 4;
    int p0 = pxg*4, ob = chg*6;
    float acc[6][4];
    #pragma unroll
    for (int i = 0; i < 6; i++)
        #pragma unroll
        for (int j = 0; j < 4; j++) acc[i][j] = 0.f;

    for (int kc = 0; kc < 3; kc++) {
        if (kc) __syncthreads();
        for (int idx = tid; idx < 32*96; idx += 256) {
            int kk = idx & 31, o = idx >> 5;
            w_s[kk][o] = Wp[o*96 + kc*32 + kk];
        }
        __syncthreads();
        #pragma unroll 4
        for (int kk = 0; kk < 32; kk++) {
            int k = kc*32 + kk;
            float tv0 = t_s[p0][k],   tv1 = t_s[p0+1][k];
            float tv2 = t_s[p0+2][k], tv3 = t_s[p0+3][k];
            #pragma unroll
            for (int i = 0; i < 6; i++) {
                float wv = w_s[kk][ob + i];
                acc[i][0] = fmaf(wv, tv0, acc[i][0]);
                acc[i][1] = fmaf(wv, tv1, acc[i][1]);
                acc[i][2] = fmaf(wv, tv2, acc[i][2]);
                acc[i][3] = fmaf(wv, tv3, acc[i][3]);
            }
        }
    }

    #pragma unroll
    for (int i = 0; i < 6; i++) {
        int o = ob + i;
        float bo = bp[o];
        *(float4*)&outp[((size_t)b*96 + o)*HW + hw0 + p0] =
            make_float4(acc[i][0] + bo, acc[i][1] + bo,
                        acc[i][2] + bo, acc[i][3] + bo);
    }
}

// ---------------- launch ----------------------------------------------------
extern "C" void kernel_launch(void* const* d_in, const int* in_sizes, int n_in,
                              void* d_out, int out_size)
{
    const float* x   = (const float*)d_in[0];
    const float* Wv  = (const float*)d_in[1];
    const float* bv  = (const float*)d_in[2];
    const float* Wqk = (const float*)d_in[3];
    const float* bqk = (const float*)d_in[4];
    const float* Wm1 = (const float*)d_in[5];
    const float* bm1 = (const float*)d_in[6];
    const float* Wm2 = (const float*)d_in[7];
    const float* bm2 = (const float*)d_in[8];
    const float* Wdw = (const float*)d_in[9];
    const float* bdw = (const float*)d_in[10];
    const float* Wp  = (const float*)d_in[11];
    const float* bp  = (const float*)d_in[12];
    float* outp = (float*)d_out;

    // dynamic smem: W hi+lo (119808 B) + x/out union (53248 B)
    const int QKV_SMEM = 288*WPAD*2*2 + 128*WPAD*2*2;
    cudaFuncSetAttribute(qkv_mma_kernel,
                         cudaFuncAttributeMaxDynamicSharedMemorySize, QKV_SMEM);

    bias_kernel   <<<16, 256>>>(Wm1, bm1, Wm2, bm2);
    prep_kernel   <<<(288*WPAD + 255)/256, 256>>>(Wqk, Wv);
    qkv_mma_kernel<<<2048, 256, QKV_SMEM>>>(x, bqk, bv);
    dw_kernel     <<<24576, 256>>>(Wdw, bdw);
    attn_kernel   <<<dim3(4096, 3), 64>>>();
    final_kernel  <<<4096, 256>>>(Wp, bp, outp);
}

// round 7
// speedup vs baseline: 1.0946x; 1.0946x over previous
#include <cuda_runtime.h>
#include <cuda_bf16.h>
#include <math.h>
#include <cstdint>

#define BATCH 4
#define CH    96
#define HRES  256
#define WRES  256
#define HW    65536
#define HEADS 3
#define HD    32
#define NPOS  64
#define NWIN  4096
#define QSCALE 0.17677669529663687f
#define WPAD  104

// ---------------- mma.sync / ldmatrix helpers (sm_80+ PTX) ------------------
#define LDM_X4(r, addr) \
    asm volatile("ldmatrix.sync.aligned.m8n8.x4.shared.b16 {%0,%1,%2,%3}, [%4];" \
        : "=r"((r)[0]), "=r"((r)[1]), "=r"((r)[2]), "=r"((r)[3]) : "r"(addr))
#define LDM_X2(r, addr) \
    asm volatile("ldmatrix.sync.aligned.m8n8.x2.shared.b16 {%0,%1}, [%2];" \
        : "=r"((r)[0]), "=r"((r)[1]) : "r"(addr))
#define MMA_BF16(d, a, b) \
    asm volatile("mma.sync.aligned.m16n8k16.row.col.f32.bf16.bf16.f32 " \
        "{%0,%1,%2,%3}, {%4,%5,%6,%7}, {%8,%9}, {%0,%1,%2,%3};" \
        : "+f"((d)[0]), "+f"((d)[1]), "+f"((d)[2]), "+f"((d)[3]) \
        : "r"((a)[0]), "r"((a)[1]), "r"((a)[2]), "r"((a)[3]), \
          "r"((b)[0]), "r"((b)[1]))

__device__ __forceinline__ uint32_t smem_u32(const void* p) {
    uint32_t a;
    asm("{ .reg .u64 t; cvta.to.shared.u64 t, %1; cvt.u32.u64 %0, t; }"
        : "=r"(a) : "l"(p));
    return a;
}

// ---------------- scratch ----------------------------------------------------
__device__ float g_V   [BATCH*CH*HW];
__device__ float g_conv[BATCH*CH*HW];
__device__ float g_q   [NWIN*HEADS*HD*NPOS];
__device__ float g_k   [NWIN*HEADS*HD*NPOS];
__device__ float g_v   [NWIN*HEADS*NPOS*HD];
__device__ float g_att [BATCH*HW*CH];
__device__ float g_bias[HEADS*NPOS*NPOS];
__device__ __align__(16) __nv_bfloat16 g_Whi[288*WPAD];
__device__ __align__(16) __nv_bfloat16 g_Wlo[288*WPAD];

// ---------------- kernel P: split W into bf16 hi/lo padded blobs ------------
__global__ void prep_kernel(const float* __restrict__ Wqk,
                            const float* __restrict__ Wv)
{
    int idx = blockIdx.x * 256 + threadIdx.x;
    if (idx >= 288*WPAD) return;
    int o = idx / WPAD, k = idx % WPAD;
    float w = 0.f;
    if (k < 96) {
        if (o < 96)        w = Wqk[o*96 + k] * QSCALE;
        else if (o < 192)  w = Wqk[o*96 + k];
        else               w = Wv[(o - 192)*96 + k];
    }
    __nv_bfloat16 hi = __float2bfloat16_rn(w);
    __nv_bfloat16 lo = __float2bfloat16_rn(w - __bfloat162float(hi));
    g_Whi[idx] = hi;
    g_Wlo[idx] = lo;
}

// ---------------- kernel B: bias MLP table ----------------------------------
__global__ void bias_kernel(const float* __restrict__ Wm1, const float* __restrict__ bm1,
                            const float* __restrict__ Wm2, const float* __restrict__ bm2)
{
    int gid = blockIdx.x * 256 + threadIdx.x;
    int n = gid >> 6, m = gid & 63;
    float r0 = (float)((n >> 3) - (m >> 3));
    float r1 = (float)((n & 7)  - (m & 7));
    r0 = copysignf(log1pf(fabsf(r0)), r0);
    r1 = copysignf(log1pf(fabsf(r1)), r1);
    float a0 = bm2[0], a1 = bm2[1], a2 = bm2[2];
    for (int j = 0; j < 256; j++) {
        float h = fmaf(r0, Wm1[j], fmaf(r1, Wm1[256 + j], bm1[j]));
        h = fmaxf(h, 0.f);
        a0 = fmaf(h, Wm2[j*3 + 0], a0);
        a1 = fmaf(h, Wm2[j*3 + 1], a1);
        a2 = fmaf(h, Wm2[j*3 + 2], a2);
    }
    g_bias[0*4096 + gid] = a0;
    g_bias[1*4096 + gid] = a1;
    g_bias[2*4096 + gid] = a2;
}

// ---------------- kernel A: persistent QKV GEMM via mma.sync ----------------
// W loaded to smem ONCE per block; grid-stride over 128-pixel tiles.
__global__ __launch_bounds__(256) void qkv_mma_kernel(
    const float* __restrict__ x,
    const float* __restrict__ bqk, const float* __restrict__ bv)
{
    extern __shared__ __align__(16) unsigned char dsm[];
    __nv_bfloat16* whi_s = (__nv_bfloat16*)dsm;            // [288*WPAD]
    __nv_bfloat16* wlo_s = whi_s + 288*WPAD;
    __nv_bfloat16* xhi_s = wlo_s + 288*WPAD;               // [128*WPAD]
    __nv_bfloat16* xlo_s = xhi_s + 128*WPAD;
    float* out_s = (float*)(wlo_s + 288*WPAD);             // overlays x area

    int tid  = threadIdx.x;
    int warp = tid >> 5, lane = tid & 31;

    // W blobs -> smem once
    {
        const uint4* s1 = (const uint4*)g_Whi; uint4* d1 = (uint4*)whi_s;
        const uint4* s2 = (const uint4*)g_Wlo; uint4* d2 = (uint4*)wlo_s;
        #pragma unroll 4
        for (int i = tid; i < 288*WPAD*2/16; i += 256) { d1[i] = s1[i]; d2[i] = s2[i]; }
    }

    int idx8 = lane & 7, quad = lane >> 3;
    int arow = warp*16 + (quad & 1)*8 + idx8;
    int acol = (quad >> 1)*8;
    int brow = lane & 7;
    int bcol = ((lane >> 3) & 1)*8;
    int pq   = tid & 31;
    int p0   = pq*4;
    int c0   = tid >> 5;
    int orow = warp*16 + (lane >> 2);
    int oc   = (lane & 3)*2;

    for (int tile = blockIdx.x; tile < 2048; tile += gridDim.x) {
        int b   = tile >> 9;
        int hw0 = (tile & 511) << 7;

        // X load (coalesced float4), hi/lo split
        __syncthreads();   // out_s of previous tile fully consumed
        for (int idx = tid; idx < 96*32; idx += 256) {
            int k = idx >> 5, pg = idx & 31;
            float4 v = *(const float4*)&x[(b*96 + k)*HW + hw0 + pg*4];
            float vf[4] = {v.x, v.y, v.z, v.w};
            #pragma unroll
            for (int j = 0; j < 4; j++) {
                int px = pg*4 + j;
                __nv_bfloat16 hi = __float2bfloat16_rn(vf[j]);
                __nv_bfloat16 lo = __float2bfloat16_rn(vf[j] - __bfloat162float(hi));
                xhi_s[px*WPAD + k] = hi;
                xlo_s[px*WPAD + k] = lo;
            }
        }
        __syncthreads();

        // A fragments (held in regs through all 3 groups)
        uint32_t ahi[6][4], alo[6][4];
        #pragma unroll
        for (int ks = 0; ks < 6; ks++) {
            LDM_X4(ahi[ks], smem_u32(&xhi_s[arow*WPAD + ks*16 + acol]));
            LDM_X4(alo[ks], smem_u32(&xlo_s[arow*WPAD + ks*16 + acol]));
        }
        __syncthreads();   // x area now reusable as out_s

        // writeout coords
        int hwp = hw0 + p0;
        int h_  = hwp >> 8, w_ = hwp & 255;
        int hp  = (h_ + 252) & 255;
        int wp  = (w_ + 252) & 255;
        int wh  = hp >> 3, ww = wp >> 3;
        int win = b*1024 + wh*32 + ww;
        int n   = (hp & 7)*8 + (wp & 7);
        int whn = win*3;

        #pragma unroll 1
        for (int g = 0; g < 3; g++) {
            float acc[12][4];
            #pragma unroll
            for (int nt = 0; nt < 12; nt++)
                #pragma unroll
                for (int j = 0; j < 4; j++) acc[nt][j] = 0.f;

            int n_base = g*96;
            #pragma unroll 1
            for (int ks = 0; ks < 6; ks++) {
                uint32_t bh[12][2];
                #pragma unroll
                for (int nt = 0; nt < 12; nt++)
                    LDM_X2(bh[nt], smem_u32(&whi_s[(n_base + nt*8 + brow)*WPAD + ks*16 + bcol]));
                #pragma unroll
                for (int nt = 0; nt < 12; nt++) {
                    MMA_BF16(acc[nt], ahi[ks], bh[nt]);   // hi*hi
                    MMA_BF16(acc[nt], alo[ks], bh[nt]);   // lo*hi
                }
                #pragma unroll
                for (int nt = 0; nt < 12; nt++) {
                    uint32_t bl[2];
                    LDM_X2(bl, smem_u32(&wlo_s[(n_base + nt*8 + brow)*WPAD + ks*16 + bcol]));
                    MMA_BF16(acc[nt], ahi[ks], bl);       // hi*lo
                }
            }

            // stage accum -> out_s [px][97]
            #pragma unroll
            for (int nt = 0; nt < 12; nt++) {
                out_s[orow*97 + nt*8 + oc]         = acc[nt][0];
                out_s[orow*97 + nt*8 + oc + 1]     = acc[nt][1];
                out_s[(orow+8)*97 + nt*8 + oc]     = acc[nt][2];
                out_s[(orow+8)*97 + nt*8 + oc + 1] = acc[nt][3];
            }
            __syncthreads();

            // cooperative coalesced writeout
            #pragma unroll 1
            for (int j = 0; j < 12; j++) {
                int c = c0 + j*8;
                int head = c >> 5, d = c & 31;
                float v0 = out_s[(p0    )*97 + c];
                float v1 = out_s[(p0 + 1)*97 + c];
                float v2 = out_s[(p0 + 2)*97 + c];
                float v3 = out_s[(p0 + 3)*97 + c];
                if (g == 0) {
                    float bia = bqk[c] * QSCALE;
                    int qi = ((whn + head)*32 + d)*64 + n;
                    *(float4*)&g_q[qi] = make_float4(v0+bia, v1+bia, v2+bia, v3+bia);
                } else if (g == 1) {
                    float bia = bqk[96 + c];
                    int ki = ((whn + head)*32 + d)*64 + n;
                    *(float4*)&g_k[ki] = make_float4(v0+bia, v1+bia, v2+bia, v3+bia);
                } else {
                    float bia = bv[c];
                    int vi = ((whn + head)*64 + n)*32 + d;
                    g_v[vi]      = v0 + bia;
                    g_v[vi + 32] = v1 + bia;
                    g_v[vi + 64] = v2 + bia;
                    g_v[vi + 96] = v3 + bia;
                    *(float4*)&g_V[(b*96 + c)*HW + hwp] =
                        make_float4(v0+bia, v1+bia, v2+bia, v3+bia);
                }
            }
            __syncthreads();
        }
    }
}

// ---------------- kernel DW: depthwise 5x5, vectorized (4 px/thread) --------
__global__ __launch_bounds__(256) void dw_kernel(const float* __restrict__ Wdw,
                                                 const float* __restrict__ bdw)
{
    __shared__ __align__(16) float s[36][44];   // rows h0-2..h0+33, cols w0-4..w0+39
    __shared__ float wk[25];

    int blk  = blockIdx.x;
    int img  = blk >> 6;
    int tile = blk & 63;
    int c    = img % 96;
    int h0   = (tile >> 3) << 5, w0 = (tile & 7) << 5;
    int tid  = threadIdx.x;

    if (tid < 25) wk[tid] = Wdw[c*25 + tid];
    const float* vimg = g_V + (size_t)img * HW;
    for (int idx = tid; idx < 36*44; idx += 256) {
        int r  = idx / 44, cc = idx % 44;
        int hh = h0 - 2 + r;  hh = (hh < 0) ? -hh : ((hh > 255) ? 510 - hh : hh);
        int wq = w0 - 4 + cc; wq = (wq < 0) ? -wq : ((wq > 255) ? 510 - wq : wq);
        s[r][cc] = vimg[hh*256 + wq];
    }
    __syncthreads();

    int y   = tid >> 3;          // 0..31
    int xq0 = (tid & 7) * 4;     // 0..28
    float b0 = bdw[c];
    float acc[4] = {b0, b0, b0, b0};
    #pragma unroll
    for (int i = 0; i < 5; i++) {
        float4 fa = *(const float4*)&s[y + i][xq0];
        float4 fb = *(const float4*)&s[y + i][xq0 + 4];
        float4 fc = *(const float4*)&s[y + i][xq0 + 8];
        float f[12] = {fa.x, fa.y, fa.z, fa.w, fb.x, fb.y, fb.z, fb.w,
                       fc.x, fc.y, fc.z, fc.w};
        #pragma unroll
        for (int j = 0; j < 5; j++) {
            float wv = wk[i*5 + j];
            acc[0] = fmaf(f[j + 2], wv, acc[0]);
            acc[1] = fmaf(f[j + 3], wv, acc[1]);
            acc[2] = fmaf(f[j + 4], wv, acc[2]);
            acc[3] = fmaf(f[j + 5], wv, acc[3]);
        }
    }
    *(float4*)&g_conv[(size_t)img*HW + (h0 + y)*256 + (w0 + xq0)] =
        make_float4(acc[0], acc[1], acc[2], acc[3]);
}

// ---------------- kernel C: attention (smem union: p over q/k) --------------
__device__ __forceinline__ int swin_label(int wh, int ww, int idx) {
    int rh = (wh == 31) ? (1 + (((idx >> 3) >= 4) ? 1 : 0)) : 0;
    int rw = (ww == 31) ? (1 + (((idx & 7)  >= 4) ? 1 : 0)) : 0;
    return rh*3 + rw;
}

__global__ __launch_bounds__(64) void attn_kernel()
{
    __shared__ __align__(16) float buf[4096];      // q[2048]+k[2048] OR p[4096]
    __shared__ __align__(16) float v_s[64][36];
    __shared__ float psum_s[64][9];

    float* q_s = buf;                // [32][64]
    float* k_s = buf + 2048;         // [32][64]
    float* p_s = buf;                // [64][64] (overlays q/k after QK)

    int win  = blockIdx.x;
    int head = blockIdx.y;
    int tid  = threadIdx.x;
    int tn   = tid & 7;
    int tm   = tid >> 3;
    int n0   = tn*8, m0 = tm*8, d0 = tm*4;
    size_t base = (size_t)(win*3 + head) * 2048;

    const float4* qg = (const float4*)(g_q + base);
    const float4* kg = (const float4*)(g_k + base);
    const float4* vg = (const float4*)(g_v + base);
    for (int i = tid; i < 512; i += 64) {
        ((float4*)q_s)[i] = qg[i];
        ((float4*)k_s)[i] = kg[i];
        int m = i >> 3, dq = i & 7;
        *(float4*)&v_s[m][dq*4] = vg[i];
    }
    __syncthreads();

    float acc[8][8];
    #pragma unroll
    for (int i = 0; i < 8; i++)
        #pragma unroll
        for (int j = 0; j < 8; j++) acc[i][j] = 0.f;

    #pragma unroll 4
    for (int d = 0; d < 32; d++) {
        float4 qa = *(const float4*)&q_s[d*64 + n0];
        float4 qb = *(const float4*)&q_s[d*64 + n0 + 4];
        float4 ka = *(const float4*)&k_s[d*64 + m0];
        float4 kb = *(const float4*)&k_s[d*64 + m0 + 4];
        float qv[8] = {qa.x, qa.y, qa.z, qa.w, qb.x, qb.y, qb.z, qb.w};
        float kv[8] = {ka.x, ka.y, ka.z, ka.w, kb.x, kb.y, kb.z, kb.w};
        #pragma unroll
        for (int i = 0; i < 8; i++)
            #pragma unroll
            for (int j = 0; j < 8; j++)
                acc[i][j] = fmaf(qv[i], kv[j], acc[i][j]);
    }
    __syncthreads();   // everyone done reading q/k before p overwrites

    int wloc = win & 1023;
    int wh = wloc >> 5, ww = wloc & 31;
    bool masked = (wh == 31) || (ww == 31);
    int labn[8], labm[8];
    if (masked) {
        #pragma unroll
        for (int i = 0; i < 8; i++) {
            labn[i] = swin_label(wh, ww, n0 + i);
            labm[i] = swin_label(wh, ww, m0 + i);
        }
    }
    const float* bb = g_bias + head*4096;
    float lpart[8];
    #pragma unroll
    for (int i = 0; i < 8; i++) {
        float4 b0 = *(const float4*)&bb[(n0 + i)*64 + m0];
        float4 b1 = *(const float4*)&bb[(n0 + i)*64 + m0 + 4];
        float bv[8] = {b0.x, b0.y, b0.z, b0.w, b1.x, b1.y, b1.z, b1.w};
        float lp = 0.f;
        #pragma unroll
        for (int j = 0; j < 8; j++) {
            float p = __expf(acc[i][j] + bv[j]);
            if (masked && labm[j] != labn[i]) p = 0.f;
            acc[i][j] = p;
            lp += p;
        }
        lpart[i] = lp;
    }
    #pragma unroll
    for (int j = 0; j < 8; j++) {
        *(float4*)&p_s[(m0 + j)*64 + n0] =
            make_float4(acc[0][j], acc[1][j], acc[2][j], acc[3][j]);
        *(float4*)&p_s[(m0 + j)*64 + n0 + 4] =
            make_float4(acc[4][j], acc[5][j], acc[6][j], acc[7][j]);
    }
    #pragma unroll
    for (int i = 0; i < 8; i++) psum_s[n0 + i][tm] = lpart[i];
    __syncthreads();

    float out[8][4];
    #pragma unroll
    for (int i = 0; i < 8; i++)
        #pragma unroll
        for (int cc = 0; cc < 4; cc++) out[i][cc] = 0.f;

    #pragma unroll 4
    for (int m = 0; m < 64; m++) {
        float4 pa = *(const float4*)&p_s[m*64 + n0];
        float4 pb = *(const float4*)&p_s[m*64 + n0 + 4];
        float4 vv = *(const float4*)&v_s[m][d0];
        float pv[8] = {pa.x, pa.y, pa.z, pa.w, pb.x, pb.y, pb.z, pb.w};
        #pragma unroll
        for (int i = 0; i < 8; i++) {
            out[i][0] = fmaf(pv[i], vv.x, out[i][0]);
            out[i][1] = fmaf(pv[i], vv.y, out[i][1]);
            out[i][2] = fmaf(pv[i], vv.z, out[i][2]);
            out[i][3] = fmaf(pv[i], vv.w, out[i][3]);
        }
    }

    int b = win >> 10;
    #pragma unroll
    for (int i = 0; i < 8; i++) {
        float l = 0.f;
        #pragma unroll
        for (int j = 0; j < 8; j++) l += psum_s[n0 + i][j];
        float inv = 1.f / l;
        int n = n0 + i;
        int r = n >> 3, cc = n & 7;
        int h = ((wh << 3) + r + 4) & 255;
        int w = ((ww << 3) + cc + 4) & 255;
        float* ap = g_att + ((size_t)(b*256 + h)*256 + w)*96 + head*32 + d0;
        *(float4*)ap = make_float4(out[i][0]*inv, out[i][1]*inv,
                                   out[i][2]*inv, out[i][3]*inv);
    }
}

// ---------------- kernel D: add (conv + attn), final 96x96 GEMM -------------
__global__ __launch_bounds__(256) void final_kernel(
    const float* __restrict__ Wp, const float* __restrict__ bp,
    float* __restrict__ outp)
{
    __shared__ float t_s[64][97];
    __shared__ float w_s[32][97];

    int t   = blockIdx.x;
    int b   = t >> 10;
    int hw0 = (t & 1023) << 6;
    int h   = hw0 >> 8;
    int tid = threadIdx.x;

    for (int idx = tid; idx < 96*16; idx += 256) {
        int c = idx >> 4, pq = idx & 15;
        float4 v4 = *(const float4*)&g_conv[((size_t)b*96 + c)*HW + hw0 + pq*4];
        t_s[pq*4 + 0][c] = v4.x;
        t_s[pq*4 + 1][c] = v4.y;
        t_s[pq*4 + 2][c] = v4.z;
        t_s[pq*4 + 3][c] = v4.w;
    }
    __syncthreads();

    const float* ab = g_att + ((size_t)(b*256 + h)*256 + (hw0 & 255))*96;
    for (int idx = tid; idx < 64*24; idx += 256) {
        int f4 = idx % 24, p = idx / 24;
        float4 a4 = *(const float4*)&ab[p*96 + f4*4];
        int c = f4*4;
        t_s[p][c]     += a4.x;
        t_s[p][c + 1] += a4.y;
        t_s[p][c + 2] += a4.z;
        t_s[p][c + 3] += a4.w;
    }
    __syncthreads();

    int pxg = tid & 15, chg = tid >> 4;
    int p0 = pxg*4, ob = chg*6;
    float acc[6][4];
    #pragma unroll
    for (int i = 0; i < 6; i++)
        #pragma unroll
        for (int j = 0; j < 4; j++) acc[i][j] = 0.f;

    for (int kc = 0; kc < 3; kc++) {
        if (kc) __syncthreads();
        for (int idx = tid; idx < 32*96; idx += 256) {
            int kk = idx & 31, o = idx >> 5;
            w_s[kk][o] = Wp[o*96 + kc*32 + kk];
        }
        __syncthreads();
        #pragma unroll 4
        for (int kk = 0; kk < 32; kk++) {
            int k = kc*32 + kk;
            float tv0 = t_s[p0][k],   tv1 = t_s[p0+1][k];
            float tv2 = t_s[p0+2][k], tv3 = t_s[p0+3][k];
            #pragma unroll
            for (int i = 0; i < 6; i++) {
                float wv = w_s[kk][ob + i];
                acc[i][0] = fmaf(wv, tv0, acc[i][0]);
                acc[i][1] = fmaf(wv, tv1, acc[i][1]);
                acc[i][2] = fmaf(wv, tv2, acc[i][2]);
                acc[i][3] = fmaf(wv, tv3, acc[i][3]);
            }
        }
    }

    #pragma unroll
    for (int i = 0; i < 6; i++) {
        int o = ob + i;
        float bo = bp[o];
        *(float4*)&outp[((size_t)b*96 + o)*HW + hw0 + p0] =
            make_float4(acc[i][0] + bo, acc[i][1] + bo,
                        acc[i][2] + bo, acc[i][3] + bo);
    }
}

// ---------------- launch ------------------------------------------------------
extern "C" void kernel_launch(void* const* d_in, const int* in_sizes, int n_in,
                              void* d_out, int out_size)
{
    const float* x   = (const float*)d_in[0];
    const float* Wv  = (const float*)d_in[1];
    const float* bv  = (const float*)d_in[2];
    const float* Wqk = (const float*)d_in[3];
    const float* bqk = (const float*)d_in[4];
    const float* Wm1 = (const float*)d_in[5];
    const float* bm1 = (const float*)d_in[6];
    const float* Wm2 = (const float*)d_in[7];
    const float* bm2 = (const float*)d_in[8];
    const float* Wdw = (const float*)d_in[9];
    const float* bdw = (const float*)d_in[10];
    const float* Wp  = (const float*)d_in[11];
    const float* bp  = (const float*)d_in[12];
    float* outp = (float*)d_out;

    const int QKV_SMEM = 288*WPAD*2*2 + 128*WPAD*2*2;   // 173056 B
    cudaFuncSetAttribute(qkv_mma_kernel,
                         cudaFuncAttributeMaxDynamicSharedMemorySize, QKV_SMEM);

    bias_kernel   <<<16, 256>>>(Wm1, bm1, Wm2, bm2);
    prep_kernel   <<<(288*WPAD + 255)/256, 256>>>(Wqk, Wv);
    qkv_mma_kernel<<<296, 256, QKV_SMEM>>>(x, bqk, bv);
    dw_kernel     <<<24576, 256>>>(Wdw, bdw);
    attn_kernel   <<<dim3(4096, 3), 64>>>();
    final_kernel  <<<4096, 256>>>(Wp, bp, outp);
}

// round 8
// speedup vs baseline: 1.1475x; 1.0483x over previous
#include <cuda_runtime.h>
#include <cuda_bf16.h>
#include <math.h>
#include <cstdint>

#define BATCH 4
#define CH    96
#define HRES  256
#define WRES  256
#define HW    65536
#define HEADS 3
#define HD    32
#define NPOS  64
#define NWIN  4096
#define QSCALE 0.17677669529663687f
#define WPAD  104

// ---------------- mma.sync / ldmatrix helpers (sm_80+ PTX) ------------------
#define LDM_X4(r, addr) \
    asm volatile("ldmatrix.sync.aligned.m8n8.x4.shared.b16 {%0,%1,%2,%3}, [%4];" \
        : "=r"((r)[0]), "=r"((r)[1]), "=r"((r)[2]), "=r"((r)[3]) : "r"(addr))
#define LDM_X2(r, addr) \
    asm volatile("ldmatrix.sync.aligned.m8n8.x2.shared.b16 {%0,%1}, [%2];" \
        : "=r"((r)[0]), "=r"((r)[1]) : "r"(addr))
#define MMA_BF16(d, a, b) \
    asm volatile("mma.sync.aligned.m16n8k16.row.col.f32.bf16.bf16.f32 " \
        "{%0,%1,%2,%3}, {%4,%5,%6,%7}, {%8,%9}, {%0,%1,%2,%3};" \
        : "+f"((d)[0]), "+f"((d)[1]), "+f"((d)[2]), "+f"((d)[3]) \
        : "r"((a)[0]), "r"((a)[1]), "r"((a)[2]), "r"((a)[3]), \
          "r"((b)[0]), "r"((b)[1]))

__device__ __forceinline__ uint32_t smem_u32(const void* p) {
    uint32_t a;
    asm("{ .reg .u64 t; cvta.to.shared.u64 t, %1; cvt.u32.u64 %0, t; }"
        : "=r"(a) : "l"(p));
    return a;
}

// ---------------- scratch ----------------------------------------------------
__device__ float g_V   [BATCH*CH*HW];
__device__ float g_conv[BATCH*CH*HW];
__device__ float g_q   [NWIN*HEADS*HD*NPOS];
__device__ float g_k   [NWIN*HEADS*HD*NPOS];
__device__ float g_v   [NWIN*HEADS*NPOS*HD];
__device__ float g_att [BATCH*HW*CH];
__device__ float g_bias[HEADS*NPOS*NPOS];
__device__ __align__(16) __nv_bfloat16 g_Whi[288*WPAD];
__device__ __align__(16) __nv_bfloat16 g_Wlo[288*WPAD];

// ---------------- kernels P: split W into bf16 hi/lo padded blobs -----------
__device__ __forceinline__ float wval(const float* Wqk, const float* Wv,
                                      int o, int k) {
    if (k >= 96) return 0.f;
    if (o < 96)       return Wqk[o*96 + k] * QSCALE;
    else if (o < 192) return Wqk[o*96 + k];
    else              return Wv[(o - 192)*96 + k];
}
__global__ void prep_hi_kernel(const float* __restrict__ Wqk,
                               const float* __restrict__ Wv)
{
    int idx = blockIdx.x * 256 + threadIdx.x;
    if (idx >= 288*WPAD) return;
    float w = wval(Wqk, Wv, idx / WPAD, idx % WPAD);
    g_Whi[idx] = __float2bfloat16_rn(w);
}
__global__ void prep_lo_kernel(const float* __restrict__ Wqk,
                               const float* __restrict__ Wv)
{
    int idx = blockIdx.x * 256 + threadIdx.x;
    if (idx >= 288*WPAD) return;
    float w = wval(Wqk, Wv, idx / WPAD, idx % WPAD);
    __nv_bfloat16 hi = __float2bfloat16_rn(w);
    g_Wlo[idx] = __float2bfloat16_rn(w - __bfloat162float(hi));
}

// ---------------- kernel B: bias MLP table ----------------------------------
__global__ void bias_kernel(const float* __restrict__ Wm1, const float* __restrict__ bm1,
                            const float* __restrict__ Wm2, const float* __restrict__ bm2)
{
    int gid = blockIdx.x * 256 + threadIdx.x;
    int n = gid >> 6, m = gid & 63;
    float r0 = (float)((n >> 3) - (m >> 3));
    float r1 = (float)((n & 7)  - (m & 7));
    r0 = copysignf(log1pf(fabsf(r0)), r0);
    r1 = copysignf(log1pf(fabsf(r1)), r1);
    float a0 = bm2[0], a1 = bm2[1], a2 = bm2[2];
    for (int j = 0; j < 256; j++) {
        float h = fmaf(r0, Wm1[j], fmaf(r1, Wm1[256 + j], bm1[j]));
        h = fmaxf(h, 0.f);
        a0 = fmaf(h, Wm2[j*3 + 0], a0);
        a1 = fmaf(h, Wm2[j*3 + 1], a1);
        a2 = fmaf(h, Wm2[j*3 + 2], a2);
    }
    g_bias[0*4096 + gid] = a0;
    g_bias[1*4096 + gid] = a1;
    g_bias[2*4096 + gid] = a2;
}

// ---------------- kernel A: persistent QKV GEMM via mma.sync ----------------
__global__ __launch_bounds__(256) void qkv_mma_kernel(
    const float* __restrict__ x,
    const float* __restrict__ bqk, const float* __restrict__ bv)
{
    extern __shared__ __align__(16) unsigned char dsm[];
    __nv_bfloat16* whi_s = (__nv_bfloat16*)dsm;
    __nv_bfloat16* wlo_s = whi_s + 288*WPAD;
    __nv_bfloat16* xhi_s = wlo_s + 288*WPAD;
    __nv_bfloat16* xlo_s = xhi_s + 128*WPAD;
    float* out_s = (float*)(wlo_s + 288*WPAD);

    int tid  = threadIdx.x;
    int warp = tid >> 5, lane = tid & 31;

    {
        const uint4* s1 = (const uint4*)g_Whi; uint4* d1 = (uint4*)whi_s;
        const uint4* s2 = (const uint4*)g_Wlo; uint4* d2 = (uint4*)wlo_s;
        #pragma unroll 4
        for (int i = tid; i < 288*WPAD*2/16; i += 256) { d1[i] = s1[i]; d2[i] = s2[i]; }
    }

    int idx8 = lane & 7, quad = lane >> 3;
    int arow = warp*16 + (quad & 1)*8 + idx8;
    int acol = (quad >> 1)*8;
    int brow = lane & 7;
    int bcol = ((lane >> 3) & 1)*8;
    int pq   = tid & 31;
    int p0   = pq*4;
    int c0   = tid >> 5;
    int orow = warp*16 + (lane >> 2);
    int oc   = (lane & 3)*2;

    for (int tile = blockIdx.x; tile < 2048; tile += gridDim.x) {
        int b   = tile >> 9;
        int hw0 = (tile & 511) << 7;

        __syncthreads();
        for (int idx = tid; idx < 96*32; idx += 256) {
            int k = idx >> 5, pg = idx & 31;
            float4 v = *(const float4*)&x[(b*96 + k)*HW + hw0 + pg*4];
            float vf[4] = {v.x, v.y, v.z, v.w};
            #pragma unroll
            for (int j = 0; j < 4; j++) {
                int px = pg*4 + j;
                __nv_bfloat16 hi = __float2bfloat16_rn(vf[j]);
                __nv_bfloat16 lo = __float2bfloat16_rn(vf[j] - __bfloat162float(hi));
                xhi_s[px*WPAD + k] = hi;
                xlo_s[px*WPAD + k] = lo;
            }
        }
        __syncthreads();

        uint32_t ahi[6][4], alo[6][4];
        #pragma unroll
        for (int ks = 0; ks < 6; ks++) {
            LDM_X4(ahi[ks], smem_u32(&xhi_s[arow*WPAD + ks*16 + acol]));
            LDM_X4(alo[ks], smem_u32(&xlo_s[arow*WPAD + ks*16 + acol]));
        }
        __syncthreads();

        int hwp = hw0 + p0;
        int h_  = hwp >> 8, w_ = hwp & 255;
        int hp  = (h_ + 252) & 255;
        int wp  = (w_ + 252) & 255;
        int wh  = hp >> 3, ww = wp >> 3;
        int win = b*1024 + wh*32 + ww;
        int n   = (hp & 7)*8 + (wp & 7);
        int whn = win*3;

        #pragma unroll 1
        for (int g = 0; g < 3; g++) {
            float acc[12][4];
            #pragma unroll
            for (int nt = 0; nt < 12; nt++)
                #pragma unroll
                for (int j = 0; j < 4; j++) acc[nt][j] = 0.f;

            int n_base = g*96;
            #pragma unroll 1
            for (int ks = 0; ks < 6; ks++) {
                uint32_t bh[12][2];
                #pragma unroll
                for (int nt = 0; nt < 12; nt++)
                    LDM_X2(bh[nt], smem_u32(&whi_s[(n_base + nt*8 + brow)*WPAD + ks*16 + bcol]));
                #pragma unroll
                for (int nt = 0; nt < 12; nt++) {
                    MMA_BF16(acc[nt], ahi[ks], bh[nt]);
                    MMA_BF16(acc[nt], alo[ks], bh[nt]);
                }
                #pragma unroll
                for (int nt = 0; nt < 12; nt++) {
                    uint32_t bl[2];
                    LDM_X2(bl, smem_u32(&wlo_s[(n_base + nt*8 + brow)*WPAD + ks*16 + bcol]));
                    MMA_BF16(acc[nt], ahi[ks], bl);
                }
            }

            #pragma unroll
            for (int nt = 0; nt < 12; nt++) {
                out_s[orow*97 + nt*8 + oc]         = acc[nt][0];
                out_s[orow*97 + nt*8 + oc + 1]     = acc[nt][1];
                out_s[(orow+8)*97 + nt*8 + oc]     = acc[nt][2];
                out_s[(orow+8)*97 + nt*8 + oc + 1] = acc[nt][3];
            }
            __syncthreads();

            #pragma unroll 1
            for (int j = 0; j < 12; j++) {
                int c = c0 + j*8;
                int head = c >> 5, d = c & 31;
                float v0 = out_s[(p0    )*97 + c];
                float v1 = out_s[(p0 + 1)*97 + c];
                float v2 = out_s[(p0 + 2)*97 + c];
                float v3 = out_s[(p0 + 3)*97 + c];
                if (g == 0) {
                    float bia = bqk[c] * QSCALE;
                    int qi = ((whn + head)*32 + d)*64 + n;
                    *(float4*)&g_q[qi] = make_float4(v0+bia, v1+bia, v2+bia, v3+bia);
                } else if (g == 1) {
                    float bia = bqk[96 + c];
                    int ki = ((whn + head)*32 + d)*64 + n;
                    *(float4*)&g_k[ki] = make_float4(v0+bia, v1+bia, v2+bia, v3+bia);
                } else {
                    float bia = bv[c];
                    int vi = ((whn + head)*64 + n)*32 + d;
                    g_v[vi]      = v0 + bia;
                    g_v[vi + 32] = v1 + bia;
                    g_v[vi + 64] = v2 + bia;
                    g_v[vi + 96] = v3 + bia;
                    *(float4*)&g_V[(b*96 + c)*HW + hwp] =
                        make_float4(v0+bia, v1+bia, v2+bia, v3+bia);
                }
            }
            __syncthreads();
        }
    }
}

// ---------------- kernel DW: depthwise 5x5, vectorized halo -----------------
__global__ __launch_bounds__(256) void dw_kernel(const float* __restrict__ Wdw,
                                                 const float* __restrict__ bdw)
{
    __shared__ __align__(16) float s[36][44];
    __shared__ float wk[25];

    int blk  = blockIdx.x;
    int img  = blk >> 6;
    int tile = blk & 63;
    int c    = img % 96;
    int h0   = (tile >> 3) << 5, w0 = (tile & 7) << 5;
    int tid  = threadIdx.x;

    if (tid < 25) wk[tid] = Wdw[c*25 + tid];
    const float* vimg = g_V + (size_t)img * HW;

    bool border = (h0 == 0) || (h0 == 224) || (w0 == 0) || (w0 == 224);
    if (!border) {
        // interior: straight float4 loads, no reflect ALU
        const float* src = vimg + (h0 - 2)*256 + (w0 - 4);
        for (int idx = tid; idx < 36*11; idx += 256) {
            int r = idx / 11, c4 = idx - r*11;
            *(float4*)&s[r][c4*4] = *(const float4*)&src[r*256 + c4*4];
        }
    } else {
        for (int idx = tid; idx < 36*44; idx += 256) {
            int r  = idx / 44, cc = idx % 44;
            int hh = h0 - 2 + r;  hh = (hh < 0) ? -hh : ((hh > 255) ? 510 - hh : hh);
            int wq = w0 - 4 + cc; wq = (wq < 0) ? -wq : ((wq > 255) ? 510 - wq : wq);
            s[r][cc] = vimg[hh*256 + wq];
        }
    }
    __syncthreads();

    int y   = tid >> 3;
    int xq0 = (tid & 7) * 4;
    float b0 = bdw[c];
    float acc[4] = {b0, b0, b0, b0};
    #pragma unroll
    for (int i = 0; i < 5; i++) {
        float4 fa = *(const float4*)&s[y + i][xq0];
        float4 fb = *(const float4*)&s[y + i][xq0 + 4];
        float4 fc = *(const float4*)&s[y + i][xq0 + 8];
        float f[12] = {fa.x, fa.y, fa.z, fa.w, fb.x, fb.y, fb.z, fb.w,
                       fc.x, fc.y, fc.z, fc.w};
        #pragma unroll
        for (int j = 0; j < 5; j++) {
            float wv = wk[i*5 + j];
            acc[0] = fmaf(f[j + 2], wv, acc[0]);
            acc[1] = fmaf(f[j + 3], wv, acc[1]);
            acc[2] = fmaf(f[j + 4], wv, acc[2]);
            acc[3] = fmaf(f[j + 5], wv, acc[3]);
        }
    }
    *(float4*)&g_conv[(size_t)img*HW + (h0 + y)*256 + (w0 + xq0)] =
        make_float4(acc[0], acc[1], acc[2], acc[3]);
}

// ---------------- kernel C: attention, 128 threads, 4x8 / 4x4 tiles ---------
__device__ __forceinline__ int swin_label(int wh, int ww, int idx) {
    int rh = (wh == 31) ? (1 + (((idx >> 3) >= 4) ? 1 : 0)) : 0;
    int rw = (ww == 31) ? (1 + (((idx & 7)  >= 4) ? 1 : 0)) : 0;
    return rh*3 + rw;
}

__global__ __launch_bounds__(128) void attn_kernel()
{
    __shared__ __align__(16) float buf[4096];      // q[2048]+k[2048] OR p[4096]
    __shared__ __align__(16) float v_s[64][36];
    __shared__ float psum_s[64][9];

    float* q_s = buf;
    float* k_s = buf + 2048;
    float* p_s = buf;            // [m][n] after QK

    int win  = blockIdx.x;
    int head = blockIdx.y;
    int tid  = threadIdx.x;
    int tn   = tid & 15;         // 16 n-blocks of 4
    int tm   = tid >> 4;         // 8 m-blocks of 8 / d-blocks of 4
    int n0   = tn*4, m0 = tm*8, d0 = tm*4;
    size_t base = (size_t)(win*3 + head) * 2048;

    const float4* qg = (const float4*)(g_q + base);
    const float4* kg = (const float4*)(g_k + base);
    const float4* vg = (const float4*)(g_v + base);
    for (int i = tid; i < 512; i += 128) {
        ((float4*)q_s)[i] = qg[i];
        ((float4*)k_s)[i] = kg[i];
        int m = i >> 3, dq = i & 7;
        *(float4*)&v_s[m][dq*4] = vg[i];
    }
    __syncthreads();

    // QK: 4n x 8m tile
    float acc[4][8];
    #pragma unroll
    for (int i = 0; i < 4; i++)
        #pragma unroll
        for (int j = 0; j < 8; j++) acc[i][j] = 0.f;

    #pragma unroll 4
    for (int d = 0; d < 32; d++) {
        float4 qa = *(const float4*)&q_s[d*64 + n0];
        float4 ka = *(const float4*)&k_s[d*64 + m0];
        float4 kb = *(const float4*)&k_s[d*64 + m0 + 4];
        float qv[4] = {qa.x, qa.y, qa.z, qa.w};
        float kv[8] = {ka.x, ka.y, ka.z, ka.w, kb.x, kb.y, kb.z, kb.w};
        #pragma unroll
        for (int i = 0; i < 4; i++)
            #pragma unroll
            for (int j = 0; j < 8; j++)
                acc[i][j] = fmaf(qv[i], kv[j], acc[i][j]);
    }
    __syncthreads();   // done reading q/k before p overwrites

    int wloc = win & 1023;
    int wh = wloc >> 5, ww = wloc & 31;
    bool masked = (wh == 31) || (ww == 31);
    int labn[4], labm[8];
    if (masked) {
        #pragma unroll
        for (int i = 0; i < 4; i++) labn[i] = swin_label(wh, ww, n0 + i);
        #pragma unroll
        for (int j = 0; j < 8; j++) labm[j] = swin_label(wh, ww, m0 + j);
    }
    const float* bb = g_bias + head*4096;
    float lpart[4];
    #pragma unroll
    for (int i = 0; i < 4; i++) {
        float4 b0 = *(const float4*)&bb[(n0 + i)*64 + m0];
        float4 b1 = *(const float4*)&bb[(n0 + i)*64 + m0 + 4];
        float bv[8] = {b0.x, b0.y, b0.z, b0.w, b1.x, b1.y, b1.z, b1.w};
        float lp = 0.f;
        #pragma unroll
        for (int j = 0; j < 8; j++) {
            float p = __expf(acc[i][j] + bv[j]);
            if (masked && labm[j] != labn[i]) p = 0.f;
            acc[i][j] = p;
            lp += p;
        }
        lpart[i] = lp;
    }
    #pragma unroll
    for (int j = 0; j < 8; j++) {
        *(float4*)&p_s[(m0 + j)*64 + n0] =
            make_float4(acc[0][j], acc[1][j], acc[2][j], acc[3][j]);
    }
    #pragma unroll
    for (int i = 0; i < 4; i++) psum_s[n0 + i][tm] = lpart[i];
    __syncthreads();

    // PV: 4n x 4d tile
    float out[4][4];
    #pragma unroll
    for (int i = 0; i < 4; i++)
        #pragma unroll
        for (int cc = 0; cc < 4; cc++) out[i][cc] = 0.f;

    #pragma unroll 4
    for (int m = 0; m < 64; m++) {
        float4 pa = *(const float4*)&p_s[m*64 + n0];
        float4 vv = *(const float4*)&v_s[m][d0];
        float pv[4] = {pa.x, pa.y, pa.z, pa.w};
        #pragma unroll
        for (int i = 0; i < 4; i++) {
            out[i][0] = fmaf(pv[i], vv.x, out[i][0]);
            out[i][1] = fmaf(pv[i], vv.y, out[i][1]);
            out[i][2] = fmaf(pv[i], vv.z, out[i][2]);
            out[i][3] = fmaf(pv[i], vv.w, out[i][3]);
        }
    }

    int b = win >> 10;
    #pragma unroll
    for (int i = 0; i < 4; i++) {
        float l = 0.f;
        #pragma unroll
        for (int j = 0; j < 8; j++) l += psum_s[n0 + i][j];
        float inv = 1.f / l;
        int n = n0 + i;
        int r = n >> 3, cc = n & 7;
        int h = ((wh << 3) + r + 4) & 255;
        int w = ((ww << 3) + cc + 4) & 255;
        float* ap = g_att + ((size_t)(b*256 + h)*256 + w)*96 + head*32 + d0;
        *(float4*)ap = make_float4(out[i][0]*inv, out[i][1]*inv,
                                   out[i][2]*inv, out[i][3]*inv);
    }
}

// ---------------- kernel D: add (conv + attn), final 96x96 GEMM -------------
__global__ __launch_bounds__(256) void final_kernel(
    const float* __restrict__ Wp, const float* __restrict__ bp,
    float* __restrict__ outp)
{
    __shared__ float t_s[64][97];
    __shared__ float w_s[32][97];

    int t   = blockIdx.x;
    int b   = t >> 10;
    int hw0 = (t & 1023) << 6;
    int h   = hw0 >> 8;
    int tid = threadIdx.x;

    for (int idx = tid; idx < 96*16; idx += 256) {
        int c = idx >> 4, pq = idx & 15;
        float4 v4 = *(const float4*)&g_conv[((size_t)b*96 + c)*HW + hw0 + pq*4];
        t_s[pq*4 + 0][c] = v4.x;
        t_s[pq*4 + 1][c] = v4.y;
        t_s[pq*4 + 2][c] = v4.z;
        t_s[pq*4 + 3][c] = v4.w;
    }
    __syncthreads();

    const float* ab = g_att + ((size_t)(b*256 + h)*256 + (hw0 & 255))*96;
    for (int idx = tid; idx < 64*24; idx += 256) {
        int f4 = idx % 24, p = idx / 24;
        float4 a4 = *(const float4*)&ab[p*96 + f4*4];
        int c = f4*4;
        t_s[p][c]     += a4.x;
        t_s[p][c + 1] += a4.y;
        t_s[p][c + 2] += a4.z;
        t_s[p][c + 3] += a4.w;
    }
    __syncthreads();

    int pxg = tid & 15, chg = tid >> 4;
    int p0 = pxg*4, ob = chg*6;
    float acc[6][4];
    #pragma unroll
    for (int i = 0; i < 6; i++)
        #pragma unroll
        for (int j = 0; j < 4; j++) acc[i][j] = 0.f;

    for (int kc = 0; kc < 3; kc++) {
        if (kc) __syncthreads();
        for (int idx = tid; idx < 32*96; idx += 256) {
            int kk = idx & 31, o = idx >> 5;
            w_s[kk][o] = Wp[o*96 + kc*32 + kk];
        }
        __syncthreads();
        #pragma unroll 4
        for (int kk = 0; kk < 32; kk++) {
            int k = kc*32 + kk;
            float tv0 = t_s[p0][k],   tv1 = t_s[p0+1][k];
            float tv2 = t_s[p0+2][k], tv3 = t_s[p0+3][k];
            #pragma unroll
            for (int i = 0; i < 6; i++) {
                float wv = w_s[kk][ob + i];
                acc[i][0] = fmaf(wv, tv0, acc[i][0]);
                acc[i][1] = fmaf(wv, tv1, acc[i][1]);
                acc[i][2] = fmaf(wv, tv2, acc[i][2]);
                acc[i][3] = fmaf(wv, tv3, acc[i][3]);
            }
        }
    }

    #pragma unroll
    for (int i = 0; i < 6; i++) {
        int o = ob + i;
        float bo = bp[o];
        *(float4*)&outp[((size_t)b*96 + o)*HW + hw0 + p0] =
            make_float4(acc[i][0] + bo, acc[i][1] + bo,
                        acc[i][2] + bo, acc[i][3] + bo);
    }
}

// ---------------- launch ------------------------------------------------------
extern "C" void kernel_launch(void* const* d_in, const int* in_sizes, int n_in,
                              void* d_out, int out_size)
{
    const float* x   = (const float*)d_in[0];
    const float* Wv  = (const float*)d_in[1];
    const float* bv  = (const float*)d_in[2];
    const float* Wqk = (const float*)d_in[3];
    const float* bqk = (const float*)d_in[4];
    const float* Wm1 = (const float*)d_in[5];
    const float* bm1 = (const float*)d_in[6];
    const float* Wm2 = (const float*)d_in[7];
    const float* bm2 = (const float*)d_in[8];
    const float* Wdw = (const float*)d_in[9];
    const float* bdw = (const float*)d_in[10];
    const float* Wp  = (const float*)d_in[11];
    const float* bp  = (const float*)d_in[12];
    float* outp = (float*)d_out;

    const int QKV_SMEM = 288*WPAD*2*2 + 128*WPAD*2*2;   // 173056 B
    cudaFuncSetAttribute(qkv_mma_kernel,
                         cudaFuncAttributeMaxDynamicSharedMemorySize, QKV_SMEM);

    // NOTE: qkv_mma_kernel is deliberately the 4th launch (profiled slot)
    prep_hi_kernel<<<(288*WPAD + 255)/256, 256>>>(Wqk, Wv);
    prep_lo_kernel<<<(288*WPAD + 255)/256, 256>>>(Wqk, Wv);
    bias_kernel   <<<16, 256>>>(Wm1, bm1, Wm2, bm2);
    qkv_mma_kernel<<<296, 256, QKV_SMEM>>>(x, bqk, bv);
    dw_kernel     <<<24576, 256>>>(Wdw, bdw);
    attn_kernel   <<<dim3(4096, 3), 128>>>();
    final_kernel  <<<4096, 256>>>(Wp, bp, outp);
}

// round 9
// speedup vs baseline: 1.2641x; 1.1016x over previous
#include <cuda_runtime.h>
#include <cuda_bf16.h>
#include <math.h>
#include <cstdint>

#define BATCH 4
#define CH    96
#define HRES  256
#define WRES  256
#define HW    65536
#define HEADS 3
#define HD    32
#define NPOS  64
#define NWIN  4096
#define QSCALE 0.17677669529663687f
#define WPAD  104

// ---------------- mma.sync / ldmatrix helpers (sm_80+ PTX) ------------------
#define LDM_X4(r, addr) \
    asm volatile("ldmatrix.sync.aligned.m8n8.x4.shared.b16 {%0,%1,%2,%3}, [%4];" \
        : "=r"((r)[0]), "=r"((r)[1]), "=r"((r)[2]), "=r"((r)[3]) : "r"(addr))
#define LDM_X2(r, addr) \
    asm volatile("ldmatrix.sync.aligned.m8n8.x2.shared.b16 {%0,%1}, [%2];" \
        : "=r"((r)[0]), "=r"((r)[1]) : "r"(addr))
#define MMA_BF16(d, a, b) \
    asm volatile("mma.sync.aligned.m16n8k16.row.col.f32.bf16.bf16.f32 " \
        "{%0,%1,%2,%3}, {%4,%5,%6,%7}, {%8,%9}, {%0,%1,%2,%3};" \
        : "+f"((d)[0]), "+f"((d)[1]), "+f"((d)[2]), "+f"((d)[3]) \
        : "r"((a)[0]), "r"((a)[1]), "r"((a)[2]), "r"((a)[3]), \
          "r"((b)[0]), "r"((b)[1]))

__device__ __forceinline__ uint32_t smem_u32(const void* p) {
    uint32_t a;
    asm("{ .reg .u64 t; cvta.to.shared.u64 t, %1; cvt.u32.u64 %0, t; }"
        : "=r"(a) : "l"(p));
    return a;
}

// ---------------- scratch ----------------------------------------------------
__device__ float g_V   [BATCH*CH*HW];
__device__ float g_conv[BATCH*CH*HW];
__device__ float g_q   [NWIN*HEADS*HD*NPOS];
__device__ float g_k   [NWIN*HEADS*HD*NPOS];
__device__ float g_v   [NWIN*HEADS*NPOS*HD];
__device__ float g_att [BATCH*HW*CH];
__device__ float g_bias[HEADS*NPOS*NPOS];
__device__ __align__(16) __nv_bfloat16 g_Whi[288*WPAD];
__device__ __align__(16) __nv_bfloat16 g_Wlo[288*WPAD];

// ---------------- kernels P: split W into bf16 hi/lo padded blobs -----------
__device__ __forceinline__ float wval(const float* Wqk, const float* Wv,
                                      int o, int k) {
    if (k >= 96) return 0.f;
    if (o < 96)       return Wqk[o*96 + k] * QSCALE;
    else if (o < 192) return Wqk[o*96 + k];
    else              return Wv[(o - 192)*96 + k];
}
__global__ void prep_hi_kernel(const float* __restrict__ Wqk,
                               const float* __restrict__ Wv)
{
    int idx = blockIdx.x * 256 + threadIdx.x;
    if (idx >= 288*WPAD) return;
    float w = wval(Wqk, Wv, idx / WPAD, idx % WPAD);
    g_Whi[idx] = __float2bfloat16_rn(w);
}
__global__ void prep_lo_kernel(const float* __restrict__ Wqk,
                               const float* __restrict__ Wv)
{
    int idx = blockIdx.x * 256 + threadIdx.x;
    if (idx >= 288*WPAD) return;
    float w = wval(Wqk, Wv, idx / WPAD, idx % WPAD);
    __nv_bfloat16 hi = __float2bfloat16_rn(w);
    g_Wlo[idx] = __float2bfloat16_rn(w - __bfloat162float(hi));
}

// ---------------- kernel B: bias MLP table ----------------------------------
__global__ void bias_kernel(const float* __restrict__ Wm1, const float* __restrict__ bm1,
                            const float* __restrict__ Wm2, const float* __restrict__ bm2)
{
    int gid = blockIdx.x * 256 + threadIdx.x;
    int n = gid >> 6, m = gid & 63;
    float r0 = (float)((n >> 3) - (m >> 3));
    float r1 = (float)((n & 7)  - (m & 7));
    r0 = copysignf(log1pf(fabsf(r0)), r0);
    r1 = copysignf(log1pf(fabsf(r1)), r1);
    float a0 = bm2[0], a1 = bm2[1], a2 = bm2[2];
    for (int j = 0; j < 256; j++) {
        float h = fmaf(r0, Wm1[j], fmaf(r1, Wm1[256 + j], bm1[j]));
        h = fmaxf(h, 0.f);
        a0 = fmaf(h, Wm2[j*3 + 0], a0);
        a1 = fmaf(h, Wm2[j*3 + 1], a1);
        a2 = fmaf(h, Wm2[j*3 + 2], a2);
    }
    g_bias[0*4096 + gid] = a0;
    g_bias[1*4096 + gid] = a1;
    g_bias[2*4096 + gid] = a2;
}

// ---------------- kernel A: persistent QKV GEMM, 512 thr, 256-px tiles ------
__global__ __launch_bounds__(512, 1) void qkv_mma_kernel(
    const float* __restrict__ x,
    const float* __restrict__ bqk, const float* __restrict__ bv)
{
    extern __shared__ __align__(16) unsigned char dsm[];
    __nv_bfloat16* whi_s = (__nv_bfloat16*)dsm;            // [288*WPAD]
    __nv_bfloat16* wlo_s = whi_s + 288*WPAD;
    __nv_bfloat16* xhi_s = wlo_s + 288*WPAD;               // [256*WPAD]
    __nv_bfloat16* xlo_s = xhi_s + 256*WPAD;
    float* out_s = (float*)(wlo_s + 288*WPAD);             // overlays x area

    int tid  = threadIdx.x;
    int warp = tid >> 5, lane = tid & 31;

    // W blobs -> smem once per block
    {
        const uint4* s1 = (const uint4*)g_Whi; uint4* d1 = (uint4*)whi_s;
        const uint4* s2 = (const uint4*)g_Wlo; uint4* d2 = (uint4*)wlo_s;
        #pragma unroll 4
        for (int i = tid; i < 288*WPAD*2/16; i += 512) { d1[i] = s1[i]; d2[i] = s2[i]; }
    }

    int idx8 = lane & 7, quad = lane >> 3;
    int arow = warp*16 + (quad & 1)*8 + idx8;     // warp owns px rows warp*16..+15
    int acol = (quad >> 1)*8;
    // ldmatrix.x4 B addressing: lanes 0-7 m0, 8-15 m1, 16-23 m2, 24-31 m3
    int brow4 = lane & 7;
    int bcol4 = ((lane >> 3) & 1)*8;
    int brsel = (lane >> 4) & 1;                  // 0: nt, 1: nt+1
    int pq   = tid & 63;
    int p0   = pq*4;
    int c0   = tid >> 6;                          // 0..7
    int orow = warp*16 + (lane >> 2);
    int oc   = (lane & 3)*2;

    for (int tile = blockIdx.x; tile < 1024; tile += gridDim.x) {
        int b   = tile >> 8;
        int hw0 = (tile & 255) << 8;              // one full image row (256 px)

        __syncthreads();   // out_s of previous tile fully consumed
        for (int idx = tid; idx < 96*64; idx += 512) {
            int k = idx >> 6, pg = idx & 63;
            float4 v = *(const float4*)&x[(b*96 + k)*HW + hw0 + pg*4];
            float vf[4] = {v.x, v.y, v.z, v.w};
            #pragma unroll
            for (int j = 0; j < 4; j++) {
                int px = pg*4 + j;
                __nv_bfloat16 hi = __float2bfloat16_rn(vf[j]);
                __nv_bfloat16 lo = __float2bfloat16_rn(vf[j] - __bfloat162float(hi));
                xhi_s[px*WPAD + k] = hi;
                xlo_s[px*WPAD + k] = lo;
            }
        }
        __syncthreads();

        uint32_t ahi[6][4], alo[6][4];
        #pragma unroll
        for (int ks = 0; ks < 6; ks++) {
            LDM_X4(ahi[ks], smem_u32(&xhi_s[arow*WPAD + ks*16 + acol]));
            LDM_X4(alo[ks], smem_u32(&xlo_s[arow*WPAD + ks*16 + acol]));
        }
        __syncthreads();   // x area reusable as out_s

        int hwp = hw0 + p0;
        int h_  = hwp >> 8, w_ = hwp & 255;
        int hp  = (h_ + 252) & 255;
        int wp  = (w_ + 252) & 255;
        int wh  = hp >> 3, ww = wp >> 3;
        int win = b*1024 + wh*32 + ww;
        int n   = (hp & 7)*8 + (wp & 7);
        int whn = win*3;

        #pragma unroll 1
        for (int g = 0; g < 3; g++) {
            float acc[12][4];
            #pragma unroll
            for (int nt = 0; nt < 12; nt++)
                #pragma unroll
                for (int j = 0; j < 4; j++) acc[nt][j] = 0.f;

            int n_base = g*96;
            #pragma unroll 1
            for (int ks = 0; ks < 6; ks++) {
                #pragma unroll
                for (int ntp = 0; ntp < 6; ntp++) {
                    int wrow = (n_base + (2*ntp + brsel)*8 + brow4)*WPAD + ks*16 + bcol4;
                    uint32_t bh[4], bl[4];
                    LDM_X4(bh, smem_u32(&whi_s[wrow]));
                    MMA_BF16(acc[2*ntp    ], ahi[ks], bh);       // hi*hi
                    MMA_BF16(acc[2*ntp    ], alo[ks], bh);       // lo*hi
                    MMA_BF16(acc[2*ntp + 1], ahi[ks], bh + 2);
                    MMA_BF16(acc[2*ntp + 1], alo[ks], bh + 2);
                    LDM_X4(bl, smem_u32(&wlo_s[wrow]));
                    MMA_BF16(acc[2*ntp    ], ahi[ks], bl);       // hi*lo
                    MMA_BF16(acc[2*ntp + 1], ahi[ks], bl + 2);
                }
            }

            // stage accum -> out_s [px][97]
            #pragma unroll
            for (int nt = 0; nt < 12; nt++) {
                out_s[orow*97 + nt*8 + oc]         = acc[nt][0];
                out_s[orow*97 + nt*8 + oc + 1]     = acc[nt][1];
                out_s[(orow+8)*97 + nt*8 + oc]     = acc[nt][2];
                out_s[(orow+8)*97 + nt*8 + oc + 1] = acc[nt][3];
            }
            __syncthreads();

            // cooperative coalesced writeout
            #pragma unroll 1
            for (int j = 0; j < 12; j++) {
                int c = c0 + j*8;
                int head = c >> 5, d = c & 31;
                float v0 = out_s[(p0    )*97 + c];
                float v1 = out_s[(p0 + 1)*97 + c];
                float v2 = out_s[(p0 + 2)*97 + c];
                float v3 = out_s[(p0 + 3)*97 + c];
                if (g == 0) {
                    float bia = bqk[c] * QSCALE;
                    int qi = ((whn + head)*32 + d)*64 + n;
                    *(float4*)&g_q[qi] = make_float4(v0+bia, v1+bia, v2+bia, v3+bia);
                } else if (g == 1) {
                    float bia = bqk[96 + c];
                    int ki = ((whn + head)*32 + d)*64 + n;
                    *(float4*)&g_k[ki] = make_float4(v0+bia, v1+bia, v2+bia, v3+bia);
                } else {
                    float bia = bv[c];
                    int vi = ((whn + head)*64 + n)*32 + d;
                    g_v[vi]      = v0 + bia;
                    g_v[vi + 32] = v1 + bia;
                    g_v[vi + 64] = v2 + bia;
                    g_v[vi + 96] = v3 + bia;
                    *(float4*)&g_V[(b*96 + c)*HW + hwp] =
                        make_float4(v0+bia, v1+bia, v2+bia, v3+bia);
                }
            }
            __syncthreads();
        }
    }
}

// ---------------- kernel DW: depthwise 5x5, vectorized halo -----------------
__global__ __launch_bounds__(256) void dw_kernel(const float* __restrict__ Wdw,
                                                 const float* __restrict__ bdw)
{
    __shared__ __align__(16) float s[36][44];
    __shared__ float wk[25];

    int blk  = blockIdx.x;
    int img  = blk >> 6;
    int tile = blk & 63;
    int c    = img % 96;
    int h0   = (tile >> 3) << 5, w0 = (tile & 7) << 5;
    int tid  = threadIdx.x;

    if (tid < 25) wk[tid] = Wdw[c*25 + tid];
    const float* vimg = g_V + (size_t)img * HW;

    bool border = (h0 == 0) || (h0 == 224) || (w0 == 0) || (w0 == 224);
    if (!border) {
        const float* src = vimg + (h0 - 2)*256 + (w0 - 4);
        for (int idx = tid; idx < 36*11; idx += 256) {
            int r = idx / 11, c4 = idx - r*11;
            *(float4*)&s[r][c4*4] = *(const float4*)&src[r*256 + c4*4];
        }
    } else {
        for (int idx = tid; idx < 36*44; idx += 256) {
            int r  = idx / 44, cc = idx % 44;
            int hh = h0 - 2 + r;  hh = (hh < 0) ? -hh : ((hh > 255) ? 510 - hh : hh);
            int wq = w0 - 4 + cc; wq = (wq < 0) ? -wq : ((wq > 255) ? 510 - wq : wq);
            s[r][cc] = vimg[hh*256 + wq];
        }
    }
    __syncthreads();

    int y   = tid >> 3;
    int xq0 = (tid & 7) * 4;
    float b0 = bdw[c];
    float acc[4] = {b0, b0, b0, b0};
    #pragma unroll
    for (int i = 0; i < 5; i++) {
        float4 fa = *(const float4*)&s[y + i][xq0];
        float4 fb = *(const float4*)&s[y + i][xq0 + 4];
        float4 fc = *(const float4*)&s[y + i][xq0 + 8];
        float f[12] = {fa.x, fa.y, fa.z, fa.w, fb.x, fb.y, fb.z, fb.w,
                       fc.x, fc.y, fc.z, fc.w};
        #pragma unroll
        for (int j = 0; j < 5; j++) {
            float wv = wk[i*5 + j];
            acc[0] = fmaf(f[j + 2], wv, acc[0]);
            acc[1] = fmaf(f[j + 3], wv, acc[1]);
            acc[2] = fmaf(f[j + 4], wv, acc[2]);
            acc[3] = fmaf(f[j + 5], wv, acc[3]);
        }
    }
    *(float4*)&g_conv[(size_t)img*HW + (h0 + y)*256 + (w0 + xq0)] =
        make_float4(acc[0], acc[1], acc[2], acc[3]);
}

// ---------------- kernel C: attention, 128 threads, 4x8 / 4x4 tiles ---------
__device__ __forceinline__ int swin_label(int wh, int ww, int idx) {
    int rh = (wh == 31) ? (1 + (((idx >> 3) >= 4) ? 1 : 0)) : 0;
    int rw = (ww == 31) ? (1 + (((idx & 7)  >= 4) ? 1 : 0)) : 0;
    return rh*3 + rw;
}

__global__ __launch_bounds__(128) void attn_kernel()
{
    __shared__ __align__(16) float buf[4096];
    __shared__ __align__(16) float v_s[64][36];
    __shared__ float psum_s[64][9];

    float* q_s = buf;
    float* k_s = buf + 2048;
    float* p_s = buf;

    int win  = blockIdx.x;
    int head = blockIdx.y;
    int tid  = threadIdx.x;
    int tn   = tid & 15;
    int tm   = tid >> 4;
    int n0   = tn*4, m0 = tm*8, d0 = tm*4;
    size_t base = (size_t)(win*3 + head) * 2048;

    const float4* qg = (const float4*)(g_q + base);
    const float4* kg = (const float4*)(g_k + base);
    const float4* vg = (const float4*)(g_v + base);
    for (int i = tid; i < 512; i += 128) {
        ((float4*)q_s)[i] = qg[i];
        ((float4*)k_s)[i] = kg[i];
        int m = i >> 3, dq = i & 7;
        *(float4*)&v_s[m][dq*4] = vg[i];
    }
    __syncthreads();

    float acc[4][8];
    #pragma unroll
    for (int i = 0; i < 4; i++)
        #pragma unroll
        for (int j = 0; j < 8; j++) acc[i][j] = 0.f;

    #pragma unroll 4
    for (int d = 0; d < 32; d++) {
        float4 qa = *(const float4*)&q_s[d*64 + n0];
        float4 ka = *(const float4*)&k_s[d*64 + m0];
        float4 kb = *(const float4*)&k_s[d*64 + m0 + 4];
        float qv[4] = {qa.x, qa.y, qa.z, qa.w};
        float kv[8] = {ka.x, ka.y, ka.z, ka.w, kb.x, kb.y, kb.z, kb.w};
        #pragma unroll
        for (int i = 0; i < 4; i++)
            #pragma unroll
            for (int j = 0; j < 8; j++)
                acc[i][j] = fmaf(qv[i], kv[j], acc[i][j]);
    }
    __syncthreads();

    int wloc = win & 1023;
    int wh = wloc >> 5, ww = wloc & 31;
    bool masked = (wh == 31) || (ww == 31);
    int labn[4], labm[8];
    if (masked) {
        #pragma unroll
        for (int i = 0; i < 4; i++) labn[i] = swin_label(wh, ww, n0 + i);
        #pragma unroll
        for (int j = 0; j < 8; j++) labm[j] = swin_label(wh, ww, m0 + j);
    }
    const float* bb = g_bias + head*4096;
    float lpart[4];
    #pragma unroll
    for (int i = 0; i < 4; i++) {
        float4 b0 = *(const float4*)&bb[(n0 + i)*64 + m0];
        float4 b1 = *(const float4*)&bb[(n0 + i)*64 + m0 + 4];
        float bv[8] = {b0.x, b0.y, b0.z, b0.w, b1.x, b1.y, b1.z, b1.w};
        float lp = 0.f;
        #pragma unroll
        for (int j = 0; j < 8; j++) {
            float p = __expf(acc[i][j] + bv[j]);
            if (masked && labm[j] != labn[i]) p = 0.f;
            acc[i][j] = p;
            lp += p;
        }
        lpart[i] = lp;
    }
    #pragma unroll
    for (int j = 0; j < 8; j++) {
        *(float4*)&p_s[(m0 + j)*64 + n0] =
            make_float4(acc[0][j], acc[1][j], acc[2][j], acc[3][j]);
    }
    #pragma unroll
    for (int i = 0; i < 4; i++) psum_s[n0 + i][tm] = lpart[i];
    __syncthreads();

    float out[4][4];
    #pragma unroll
    for (int i = 0; i < 4; i++)
        #pragma unroll
        for (int cc = 0; cc < 4; cc++) out[i][cc] = 0.f;

    #pragma unroll 4
    for (int m = 0; m < 64; m++) {
        float4 pa = *(const float4*)&p_s[m*64 + n0];
        float4 vv = *(const float4*)&v_s[m][d0];
        float pv[4] = {pa.x, pa.y, pa.z, pa.w};
        #pragma unroll
        for (int i = 0; i < 4; i++) {
            out[i][0] = fmaf(pv[i], vv.x, out[i][0]);
            out[i][1] = fmaf(pv[i], vv.y, out[i][1]);
            out[i][2] = fmaf(pv[i], vv.z, out[i][2]);
            out[i][3] = fmaf(pv[i], vv.w, out[i][3]);
        }
    }

    int b = win >> 10;
    #pragma unroll
    for (int i = 0; i < 4; i++) {
        float l = 0.f;
        #pragma unroll
        for (int j = 0; j < 8; j++) l += psum_s[n0 + i][j];
        float inv = 1.f / l;
        int n = n0 + i;
        int r = n >> 3, cc = n & 7;
        int h = ((wh << 3) + r + 4) & 255;
        int w = ((ww << 3) + cc + 4) & 255;
        float* ap = g_att + ((size_t)(b*256 + h)*256 + w)*96 + head*32 + d0;
        *(float4*)ap = make_float4(out[i][0]*inv, out[i][1]*inv,
                                   out[i][2]*inv, out[i][3]*inv);
    }
}

// ---------------- kernel D: add (conv + attn), final 96x96 GEMM -------------
__global__ __launch_bounds__(256) void final_kernel(
    const float* __restrict__ Wp, const float* __restrict__ bp,
    float* __restrict__ outp)
{
    __shared__ float t_s[64][97];
    __shared__ float w_s[32][97];

    int t   = blockIdx.x;
    int b   = t >> 10;
    int hw0 = (t & 1023) << 6;
    int h   = hw0 >> 8;
    int tid = threadIdx.x;

    for (int idx = tid; idx < 96*16; idx += 256) {
        int c = idx >> 4, pq = idx & 15;
        float4 v4 = *(const float4*)&g_conv[((size_t)b*96 + c)*HW + hw0 + pq*4];
        t_s[pq*4 + 0][c] = v4.x;
        t_s[pq*4 + 1][c] = v4.y;
        t_s[pq*4 + 2][c] = v4.z;
        t_s[pq*4 + 3][c] = v4.w;
    }
    __syncthreads();

    const float* ab = g_att + ((size_t)(b*256 + h)*256 + (hw0 & 255))*96;
    for (int idx = tid; idx < 64*24; idx += 256) {
        int f4 = idx % 24, p = idx / 24;
        float4 a4 = *(const float4*)&ab[p*96 + f4*4];
        int c = f4*4;
        t_s[p][c]     += a4.x;
        t_s[p][c + 1] += a4.y;
        t_s[p][c + 2] += a4.z;
        t_s[p][c + 3] += a4.w;
    }
    __syncthreads();

    int pxg = tid & 15, chg = tid >> 4;
    int p0 = pxg*4, ob = chg*6;
    float acc[6][4];
    #pragma unroll
    for (int i = 0; i < 6; i++)
        #pragma unroll
        for (int j = 0; j < 4; j++) acc[i][j] = 0.f;

    for (int kc = 0; kc < 3; kc++) {
        if (kc) __syncthreads();
        for (int idx = tid; idx < 32*96; idx += 256) {
            int kk = idx & 31, o = idx >> 5;
            w_s[kk][o] = Wp[o*96 + kc*32 + kk];
        }
        __syncthreads();
        #pragma unroll 4
        for (int kk = 0; kk < 32; kk++) {
            int k = kc*32 + kk;
            float tv0 = t_s[p0][k],   tv1 = t_s[p0+1][k];
            float tv2 = t_s[p0+2][k], tv3 = t_s[p0+3][k];
            #pragma unroll
            for (int i = 0; i < 6; i++) {
                float wv = w_s[kk][ob + i];
                acc[i][0] = fmaf(wv, tv0, acc[i][0]);
                acc[i][1] = fmaf(wv, tv1, acc[i][1]);
                acc[i][2] = fmaf(wv, tv2, acc[i][2]);
                acc[i][3] = fmaf(wv, tv3, acc[i][3]);
            }
        }
    }

    #pragma unroll
    for (int i = 0; i < 6; i++) {
        int o = ob + i;
        float bo = bp[o];
        *(float4*)&outp[((size_t)b*96 + o)*HW + hw0 + p0] =
            make_float4(acc[i][0] + bo, acc[i][1] + bo,
                        acc[i][2] + bo, acc[i][3] + bo);
    }
}

// ---------------- launch ------------------------------------------------------
extern "C" void kernel_launch(void* const* d_in, const int* in_sizes, int n_in,
                              void* d_out, int out_size)
{
    const float* x   = (const float*)d_in[0];
    const float* Wv  = (const float*)d_in[1];
    const float* bv  = (const float*)d_in[2];
    const float* Wqk = (const float*)d_in[3];
    const float* bqk = (const float*)d_in[4];
    const float* Wm1 = (const float*)d_in[5];
    const float* bm1 = (const float*)d_in[6];
    const float* Wm2 = (const float*)d_in[7];
    const float* bm2 = (const float*)d_in[8];
    const float* Wdw = (const float*)d_in[9];
    const float* bdw = (const float*)d_in[10];
    const float* Wp  = (const float*)d_in[11];
    const float* bp  = (const float*)d_in[12];
    float* outp = (float*)d_out;

    // smem: W hi+lo 119808 B + x hi/lo (256 px) 106496 B = 226304 B
    const int QKV_SMEM = 288*WPAD*2*2 + 256*WPAD*2*2;
    cudaFuncSetAttribute(qkv_mma_kernel,
                         cudaFuncAttributeMaxDynamicSharedMemorySize, QKV_SMEM);

    // NOTE: qkv_mma_kernel stays the 4th launch (profiled slot)
    prep_hi_kernel<<<(288*WPAD + 255)/256, 256>>>(Wqk, Wv);
    prep_lo_kernel<<<(288*WPAD + 255)/256, 256>>>(Wqk, Wv);
    bias_kernel   <<<16, 256>>>(Wm1, bm1, Wm2, bm2);
    qkv_mma_kernel<<<148, 512, QKV_SMEM>>>(x, bqk, bv);
    dw_kernel     <<<24576, 256>>>(Wdw, bdw);
    attn_kernel   <<<dim3(4096, 3), 128>>>();
    final_kernel  <<<4096, 256>>>(Wp, bp, outp);
}

// round 10
// speedup vs baseline: 1.5377x; 1.2164x over previous
#include <cuda_runtime.h>
#include <cuda_bf16.h>
#include <math.h>
#include <cstdint>

#define BATCH 4
#define CH    96
#define HRES  256
#define WRES  256
#define HW    65536
#define HEADS 3
#define HD    32
#define NPOS  64
#define NWIN  4096
#define QSCALE 0.17677669529663687f
#define WPAD  104
#define PXPAD 264    // halfwords per k-row of x staging (256 px + 8 pad)

// ---------------- mma.sync / ldmatrix helpers (sm_80+ PTX) ------------------
#define LDM_X4(r, addr) \
    asm volatile("ldmatrix.sync.aligned.m8n8.x4.shared.b16 {%0,%1,%2,%3}, [%4];" \
        : "=r"((r)[0]), "=r"((r)[1]), "=r"((r)[2]), "=r"((r)[3]) : "r"(addr))
#define LDM_X4T(r, addr) \
    asm volatile("ldmatrix.sync.aligned.m8n8.x4.trans.shared.b16 {%0,%1,%2,%3}, [%4];" \
        : "=r"((r)[0]), "=r"((r)[1]), "=r"((r)[2]), "=r"((r)[3]) : "r"(addr))
#define MMA_BF16(d, a, b) \
    asm volatile("mma.sync.aligned.m16n8k16.row.col.f32.bf16.bf16.f32 " \
        "{%0,%1,%2,%3}, {%4,%5,%6,%7}, {%8,%9}, {%0,%1,%2,%3};" \
        : "+f"((d)[0]), "+f"((d)[1]), "+f"((d)[2]), "+f"((d)[3]) \
        : "r"((a)[0]), "r"((a)[1]), "r"((a)[2]), "r"((a)[3]), \
          "r"((b)[0]), "r"((b)[1]))

__device__ __forceinline__ uint32_t smem_u32(const void* p) {
    uint32_t a;
    asm("{ .reg .u64 t; cvta.to.shared.u64 t, %1; cvt.u32.u64 %0, t; }"
        : "=r"(a) : "l"(p));
    return a;
}

// ---------------- scratch ----------------------------------------------------
__device__ float g_V   [BATCH*CH*HW];
__device__ float g_conv[BATCH*CH*HW];
__device__ float g_q   [NWIN*HEADS*HD*NPOS];   // [win][head][d][n]
__device__ float g_k   [NWIN*HEADS*HD*NPOS];   // [win][head][d][m]
__device__ float g_v   [NWIN*HEADS*HD*NPOS];   // [win][head][d][m]  (same as k!)
__device__ float g_att [BATCH*HW*CH];
__device__ float g_bias[HEADS*NPOS*NPOS];
__device__ __align__(16) __nv_bfloat16 g_Whi[288*WPAD];
__device__ __align__(16) __nv_bfloat16 g_Wlo[288*WPAD];

// ---------------- kernels P: split W into bf16 hi/lo padded blobs -----------
__device__ __forceinline__ float wval(const float* Wqk, const float* Wv,
                                      int o, int k) {
    if (k >= 96) return 0.f;
    if (o < 96)       return Wqk[o*96 + k] * QSCALE;
    else if (o < 192) return Wqk[o*96 + k];
    else              return Wv[(o - 192)*96 + k];
}
__global__ void prep_hi_kernel(const float* __restrict__ Wqk,
                               const float* __restrict__ Wv)
{
    int idx = blockIdx.x * 256 + threadIdx.x;
    if (idx >= 288*WPAD) return;
    float w = wval(Wqk, Wv, idx / WPAD, idx % WPAD);
    g_Whi[idx] = __float2bfloat16_rn(w);
}
__global__ void prep_lo_kernel(const float* __restrict__ Wqk,
                               const float* __restrict__ Wv)
{
    int idx = blockIdx.x * 256 + threadIdx.x;
    if (idx >= 288*WPAD) return;
    float w = wval(Wqk, Wv, idx / WPAD, idx % WPAD);
    __nv_bfloat16 hi = __float2bfloat16_rn(w);
    g_Wlo[idx] = __float2bfloat16_rn(w - __bfloat162float(hi));
}

// ---------------- kernel B: bias MLP table ----------------------------------
__global__ void bias_kernel(const float* __restrict__ Wm1, const float* __restrict__ bm1,
                            const float* __restrict__ Wm2, const float* __restrict__ bm2)
{
    int gid = blockIdx.x * 256 + threadIdx.x;
    int n = gid >> 6, m = gid & 63;
    float r0 = (float)((n >> 3) - (m >> 3));
    float r1 = (float)((n & 7)  - (m & 7));
    r0 = copysignf(log1pf(fabsf(r0)), r0);
    r1 = copysignf(log1pf(fabsf(r1)), r1);
    float a0 = bm2[0], a1 = bm2[1], a2 = bm2[2];
    for (int j = 0; j < 256; j++) {
        float h = fmaf(r0, Wm1[j], fmaf(r1, Wm1[256 + j], bm1[j]));
        h = fmaxf(h, 0.f);
        a0 = fmaf(h, Wm2[j*3 + 0], a0);
        a1 = fmaf(h, Wm2[j*3 + 1], a1);
        a2 = fmaf(h, Wm2[j*3 + 2], a2);
    }
    g_bias[0*4096 + gid] = a0;
    g_bias[1*4096 + gid] = a1;
    g_bias[2*4096 + gid] = a2;
}

// ---------------- kernel A: persistent QKV GEMM, conflict-tuned staging -----
__global__ __launch_bounds__(512, 1) void qkv_mma_kernel(
    const float* __restrict__ x,
    const float* __restrict__ bqk, const float* __restrict__ bv)
{
    extern __shared__ __align__(16) unsigned char dsm[];
    __nv_bfloat16* whi_s = (__nv_bfloat16*)dsm;            // [288*WPAD]
    __nv_bfloat16* wlo_s = whi_s + 288*WPAD;
    __nv_bfloat16* xhi_s = wlo_s + 288*WPAD;               // [96][PXPAD] k-major
    __nv_bfloat16* xlo_s = xhi_s + 96*PXPAD;
    float* out_s = (float*)xhi_s;                          // [96 c][264 px] union

    int tid  = threadIdx.x;
    int warp = tid >> 5, lane = tid & 31;

    // W blobs -> smem once per block
    {
        const uint4* s1 = (const uint4*)g_Whi; uint4* d1 = (uint4*)whi_s;
        const uint4* s2 = (const uint4*)g_Wlo; uint4* d2 = (uint4*)wlo_s;
        #pragma unroll 4
        for (int i = tid; i < 288*WPAD*2/16; i += 512) { d1[i] = s1[i]; d2[i] = s2[i]; }
    }

    int idx8 = lane & 7, quad = lane >> 3;
    // A via ldmatrix.trans from [k][px]: lanes address k-rows
    int krow = (quad >> 1)*8 + idx8;
    int apxb = warp*16 + (quad & 1)*8;
    // B (W) via non-trans ldmatrix.x4 from [o][k]
    int brow4 = lane & 7;
    int bcol4 = ((lane >> 3) & 1)*8;
    int brsel = (lane >> 4) & 1;
    int pq   = tid & 63;
    int p0   = pq*4;
    int c0   = tid >> 6;
    int orow = warp*16 + (lane >> 2);
    int oc   = (lane & 3)*2;

    for (int tile = blockIdx.x; tile < 1024; tile += gridDim.x) {
        int b   = tile >> 8;
        int hw0 = (tile & 255) << 8;          // one full image row

        __syncthreads();   // out_s of previous tile fully consumed
        // x staging: [k][px] bf16, contiguous 8B stores (conflict-free)
        for (int idx = tid; idx < 96*64; idx += 512) {
            int k = idx >> 6, pg = idx & 63;
            float4 v = *(const float4*)&x[(b*96 + k)*HW + hw0 + pg*4];
            __nv_bfloat16 h0 = __float2bfloat16_rn(v.x);
            __nv_bfloat16 h1 = __float2bfloat16_rn(v.y);
            __nv_bfloat16 h2 = __float2bfloat16_rn(v.z);
            __nv_bfloat16 h3 = __float2bfloat16_rn(v.w);
            uint32_t hp0 = (uint32_t)__bfloat16_as_ushort(h1) << 16 | __bfloat16_as_ushort(h0);
            uint32_t hp1 = (uint32_t)__bfloat16_as_ushort(h3) << 16 | __bfloat16_as_ushort(h2);
            __nv_bfloat16 l0 = __float2bfloat16_rn(v.x - __bfloat162float(h0));
            __nv_bfloat16 l1 = __float2bfloat16_rn(v.y - __bfloat162float(h1));
            __nv_bfloat16 l2 = __float2bfloat16_rn(v.z - __bfloat162float(h2));
            __nv_bfloat16 l3 = __float2bfloat16_rn(v.w - __bfloat162float(h3));
            uint32_t lp0 = (uint32_t)__bfloat16_as_ushort(l1) << 16 | __bfloat16_as_ushort(l0);
            uint32_t lp1 = (uint32_t)__bfloat16_as_ushort(l3) << 16 | __bfloat16_as_ushort(l2);
            *(uint2*)&xhi_s[k*PXPAD + pg*4] = make_uint2(hp0, hp1);
            *(uint2*)&xlo_s[k*PXPAD + pg*4] = make_uint2(lp0, lp1);
        }
        __syncthreads();

        // A fragments via ldmatrix.trans (held through all 3 groups)
        uint32_t ahi[6][4], alo[6][4];
        #pragma unroll
        for (int ks = 0; ks < 6; ks++) {
            LDM_X4T(ahi[ks], smem_u32(&xhi_s[(ks*16 + krow)*PXPAD + apxb]));
            LDM_X4T(alo[ks], smem_u32(&xlo_s[(ks*16 + krow)*PXPAD + apxb]));
        }
        __syncthreads();   // x area reusable as out_s

        int hwp = hw0 + p0;
        int h_  = hwp >> 8, w_ = hwp & 255;
        int hp  = (h_ + 252) & 255;
        int wp  = (w_ + 252) & 255;
        int wh  = hp >> 3, ww = wp >> 3;
        int win = b*1024 + wh*32 + ww;
        int n   = (hp & 7)*8 + (wp & 7);
        int whn = win*3;

        #pragma unroll 1
        for (int g = 0; g < 3; g++) {
            float acc[12][4];
            #pragma unroll
            for (int nt = 0; nt < 12; nt++)
                #pragma unroll
                for (int j = 0; j < 4; j++) acc[nt][j] = 0.f;

            int n_base = g*96;
            #pragma unroll 1
            for (int ks = 0; ks < 6; ks++) {
                #pragma unroll
                for (int ntp = 0; ntp < 6; ntp++) {
                    int wrow = (n_base + (2*ntp + brsel)*8 + brow4)*WPAD + ks*16 + bcol4;
                    uint32_t bh[4], bl[4];
                    LDM_X4(bh, smem_u32(&whi_s[wrow]));
                    MMA_BF16(acc[2*ntp    ], ahi[ks], bh);
                    MMA_BF16(acc[2*ntp    ], alo[ks], bh);
                    MMA_BF16(acc[2*ntp + 1], ahi[ks], bh + 2);
                    MMA_BF16(acc[2*ntp + 1], alo[ks], bh + 2);
                    LDM_X4(bl, smem_u32(&wlo_s[wrow]));
                    MMA_BF16(acc[2*ntp    ], ahi[ks], bl);
                    MMA_BF16(acc[2*ntp + 1], ahi[ks], bl + 2);
                }
            }

            // stage accum -> out_s [c][px]
            #pragma unroll
            for (int nt = 0; nt < 12; nt++) {
                out_s[(nt*8 + oc    )*264 + orow    ] = acc[nt][0];
                out_s[(nt*8 + oc + 1)*264 + orow    ] = acc[nt][1];
                out_s[(nt*8 + oc    )*264 + orow + 8] = acc[nt][2];
                out_s[(nt*8 + oc + 1)*264 + orow + 8] = acc[nt][3];
            }
            __syncthreads();

            // epilogue: contiguous LDS.128 reads, float4 global stores
            #pragma unroll 1
            for (int j = 0; j < 12; j++) {
                int c = c0 + j*8;
                int head = c >> 5, d = c & 31;
                float4 v4 = *(const float4*)&out_s[c*264 + p0];
                int gi = ((whn + head)*32 + d)*64 + n;
                if (g == 0) {
                    float bia = bqk[c] * QSCALE;
                    *(float4*)&g_q[gi] = make_float4(v4.x+bia, v4.y+bia, v4.z+bia, v4.w+bia);
                } else if (g == 1) {
                    float bia = bqk[96 + c];
                    *(float4*)&g_k[gi] = make_float4(v4.x+bia, v4.y+bia, v4.z+bia, v4.w+bia);
                } else {
                    float bia = bv[c];
                    float4 vo = make_float4(v4.x+bia, v4.y+bia, v4.z+bia, v4.w+bia);
                    *(float4*)&g_v[gi] = vo;                          // [d][m] layout
                    *(float4*)&g_V[(b*96 + c)*HW + hwp] = vo;         // NCHW for dw
                }
            }
            __syncthreads();
        }
    }
}

// ---------------- kernel DW: depthwise 5x5, vectorized halo -----------------
__global__ __launch_bounds__(256) void dw_kernel(const float* __restrict__ Wdw,
                                                 const float* __restrict__ bdw)
{
    __shared__ __align__(16) float s[36][44];
    __shared__ float wk[25];

    int blk  = blockIdx.x;
    int img  = blk >> 6;
    int tile = blk & 63;
    int c    = img % 96;
    int h0   = (tile >> 3) << 5, w0 = (tile & 7) << 5;
    int tid  = threadIdx.x;

    if (tid < 25) wk[tid] = Wdw[c*25 + tid];
    const float* vimg = g_V + (size_t)img * HW;

    bool border = (h0 == 0) || (h0 == 224) || (w0 == 0) || (w0 == 224);
    if (!border) {
        const float* src = vimg + (h0 - 2)*256 + (w0 - 4);
        for (int idx = tid; idx < 36*11; idx += 256) {
            int r = idx / 11, c4 = idx - r*11;
            *(float4*)&s[r][c4*4] = *(const float4*)&src[r*256 + c4*4];
        }
    } else {
        for (int idx = tid; idx < 36*44; idx += 256) {
            int r  = idx / 44, cc = idx % 44;
            int hh = h0 - 2 + r;  hh = (hh < 0) ? -hh : ((hh > 255) ? 510 - hh : hh);
            int wq = w0 - 4 + cc; wq = (wq < 0) ? -wq : ((wq > 255) ? 510 - wq : wq);
            s[r][cc] = vimg[hh*256 + wq];
        }
    }
    __syncthreads();

    int y   = tid >> 3;
    int xq0 = (tid & 7) * 4;
    float b0 = bdw[c];
    float acc[4] = {b0, b0, b0, b0};
    #pragma unroll
    for (int i = 0; i < 5; i++) {
        float4 fa = *(const float4*)&s[y + i][xq0];
        float4 fb = *(const float4*)&s[y + i][xq0 + 4];
        float4 fc = *(const float4*)&s[y + i][xq0 + 8];
        float f[12] = {fa.x, fa.y, fa.z, fa.w, fb.x, fb.y, fb.z, fb.w,
                       fc.x, fc.y, fc.z, fc.w};
        #pragma unroll
        for (int j = 0; j < 5; j++) {
            float wv = wk[i*5 + j];
            acc[0] = fmaf(f[j + 2], wv, acc[0]);
            acc[1] = fmaf(f[j + 3], wv, acc[1]);
            acc[2] = fmaf(f[j + 4], wv, acc[2]);
            acc[3] = fmaf(f[j + 5], wv, acc[3]);
        }
    }
    *(float4*)&g_conv[(size_t)img*HW + (h0 + y)*256 + (w0 + xq0)] =
        make_float4(acc[0], acc[1], acc[2], acc[3]);
}

// ---------------- kernel C: attention (v now [d][m]) -------------------------
__device__ __forceinline__ int swin_label(int wh, int ww, int idx) {
    int rh = (wh == 31) ? (1 + (((idx >> 3) >= 4) ? 1 : 0)) : 0;
    int rw = (ww == 31) ? (1 + (((idx & 7)  >= 4) ? 1 : 0)) : 0;
    return rh*3 + rw;
}

__global__ __launch_bounds__(128) void attn_kernel()
{
    __shared__ __align__(16) float buf[4096];      // q[2048]+k[2048] OR p[4096]
    __shared__ __align__(16) float v_s[2048];      // [d][m]
    __shared__ float psum_s[64][9];

    float* q_s = buf;
    float* k_s = buf + 2048;
    float* p_s = buf;            // [m][n] after QK

    int win  = blockIdx.x;
    int head = blockIdx.y;
    int tid  = threadIdx.x;
    int tn   = tid & 15;
    int tm   = tid >> 4;
    int n0   = tn*4, m0 = tm*8, d0 = tm*4;
    size_t base = (size_t)(win*3 + head) * 2048;

    const float4* qg = (const float4*)(g_q + base);
    const float4* kg = (const float4*)(g_k + base);
    const float4* vg = (const float4*)(g_v + base);
    for (int i = tid; i < 512; i += 128) {
        ((float4*)q_s)[i] = qg[i];
        ((float4*)k_s)[i] = kg[i];
        ((float4*)v_s)[i] = vg[i];
    }
    __syncthreads();

    float acc[4][8];
    #pragma unroll
    for (int i = 0; i < 4; i++)
        #pragma unroll
        for (int j = 0; j < 8; j++) acc[i][j] = 0.f;

    #pragma unroll 4
    for (int d = 0; d < 32; d++) {
        float4 qa = *(const float4*)&q_s[d*64 + n0];
        float4 ka = *(const float4*)&k_s[d*64 + m0];
        float4 kb = *(const float4*)&k_s[d*64 + m0 + 4];
        float qv[4] = {qa.x, qa.y, qa.z, qa.w};
        float kv[8] = {ka.x, ka.y, ka.z, ka.w, kb.x, kb.y, kb.z, kb.w};
        #pragma unroll
        for (int i = 0; i < 4; i++)
            #pragma unroll
            for (int j = 0; j < 8; j++)
                acc[i][j] = fmaf(qv[i], kv[j], acc[i][j]);
    }
    __syncthreads();

    int wloc = win & 1023;
    int wh = wloc >> 5, ww = wloc & 31;
    bool masked = (wh == 31) || (ww == 31);
    int labn[4], labm[8];
    if (masked) {
        #pragma unroll
        for (int i = 0; i < 4; i++) labn[i] = swin_label(wh, ww, n0 + i);
        #pragma unroll
        for (int j = 0; j < 8; j++) labm[j] = swin_label(wh, ww, m0 + j);
    }
    const float* bb = g_bias + head*4096;
    float lpart[4];
    #pragma unroll
    for (int i = 0; i < 4; i++) {
        float4 b0 = *(const float4*)&bb[(n0 + i)*64 + m0];
        float4 b1 = *(const float4*)&bb[(n0 + i)*64 + m0 + 4];
        float bv[8] = {b0.x, b0.y, b0.z, b0.w, b1.x, b1.y, b1.z, b1.w};
        float lp = 0.f;
        #pragma unroll
        for (int j = 0; j < 8; j++) {
            float p = __expf(acc[i][j] + bv[j]);
            if (masked && labm[j] != labn[i]) p = 0.f;
            acc[i][j] = p;
            lp += p;
        }
        lpart[i] = lp;
    }
    #pragma unroll
    for (int j = 0; j < 8; j++) {
        *(float4*)&p_s[(m0 + j)*64 + n0] =
            make_float4(acc[0][j], acc[1][j], acc[2][j], acc[3][j]);
    }
    #pragma unroll
    for (int i = 0; i < 4; i++) psum_s[n0 + i][tm] = lpart[i];
    __syncthreads();

    // PV with v [d][m]: 4n x 4d tile, m in chunks of 4
    float out[4][4];
    #pragma unroll
    for (int i = 0; i < 4; i++)
        #pragma unroll
        for (int cc = 0; cc < 4; cc++) out[i][cc] = 0.f;

    #pragma unroll 2
    for (int m = 0; m < 64; m += 4) {
        float pf[4][4], vf[4][4];
        #pragma unroll
        for (int mm = 0; mm < 4; mm++)
            *(float4*)pf[mm] = *(const float4*)&p_s[(m + mm)*64 + n0];
        #pragma unroll
        for (int cc = 0; cc < 4; cc++)
            *(float4*)vf[cc] = *(const float4*)&v_s[(d0 + cc)*64 + m];
        #pragma unroll
        for (int cc = 0; cc < 4; cc++)
            #pragma unroll
            for (int mm = 0; mm < 4; mm++)
                #pragma unroll
                for (int i = 0; i < 4; i++)
                    out[i][cc] = fmaf(pf[mm][i], vf[cc][mm], out[i][cc]);
    }

    int b = win >> 10;
    #pragma unroll
    for (int i = 0; i < 4; i++) {
        float l = 0.f;
        #pragma unroll
        for (int j = 0; j < 8; j++) l += psum_s[n0 + i][j];
        float inv = 1.f / l;
        int n = n0 + i;
        int r = n >> 3, cc = n & 7;
        int h = ((wh << 3) + r + 4) & 255;
        int w = ((ww << 3) + cc + 4) & 255;
        float* ap = g_att + ((size_t)(b*256 + h)*256 + w)*96 + head*32 + d0;
        *(float4*)ap = make_float4(out[i][0]*inv, out[i][1]*inv,
                                   out[i][2]*inv, out[i][3]*inv);
    }
}

// ---------------- kernel D: add (conv + attn), final 96x96 GEMM -------------
__global__ __launch_bounds__(256) void final_kernel(
    const float* __restrict__ Wp, const float* __restrict__ bp,
    float* __restrict__ outp)
{
    __shared__ float t_s[64][97];
    __shared__ float w_s[32][97];

    int t   = blockIdx.x;
    int b   = t >> 10;
    int hw0 = (t & 1023) << 6;
    int h   = hw0 >> 8;
    int tid = threadIdx.x;

    for (int idx = tid; idx < 96*16; idx += 256) {
        int c = idx >> 4, pq = idx & 15;
        float4 v4 = *(const float4*)&g_conv[((size_t)b*96 + c)*HW + hw0 + pq*4];
        t_s[pq*4 + 0][c] = v4.x;
        t_s[pq*4 + 1][c] = v4.y;
        t_s[pq*4 + 2][c] = v4.z;
        t_s[pq*4 + 3][c] = v4.w;
    }
    __syncthreads();

    const float* ab = g_att + ((size_t)(b*256 + h)*256 + (hw0 & 255))*96;
    for (int idx = tid; idx < 64*24; idx += 256) {
        int f4 = idx % 24, p = idx / 24;
        float4 a4 = *(const float4*)&ab[p*96 + f4*4];
        int c = f4*4;
        t_s[p][c]     += a4.x;
        t_s[p][c + 1] += a4.y;
        t_s[p][c + 2] += a4.z;
        t_s[p][c + 3] += a4.w;
    }
    __syncthreads();

    int pxg = tid & 15, chg = tid >> 4;
    int p0 = pxg*4, ob = chg*6;
    float acc[6][4];
    #pragma unroll
    for (int i = 0; i < 6; i++)
        #pragma unroll
        for (int j = 0; j < 4; j++) acc[i][j] = 0.f;

    for (int kc = 0; kc < 3; kc++) {
        if (kc) __syncthreads();
        for (int idx = tid; idx < 32*96; idx += 256) {
            int kk = idx & 31, o = idx >> 5;
            w_s[kk][o] = Wp[o*96 + kc*32 + kk];
        }
        __syncthreads();
        #pragma unroll 4
        for (int kk = 0; kk < 32; kk++) {
            int k = kc*32 + kk;
            float tv0 = t_s[p0][k],   tv1 = t_s[p0+1][k];
            float tv2 = t_s[p0+2][k], tv3 = t_s[p0+3][k];
            #pragma unroll
            for (int i = 0; i < 6; i++) {
                float wv = w_s[kk][ob + i];
                acc[i][0] = fmaf(wv, tv0, acc[i][0]);
                acc[i][1] = fmaf(wv, tv1, acc[i][1]);
                acc[i][2] = fmaf(wv, tv2, acc[i][2]);
                acc[i][3] = fmaf(wv, tv3, acc[i][3]);
            }
        }
    }

    #pragma unroll
    for (int i = 0; i < 6; i++) {
        int o = ob + i;
        float bo = bp[o];
        *(float4*)&outp[((size_t)b*96 + o)*HW + hw0 + p0] =
            make_float4(acc[i][0] + bo, acc[i][1] + bo,
                        acc[i][2] + bo, acc[i][3] + bo);
    }
}

// ---------------- launch ------------------------------------------------------
extern "C" void kernel_launch(void* const* d_in, const int* in_sizes, int n_in,
                              void* d_out, int out_size)
{
    const float* x   = (const float*)d_in[0];
    const float* Wv  = (const float*)d_in[1];
    const float* bv  = (const float*)d_in[2];
    const float* Wqk = (const float*)d_in[3];
    const float* bqk = (const float*)d_in[4];
    const float* Wm1 = (const float*)d_in[5];
    const float* bm1 = (const float*)d_in[6];
    const float* Wm2 = (const float*)d_in[7];
    const float* bm2 = (const float*)d_in[8];
    const float* Wdw = (const float*)d_in[9];
    const float* bdw = (const float*)d_in[10];
    const float* Wp  = (const float*)d_in[11];
    const float* bp  = (const float*)d_in[12];
    float* outp = (float*)d_out;

    // smem: W hi+lo 119808 B + x/out union 101376 B = 221184 B
    const int QKV_SMEM = 288*WPAD*2*2 + 96*PXPAD*2*2;
    cudaFuncSetAttribute(qkv_mma_kernel,
                         cudaFuncAttributeMaxDynamicSharedMemorySize, QKV_SMEM);

    // NOTE: qkv_mma_kernel stays the 4th launch (profiled slot)
    prep_hi_kernel<<<(288*WPAD + 255)/256, 256>>>(Wqk, Wv);
    prep_lo_kernel<<<(288*WPAD + 255)/256, 256>>>(Wqk, Wv);
    bias_kernel   <<<16, 256>>>(Wm1, bm1, Wm2, bm2);
    qkv_mma_kernel<<<148, 512, QKV_SMEM>>>(x, bqk, bv);
    dw_kernel     <<<24576, 256>>>(Wdw, bdw);
    attn_kernel   <<<dim3(4096, 3), 128>>>();
    final_kernel  <<<4096, 256>>>(Wp, bp, outp);
}

// round 11
// speedup vs baseline: 1.8193x; 1.1831x over previous
#include <cuda_runtime.h>
#include <cuda_bf16.h>
#include <math.h>
#include <cstdint>

#define BATCH 4
#define CH    96
#define HRES  256
#define WRES  256
#define HW    65536
#define HEADS 3
#define HD    32
#define NPOS  64
#define NWIN  4096
#define QSCALE 0.17677669529663687f
#define WPAD  104
#define PXPAD 264

// ---------------- mma.sync / ldmatrix helpers (sm_80+ PTX) ------------------
#define LDM_X4(r, addr) \
    asm volatile("ldmatrix.sync.aligned.m8n8.x4.shared.b16 {%0,%1,%2,%3}, [%4];" \
        : "=r"((r)[0]), "=r"((r)[1]), "=r"((r)[2]), "=r"((r)[3]) : "r"(addr))
#define LDM_X4T(r, addr) \
    asm volatile("ldmatrix.sync.aligned.m8n8.x4.trans.shared.b16 {%0,%1,%2,%3}, [%4];" \
        : "=r"((r)[0]), "=r"((r)[1]), "=r"((r)[2]), "=r"((r)[3]) : "r"(addr))
#define MMA_BF16(d, a, b) \
    asm volatile("mma.sync.aligned.m16n8k16.row.col.f32.bf16.bf16.f32 " \
        "{%0,%1,%2,%3}, {%4,%5,%6,%7}, {%8,%9}, {%0,%1,%2,%3};" \
        : "+f"((d)[0]), "+f"((d)[1]), "+f"((d)[2]), "+f"((d)[3]) \
        : "r"((a)[0]), "r"((a)[1]), "r"((a)[2]), "r"((a)[3]), \
          "r"((b)[0]), "r"((b)[1]))

__device__ __forceinline__ uint32_t smem_u32(const void* p) {
    uint32_t a;
    asm("{ .reg .u64 t; cvta.to.shared.u64 t, %1; cvt.u32.u64 %0, t; }"
        : "=r"(a) : "l"(p));
    return a;
}
__device__ __forceinline__ uint32_t packbf2(float x, float y) {
    __nv_bfloat16 bx = __float2bfloat16_rn(x);
    __nv_bfloat16 by = __float2bfloat16_rn(y);
    return ((uint32_t)__bfloat16_as_ushort(by) << 16) | __bfloat16_as_ushort(bx);
}

// ---------------- scratch ----------------------------------------------------
__device__ float g_V   [BATCH*CH*HW];
__device__ float g_conv[BATCH*CH*HW];
__device__ float g_q   [NWIN*HEADS*HD*NPOS];   // [win][head][d][n]
__device__ float g_k   [NWIN*HEADS*HD*NPOS];   // [win][head][d][m]
__device__ float g_v   [NWIN*HEADS*HD*NPOS];   // [win][head][d][m]
__device__ float g_att [BATCH*HW*CH];
__device__ float g_bias[HEADS*NPOS*NPOS];      // [head][n][m]
__device__ __align__(16) __nv_bfloat16 g_Whi[288*WPAD];
__device__ __align__(16) __nv_bfloat16 g_Wlo[288*WPAD];

// ---------------- kernel P: split W into bf16 hi/lo padded blobs ------------
__device__ __forceinline__ float wval(const float* Wqk, const float* Wv,
                                      int o, int k) {
    if (k >= 96) return 0.f;
    if (o < 96)       return Wqk[o*96 + k] * QSCALE;
    else if (o < 192) return Wqk[o*96 + k];
    else              return Wv[(o - 192)*96 + k];
}
__global__ void prep_kernel(const float* __restrict__ Wqk,
                            const float* __restrict__ Wv)
{
    int idx = blockIdx.x * 256 + threadIdx.x;
    if (idx >= 288*WPAD) return;
    float w = wval(Wqk, Wv, idx / WPAD, idx % WPAD);
    __nv_bfloat16 hi = __float2bfloat16_rn(w);
    g_Whi[idx] = hi;
    g_Wlo[idx] = __float2bfloat16_rn(w - __bfloat162float(hi));
}

// ---------------- kernel B: bias MLP table ----------------------------------
__global__ void bias_kernel(const float* __restrict__ Wm1, const float* __restrict__ bm1,
                            const float* __restrict__ Wm2, const float* __restrict__ bm2)
{
    int gid = blockIdx.x * 256 + threadIdx.x;
    int n = gid >> 6, m = gid & 63;
    float r0 = (float)((n >> 3) - (m >> 3));
    float r1 = (float)((n & 7)  - (m & 7));
    r0 = copysignf(log1pf(fabsf(r0)), r0);
    r1 = copysignf(log1pf(fabsf(r1)), r1);
    float a0 = bm2[0], a1 = bm2[1], a2 = bm2[2];
    for (int j = 0; j < 256; j++) {
        float h = fmaf(r0, Wm1[j], fmaf(r1, Wm1[256 + j], bm1[j]));
        h = fmaxf(h, 0.f);
        a0 = fmaf(h, Wm2[j*3 + 0], a0);
        a1 = fmaf(h, Wm2[j*3 + 1], a1);
        a2 = fmaf(h, Wm2[j*3 + 2], a2);
    }
    g_bias[0*4096 + gid] = a0;
    g_bias[1*4096 + gid] = a1;
    g_bias[2*4096 + gid] = a2;
}

// ---------------- kernel A: persistent QKV GEMM (unchanged from R10) --------
__global__ __launch_bounds__(512, 1) void qkv_mma_kernel(
    const float* __restrict__ x,
    const float* __restrict__ bqk, const float* __restrict__ bv)
{
    extern __shared__ __align__(16) unsigned char dsm[];
    __nv_bfloat16* whi_s = (__nv_bfloat16*)dsm;
    __nv_bfloat16* wlo_s = whi_s + 288*WPAD;
    __nv_bfloat16* xhi_s = wlo_s + 288*WPAD;
    __nv_bfloat16* xlo_s = xhi_s + 96*PXPAD;
    float* out_s = (float*)xhi_s;

    int tid  = threadIdx.x;
    int warp = tid >> 5, lane = tid & 31;

    {
        const uint4* s1 = (const uint4*)g_Whi; uint4* d1 = (uint4*)whi_s;
        const uint4* s2 = (const uint4*)g_Wlo; uint4* d2 = (uint4*)wlo_s;
        #pragma unroll 4
        for (int i = tid; i < 288*WPAD*2/16; i += 512) { d1[i] = s1[i]; d2[i] = s2[i]; }
    }

    int idx8 = lane & 7, quad = lane >> 3;
    int krow = (quad >> 1)*8 + idx8;
    int apxb = warp*16 + (quad & 1)*8;
    int brow4 = lane & 7;
    int bcol4 = ((lane >> 3) & 1)*8;
    int brsel = (lane >> 4) & 1;
    int pq   = tid & 63;
    int p0   = pq*4;
    int c0   = tid >> 6;
    int orow = warp*16 + (lane >> 2);
    int oc   = (lane & 3)*2;

    for (int tile = blockIdx.x; tile < 1024; tile += gridDim.x) {
        int b   = tile >> 8;
        int hw0 = (tile & 255) << 8;

        __syncthreads();
        for (int idx = tid; idx < 96*64; idx += 512) {
            int k = idx >> 6, pg = idx & 63;
            float4 v = *(const float4*)&x[(b*96 + k)*HW + hw0 + pg*4];
            __nv_bfloat16 h0 = __float2bfloat16_rn(v.x);
            __nv_bfloat16 h1 = __float2bfloat16_rn(v.y);
            __nv_bfloat16 h2 = __float2bfloat16_rn(v.z);
            __nv_bfloat16 h3 = __float2bfloat16_rn(v.w);
            uint32_t hp0 = (uint32_t)__bfloat16_as_ushort(h1) << 16 | __bfloat16_as_ushort(h0);
            uint32_t hp1 = (uint32_t)__bfloat16_as_ushort(h3) << 16 | __bfloat16_as_ushort(h2);
            __nv_bfloat16 l0 = __float2bfloat16_rn(v.x - __bfloat162float(h0));
            __nv_bfloat16 l1 = __float2bfloat16_rn(v.y - __bfloat162float(h1));
            __nv_bfloat16 l2 = __float2bfloat16_rn(v.z - __bfloat162float(h2));
            __nv_bfloat16 l3 = __float2bfloat16_rn(v.w - __bfloat162float(h3));
            uint32_t lp0 = (uint32_t)__bfloat16_as_ushort(l1) << 16 | __bfloat16_as_ushort(l0);
            uint32_t lp1 = (uint32_t)__bfloat16_as_ushort(l3) << 16 | __bfloat16_as_ushort(l2);
            *(uint2*)&xhi_s[k*PXPAD + pg*4] = make_uint2(hp0, hp1);
            *(uint2*)&xlo_s[k*PXPAD + pg*4] = make_uint2(lp0, lp1);
        }
        __syncthreads();

        uint32_t ahi[6][4], alo[6][4];
        #pragma unroll
        for (int ks = 0; ks < 6; ks++) {
            LDM_X4T(ahi[ks], smem_u32(&xhi_s[(ks*16 + krow)*PXPAD + apxb]));
            LDM_X4T(alo[ks], smem_u32(&xlo_s[(ks*16 + krow)*PXPAD + apxb]));
        }
        __syncthreads();

        int hwp = hw0 + p0;
        int h_  = hwp >> 8, w_ = hwp & 255;
        int hp  = (h_ + 252) & 255;
        int wp  = (w_ + 252) & 255;
        int wh  = hp >> 3, ww = wp >> 3;
        int win = b*1024 + wh*32 + ww;
        int n   = (hp & 7)*8 + (wp & 7);
        int whn = win*3;

        #pragma unroll 1
        for (int g = 0; g < 3; g++) {
            float acc[12][4];
            #pragma unroll
            for (int nt = 0; nt < 12; nt++)
                #pragma unroll
                for (int j = 0; j < 4; j++) acc[nt][j] = 0.f;

            int n_base = g*96;
            #pragma unroll 1
            for (int ks = 0; ks < 6; ks++) {
                #pragma unroll
                for (int ntp = 0; ntp < 6; ntp++) {
                    int wrow = (n_base + (2*ntp + brsel)*8 + brow4)*WPAD + ks*16 + bcol4;
                    uint32_t bh[4], bl[4];
                    LDM_X4(bh, smem_u32(&whi_s[wrow]));
                    MMA_BF16(acc[2*ntp    ], ahi[ks], bh);
                    MMA_BF16(acc[2*ntp    ], alo[ks], bh);
                    MMA_BF16(acc[2*ntp + 1], ahi[ks], bh + 2);
                    MMA_BF16(acc[2*ntp + 1], alo[ks], bh + 2);
                    LDM_X4(bl, smem_u32(&wlo_s[wrow]));
                    MMA_BF16(acc[2*ntp    ], ahi[ks], bl);
                    MMA_BF16(acc[2*ntp + 1], ahi[ks], bl + 2);
                }
            }

            #pragma unroll
            for (int nt = 0; nt < 12; nt++) {
                out_s[(nt*8 + oc    )*264 + orow    ] = acc[nt][0];
                out_s[(nt*8 + oc + 1)*264 + orow    ] = acc[nt][1];
                out_s[(nt*8 + oc    )*264 + orow + 8] = acc[nt][2];
                out_s[(nt*8 + oc + 1)*264 + orow + 8] = acc[nt][3];
            }
            __syncthreads();

            #pragma unroll 1
            for (int j = 0; j < 12; j++) {
                int c = c0 + j*8;
                int head = c >> 5, d = c & 31;
                float4 v4 = *(const float4*)&out_s[c*264 + p0];
                int gi = ((whn + head)*32 + d)*64 + n;
                if (g == 0) {
                    float bia = bqk[c] * QSCALE;
                    *(float4*)&g_q[gi] = make_float4(v4.x+bia, v4.y+bia, v4.z+bia, v4.w+bia);
                } else if (g == 1) {
                    float bia = bqk[96 + c];
                    *(float4*)&g_k[gi] = make_float4(v4.x+bia, v4.y+bia, v4.z+bia, v4.w+bia);
                } else {
                    float bia = bv[c];
                    float4 vo = make_float4(v4.x+bia, v4.y+bia, v4.z+bia, v4.w+bia);
                    *(float4*)&g_v[gi] = vo;
                    *(float4*)&g_V[(b*96 + c)*HW + hwp] = vo;
                }
            }
            __syncthreads();
        }
    }
}

// ---------------- kernel C: attention, full HMMA + register softmax ---------
__device__ __forceinline__ int swin_label(int wh, int ww, int idx) {
    int rh = (wh == 31) ? (1 + (((idx >> 3) >= 4) ? 1 : 0)) : 0;
    int rw = (ww == 31) ? (1 + (((idx & 7)  >= 4) ? 1 : 0)) : 0;
    return rh*3 + rw;
}

#define APAD 72   // bf16 row stride for staged tiles

__global__ __launch_bounds__(128) void attn_kernel()
{
    __shared__ __align__(16) __nv_bfloat16 qhi[32*APAD], qlo[32*APAD];
    __shared__ __align__(16) __nv_bfloat16 khi[32*APAD], klo[32*APAD];
    __shared__ __align__(16) __nv_bfloat16 vhi[32*APAD], vlo[32*APAD];

    int win  = blockIdx.x;
    int head = blockIdx.y;
    int tid  = threadIdx.x;
    int warp = tid >> 5, lane = tid & 31;
    size_t base = (size_t)(win*3 + head) * 2048;

    // stage q/k/v [d][m] fp32 -> bf16 hi/lo [d][APAD]
    const float4* qg = (const float4*)(g_q + base);
    const float4* kg = (const float4*)(g_k + base);
    const float4* vg = (const float4*)(g_v + base);
    for (int i = tid; i < 512; i += 128) {
        int d = i >> 4, m4 = (i & 15)*4;
        float4 q4 = qg[i], k4 = kg[i], v4 = vg[i];
        #pragma unroll
        for (int t = 0; t < 3; t++) {
            float4 s4 = (t == 0) ? q4 : (t == 1) ? k4 : v4;
            __nv_bfloat16 h0 = __float2bfloat16_rn(s4.x);
            __nv_bfloat16 h1 = __float2bfloat16_rn(s4.y);
            __nv_bfloat16 h2 = __float2bfloat16_rn(s4.z);
            __nv_bfloat16 h3 = __float2bfloat16_rn(s4.w);
            uint32_t hp0 = (uint32_t)__bfloat16_as_ushort(h1) << 16 | __bfloat16_as_ushort(h0);
            uint32_t hp1 = (uint32_t)__bfloat16_as_ushort(h3) << 16 | __bfloat16_as_ushort(h2);
            uint32_t lp0 = packbf2(s4.x - __bfloat162float(h0), s4.y - __bfloat162float(h1));
            uint32_t lp1 = packbf2(s4.z - __bfloat162float(h2), s4.w - __bfloat162float(h3));
            __nv_bfloat16* dsth = (t == 0) ? qhi : (t == 1) ? khi : vhi;
            __nv_bfloat16* dstl = (t == 0) ? qlo : (t == 1) ? klo : vlo;
            *(uint2*)&dsth[d*APAD + m4] = make_uint2(hp0, hp1);
            *(uint2*)&dstl[d*APAD + m4] = make_uint2(lp0, lp1);
        }
    }
    __syncthreads();

    int idx8 = lane & 7, quad = lane >> 3;
    int n0 = warp*16;

    // A fragments (q): trans ldmatrix, proven qkv pattern
    uint32_t ahi[2][4], alo[2][4];
    {
        int krow = (quad >> 1)*8 + idx8;
        int apx  = n0 + (quad & 1)*8;
        #pragma unroll
        for (int ks = 0; ks < 2; ks++) {
            LDM_X4T(ahi[ks], smem_u32(&qhi[(ks*16 + krow)*APAD + apx]));
            LDM_X4T(alo[ks], smem_u32(&qlo[(ks*16 + krow)*APAD + apx]));
        }
    }

    // QK^T: acc tiles j=0..7 (m blocks of 8)
    float acc[8][4];
    #pragma unroll
    for (int j = 0; j < 8; j++)
        #pragma unroll
        for (int r = 0; r < 4; r++) acc[j][r] = 0.f;

    {
        // B (k) trans addressing: row = ks*16 + (quad&1)*8 + idx8, col = (2jp + quad>>1)*8
        int brow = (quad & 1)*8 + idx8;
        int bcol = (quad >> 1)*8;
        #pragma unroll
        for (int ks = 0; ks < 2; ks++) {
            #pragma unroll
            for (int jp = 0; jp < 4; jp++) {
                uint32_t addr_off = (ks*16 + brow)*APAD + jp*16 + bcol;
                uint32_t bh[4], bl[4];
                LDM_X4T(bh, smem_u32(&khi[addr_off]));
                MMA_BF16(acc[2*jp    ], ahi[ks], bh);
                MMA_BF16(acc[2*jp    ], alo[ks], bh);
                MMA_BF16(acc[2*jp + 1], ahi[ks], bh + 2);
                MMA_BF16(acc[2*jp + 1], alo[ks], bh + 2);
                LDM_X4T(bl, smem_u32(&klo[addr_off]));
                MMA_BF16(acc[2*jp    ], ahi[ks], bl);
                MMA_BF16(acc[2*jp + 1], ahi[ks], bl + 2);
            }
        }
    }

    // softmax in registers
    int wloc = win & 1023;
    int wh = wloc >> 5, ww = wloc & 31;
    bool masked = (wh == 31) || (ww == 31);
    int n1 = n0 + (lane >> 2);
    int n2 = n1 + 8;
    int mq = (lane & 3)*2;
    int labn1 = 0, labn2 = 0;
    if (masked) { labn1 = swin_label(wh, ww, n1); labn2 = swin_label(wh, ww, n2); }

    const float* bb = g_bias + head*4096;
    float lsum1 = 0.f, lsum2 = 0.f;
    uint32_t pahi[4][4], palo[4][4];

    #pragma unroll
    for (int j = 0; j < 8; j++) {
        int m0 = j*8 + mq;
        float2 b1 = *(const float2*)&bb[n1*64 + m0];
        float2 b2 = *(const float2*)&bb[n2*64 + m0];
        float p0 = __expf(acc[j][0] + b1.x);
        float p1 = __expf(acc[j][1] + b1.y);
        float p2 = __expf(acc[j][2] + b2.x);
        float p3 = __expf(acc[j][3] + b2.y);
        if (masked) {
            int lm0 = swin_label(wh, ww, m0);
            int lm1 = swin_label(wh, ww, m0 + 1);
            if (lm0 != labn1) p0 = 0.f;
            if (lm1 != labn1) p1 = 0.f;
            if (lm0 != labn2) p2 = 0.f;
            if (lm1 != labn2) p3 = 0.f;
        }
        lsum1 += p0 + p1;
        lsum2 += p2 + p3;
        // convert to PV A-fragments (C layout == A layout)
        int s = j >> 1, half = (j & 1)*2;
        __nv_bfloat16 h0 = __float2bfloat16_rn(p0);
        __nv_bfloat16 h1 = __float2bfloat16_rn(p1);
        __nv_bfloat16 h2 = __float2bfloat16_rn(p2);
        __nv_bfloat16 h3 = __float2bfloat16_rn(p3);
        pahi[s][half]     = ((uint32_t)__bfloat16_as_ushort(h1) << 16) | __bfloat16_as_ushort(h0);
        pahi[s][half + 1] = ((uint32_t)__bfloat16_as_ushort(h3) << 16) | __bfloat16_as_ushort(h2);
        palo[s][half]     = packbf2(p0 - __bfloat162float(h0), p1 - __bfloat162float(h1));
        palo[s][half + 1] = packbf2(p2 - __bfloat162float(h2), p3 - __bfloat162float(h3));
    }
    lsum1 += __shfl_xor_sync(0xFFFFFFFF, lsum1, 1);
    lsum1 += __shfl_xor_sync(0xFFFFFFFF, lsum1, 2);
    lsum2 += __shfl_xor_sync(0xFFFFFFFF, lsum2, 1);
    lsum2 += __shfl_xor_sync(0xFFFFFFFF, lsum2, 2);
    float inv1 = 1.f / lsum1, inv2 = 1.f / lsum2;

    // PV: out tiles t=0..3 (d blocks of 8); B (v) non-trans from [d][m]
    float o[4][4];
    #pragma unroll
    for (int t = 0; t < 4; t++)
        #pragma unroll
        for (int r = 0; r < 4; r++) o[t][r] = 0.f;

    {
        // non-trans x4: row = (2tp + quad>>1)*8 + idx8, col = s*16 + (quad&1)*8
        int vrow = (quad >> 1)*8 + idx8;
        int vcol = (quad & 1)*8;
        #pragma unroll
        for (int s = 0; s < 4; s++) {
            #pragma unroll
            for (int tp = 0; tp < 2; tp++) {
                uint32_t addr_off = (tp*16 + vrow)*APAD + s*16 + vcol;
                uint32_t bh[4], bl[4];
                LDM_X4(bh, smem_u32(&vhi[addr_off]));
                MMA_BF16(o[2*tp    ], pahi[s], bh);
                MMA_BF16(o[2*tp    ], palo[s], bh);
                MMA_BF16(o[2*tp + 1], pahi[s], bh + 2);
                MMA_BF16(o[2*tp + 1], palo[s], bh + 2);
                LDM_X4(bl, smem_u32(&vlo[addr_off]));
                MMA_BF16(o[2*tp    ], pahi[s], bl);
                MMA_BF16(o[2*tp + 1], pahi[s], bl + 2);
            }
        }
    }

    // epilogue: scale, un-window, roll back, write channels-last float2
    int b = win >> 10;
    int r1 = n1 >> 3, c1 = n1 & 7;
    int r2 = n2 >> 3, c2 = n2 & 7;
    int h1 = ((wh << 3) + r1 + 4) & 255;
    int w1 = ((ww << 3) + c1 + 4) & 255;
    int h2 = ((wh << 3) + r2 + 4) & 255;
    int w2 = ((ww << 3) + c2 + 4) & 255;
    float* ap1 = g_att + ((size_t)(b*256 + h1)*256 + w1)*96 + head*32 + mq;
    float* ap2 = g_att + ((size_t)(b*256 + h2)*256 + w2)*96 + head*32 + mq;
    #pragma unroll
    for (int t = 0; t < 4; t++) {
        *(float2*)&ap1[t*8] = make_float2(o[t][0]*inv1, o[t][1]*inv1);
        *(float2*)&ap2[t*8] = make_float2(o[t][2]*inv2, o[t][3]*inv2);
    }
}

// ---------------- kernel DW: depthwise 5x5, vectorized halo -----------------
__global__ __launch_bounds__(256) void dw_kernel(const float* __restrict__ Wdw,
                                                 const float* __restrict__ bdw)
{
    __shared__ __align__(16) float s[36][44];
    __shared__ float wk[25];

    int blk  = blockIdx.x;
    int img  = blk >> 6;
    int tile = blk & 63;
    int c    = img % 96;
    int h0   = (tile >> 3) << 5, w0 = (tile & 7) << 5;
    int tid  = threadIdx.x;

    if (tid < 25) wk[tid] = Wdw[c*25 + tid];
    const float* vimg = g_V + (size_t)img * HW;

    bool border = (h0 == 0) || (h0 == 224) || (w0 == 0) || (w0 == 224);
    if (!border) {
        const float* src = vimg + (h0 - 2)*256 + (w0 - 4);
        for (int idx = tid; idx < 36*11; idx += 256) {
            int r = idx / 11, c4 = idx - r*11;
            *(float4*)&s[r][c4*4] = *(const float4*)&src[r*256 + c4*4];
        }
    } else {
        for (int idx = tid; idx < 36*44; idx += 256) {
            int r  = idx / 44, cc = idx % 44;
            int hh = h0 - 2 + r;  hh = (hh < 0) ? -hh : ((hh > 255) ? 510 - hh : hh);
            int wq = w0 - 4 + cc; wq = (wq < 0) ? -wq : ((wq > 255) ? 510 - wq : wq);
            s[r][cc] = vimg[hh*256 + wq];
        }
    }
    __syncthreads();

    int y   = tid >> 3;
    int xq0 = (tid & 7) * 4;
    float b0 = bdw[c];
    float acc[4] = {b0, b0, b0, b0};
    #pragma unroll
    for (int i = 0; i < 5; i++) {
        float4 fa = *(const float4*)&s[y + i][xq0];
        float4 fb = *(const float4*)&s[y + i][xq0 + 4];
        float4 fc = *(const float4*)&s[y + i][xq0 + 8];
        float f[12] = {fa.x, fa.y, fa.z, fa.w, fb.x, fb.y, fb.z, fb.w,
                       fc.x, fc.y, fc.z, fc.w};
        #pragma unroll
        for (int j = 0; j < 5; j++) {
            float wv = wk[i*5 + j];
            acc[0] = fmaf(f[j + 2], wv, acc[0]);
            acc[1] = fmaf(f[j + 3], wv, acc[1]);
            acc[2] = fmaf(f[j + 4], wv, acc[2]);
            acc[3] = fmaf(f[j + 5], wv, acc[3]);
        }
    }
    *(float4*)&g_conv[(size_t)img*HW + (h0 + y)*256 + (w0 + xq0)] =
        make_float4(acc[0], acc[1], acc[2], acc[3]);
}

// ---------------- kernel D: add (conv + attn), final 96x96 GEMM -------------
__global__ __launch_bounds__(256) void final_kernel(
    const float* __restrict__ Wp, const float* __restrict__ bp,
    float* __restrict__ outp)
{
    __shared__ float t_s[64][97];
    __shared__ float w_s[32][97];

    int t   = blockIdx.x;
    int b   = t >> 10;
    int hw0 = (t & 1023) << 6;
    int h   = hw0 >> 8;
    int tid = threadIdx.x;

    for (int idx = tid; idx < 96*16; idx += 256) {
        int c = idx >> 4, pq = idx & 15;
        float4 v4 = *(const float4*)&g_conv[((size_t)b*96 + c)*HW + hw0 + pq*4];
        t_s[pq*4 + 0][c] = v4.x;
        t_s[pq*4 + 1][c] = v4.y;
        t_s[pq*4 + 2][c] = v4.z;
        t_s[pq*4 + 3][c] = v4.w;
    }
    __syncthreads();

    const float* ab = g_att + ((size_t)(b*256 + h)*256 + (hw0 & 255))*96;
    for (int idx = tid; idx < 64*24; idx += 256) {
        int f4 = idx % 24, p = idx / 24;
        float4 a4 = *(const float4*)&ab[p*96 + f4*4];
        int c = f4*4;
        t_s[p][c]     += a4.x;
        t_s[p][c + 1] += a4.y;
        t_s[p][c + 2] += a4.z;
        t_s[p][c + 3] += a4.w;
    }
    __syncthreads();

    int pxg = tid & 15, chg = tid >> 4;
    int p0 = pxg*4, ob = chg*6;
    float acc[6][4];
    #pragma unroll
    for (int i = 0; i < 6; i++)
        #pragma unroll
        for (int j = 0; j < 4; j++) acc[i][j] = 0.f;

    for (int kc = 0; kc < 3; kc++) {
        if (kc) __syncthreads();
        for (int idx = tid; idx < 32*96; idx += 256) {
            int kk = idx & 31, o = idx >> 5;
            w_s[kk][o] = Wp[o*96 + kc*32 + kk];
        }
        __syncthreads();
        #pragma unroll 4
        for (int kk = 0; kk < 32; kk++) {
            int k = kc*32 + kk;
            float tv0 = t_s[p0][k],   tv1 = t_s[p0+1][k];
            float tv2 = t_s[p0+2][k], tv3 = t_s[p0+3][k];
            #pragma unroll
            for (int i = 0; i < 6; i++) {
                float wv = w_s[kk][ob + i];
                acc[i][0] = fmaf(wv, tv0, acc[i][0]);
                acc[i][1] = fmaf(wv, tv1, acc[i][1]);
                acc[i][2] = fmaf(wv, tv2, acc[i][2]);
                acc[i][3] = fmaf(wv, tv3, acc[i][3]);
            }
        }
    }

    #pragma unroll
    for (int i = 0; i < 6; i++) {
        int o = ob + i;
        float bo = bp[o];
        *(float4*)&outp[((size_t)b*96 + o)*HW + hw0 + p0] =
            make_float4(acc[i][0] + bo, acc[i][1] + bo,
                        acc[i][2] + bo, acc[i][3] + bo);
    }
}

// ---------------- launch ------------------------------------------------------
extern "C" void kernel_launch(void* const* d_in, const int* in_sizes, int n_in,
                              void* d_out, int out_size)
{
    const float* x   = (const float*)d_in[0];
    const float* Wv  = (const float*)d_in[1];
    const float* bv  = (const float*)d_in[2];
    const float* Wqk = (const float*)d_in[3];
    const float* bqk = (const float*)d_in[4];
    const float* Wm1 = (const float*)d_in[5];
    const float* bm1 = (const float*)d_in[6];
    const float* Wm2 = (const float*)d_in[7];
    const float* bm2 = (const float*)d_in[8];
    const float* Wdw = (const float*)d_in[9];
    const float* bdw = (const float*)d_in[10];
    const float* Wp  = (const float*)d_in[11];
    const float* bp  = (const float*)d_in[12];
    float* outp = (float*)d_out;

    const int QKV_SMEM = 288*WPAD*2*2 + 96*PXPAD*2*2;
    cudaFuncSetAttribute(qkv_mma_kernel,
                         cudaFuncAttributeMaxDynamicSharedMemorySize, QKV_SMEM);

    // NOTE: attn_kernel is now the 4th launch (profiled slot)
    prep_kernel   <<<(288*WPAD + 255)/256, 256>>>(Wqk, Wv);
    bias_kernel   <<<16, 256>>>(Wm1, bm1, Wm2, bm2);
    qkv_mma_kernel<<<148, 512, QKV_SMEM>>>(x, bqk, bv);
    attn_kernel   <<<dim3(4096, 3), 128>>>();
    dw_kernel     <<<24576, 256>>>(Wdw, bdw);
    final_kernel  <<<4096, 256>>>(Wp, bp, outp);
}

// round 12
// speedup vs baseline: 1.9701x; 1.0829x over previous
#include <cuda_runtime.h>
#include <cuda_bf16.h>
#include <math.h>
#include <cstdint>

#define BATCH 4
#define CH    96
#define HRES  256
#define WRES  256
#define HW    65536
#define HEADS 3
#define HD    32
#define NPOS  64
#define NWIN  4096
#define QSCALE 0.17677669529663687f
#define WPAD  104
#define PXPAD 264

// ---------------- mma.sync / ldmatrix helpers (sm_80+ PTX) ------------------
#define LDM_X4(r, addr) \
    asm volatile("ldmatrix.sync.aligned.m8n8.x4.shared.b16 {%0,%1,%2,%3}, [%4];" \
        : "=r"((r)[0]), "=r"((r)[1]), "=r"((r)[2]), "=r"((r)[3]) : "r"(addr))
#define LDM_X4T(r, addr) \
    asm volatile("ldmatrix.sync.aligned.m8n8.x4.trans.shared.b16 {%0,%1,%2,%3}, [%4];" \
        : "=r"((r)[0]), "=r"((r)[1]), "=r"((r)[2]), "=r"((r)[3]) : "r"(addr))
#define MMA_BF16(d, a, b) \
    asm volatile("mma.sync.aligned.m16n8k16.row.col.f32.bf16.bf16.f32 " \
        "{%0,%1,%2,%3}, {%4,%5,%6,%7}, {%8,%9}, {%0,%1,%2,%3};" \
        : "+f"((d)[0]), "+f"((d)[1]), "+f"((d)[2]), "+f"((d)[3]) \
        : "r"((a)[0]), "r"((a)[1]), "r"((a)[2]), "r"((a)[3]), \
          "r"((b)[0]), "r"((b)[1]))

__device__ __forceinline__ uint32_t smem_u32(const void* p) {
    uint32_t a;
    asm("{ .reg .u64 t; cvta.to.shared.u64 t, %1; cvt.u32.u64 %0, t; }"
        : "=r"(a) : "l"(p));
    return a;
}
__device__ __forceinline__ uint32_t packbf2(float x, float y) {
    __nv_bfloat16 bx = __float2bfloat16_rn(x);
    __nv_bfloat16 by = __float2bfloat16_rn(y);
    return ((uint32_t)__bfloat16_as_ushort(by) << 16) | __bfloat16_as_ushort(bx);
}

// ---------------- scratch ----------------------------------------------------
__device__ float g_V   [BATCH*CH*HW];
__device__ float g_conv[BATCH*CH*HW];
__device__ float g_q   [NWIN*HEADS*HD*NPOS];   // [win][head][d][n]
__device__ float g_k   [NWIN*HEADS*HD*NPOS];   // [win][head][d][m]
__device__ float g_v   [NWIN*HEADS*HD*NPOS];   // [win][head][d][m]
__device__ float g_att [BATCH*CH*HW];          // CHANNELS-FIRST (NCHW)
__device__ float g_bias[HEADS*NPOS*NPOS];      // [head][n][m]
__device__ __align__(16) __nv_bfloat16 g_Whi[288*WPAD];
__device__ __align__(16) __nv_bfloat16 g_Wlo[288*WPAD];
__device__ __align__(16) __nv_bfloat16 g_Phi[96*WPAD];
__device__ __align__(16) __nv_bfloat16 g_Plo[96*WPAD];

// ---------------- kernel P: split W into bf16 hi/lo padded blobs ------------
__device__ __forceinline__ float wval(const float* Wqk, const float* Wv,
                                      int o, int k) {
    if (k >= 96) return 0.f;
    if (o < 96)       return Wqk[o*96 + k] * QSCALE;
    else if (o < 192) return Wqk[o*96 + k];
    else              return Wv[(o - 192)*96 + k];
}
__global__ void prep_kernel(const float* __restrict__ Wqk,
                            const float* __restrict__ Wv)
{
    int idx = blockIdx.x * 256 + threadIdx.x;
    if (idx >= 288*WPAD) return;
    float w = wval(Wqk, Wv, idx / WPAD, idx % WPAD);
    __nv_bfloat16 hi = __float2bfloat16_rn(w);
    g_Whi[idx] = hi;
    g_Wlo[idx] = __float2bfloat16_rn(w - __bfloat162float(hi));
}
__global__ void prep2_kernel(const float* __restrict__ Wp)
{
    int idx = blockIdx.x * 256 + threadIdx.x;
    if (idx >= 96*WPAD) return;
    int o = idx / WPAD, k = idx % WPAD;
    float w = (k < 96) ? Wp[o*96 + k] : 0.f;
    __nv_bfloat16 hi = __float2bfloat16_rn(w);
    g_Phi[idx] = hi;
    g_Plo[idx] = __float2bfloat16_rn(w - __bfloat162float(hi));
}

// ---------------- kernel B: bias MLP table ----------------------------------
__global__ void bias_kernel(const float* __restrict__ Wm1, const float* __restrict__ bm1,
                            const float* __restrict__ Wm2, const float* __restrict__ bm2)
{
    int gid = blockIdx.x * 256 + threadIdx.x;
    int n = gid >> 6, m = gid & 63;
    float r0 = (float)((n >> 3) - (m >> 3));
    float r1 = (float)((n & 7)  - (m & 7));
    r0 = copysignf(log1pf(fabsf(r0)), r0);
    r1 = copysignf(log1pf(fabsf(r1)), r1);
    float a0 = bm2[0], a1 = bm2[1], a2 = bm2[2];
    for (int j = 0; j < 256; j++) {
        float h = fmaf(r0, Wm1[j], fmaf(r1, Wm1[256 + j], bm1[j]));
        h = fmaxf(h, 0.f);
        a0 = fmaf(h, Wm2[j*3 + 0], a0);
        a1 = fmaf(h, Wm2[j*3 + 1], a1);
        a2 = fmaf(h, Wm2[j*3 + 2], a2);
    }
    g_bias[0*4096 + gid] = a0;
    g_bias[1*4096 + gid] = a1;
    g_bias[2*4096 + gid] = a2;
}

// ---------------- kernel A: persistent QKV GEMM (unchanged) -----------------
__global__ __launch_bounds__(512, 1) void qkv_mma_kernel(
    const float* __restrict__ x,
    const float* __restrict__ bqk, const float* __restrict__ bv)
{
    extern __shared__ __align__(16) unsigned char dsm[];
    __nv_bfloat16* whi_s = (__nv_bfloat16*)dsm;
    __nv_bfloat16* wlo_s = whi_s + 288*WPAD;
    __nv_bfloat16* xhi_s = wlo_s + 288*WPAD;
    __nv_bfloat16* xlo_s = xhi_s + 96*PXPAD;
    float* out_s = (float*)xhi_s;

    int tid  = threadIdx.x;
    int warp = tid >> 5, lane = tid & 31;

    {
        const uint4* s1 = (const uint4*)g_Whi; uint4* d1 = (uint4*)whi_s;
        const uint4* s2 = (const uint4*)g_Wlo; uint4* d2 = (uint4*)wlo_s;
        #pragma unroll 4
        for (int i = tid; i < 288*WPAD*2/16; i += 512) { d1[i] = s1[i]; d2[i] = s2[i]; }
    }

    int idx8 = lane & 7, quad = lane >> 3;
    int krow = (quad >> 1)*8 + idx8;
    int apxb = warp*16 + (quad & 1)*8;
    int brow4 = lane & 7;
    int bcol4 = ((lane >> 3) & 1)*8;
    int brsel = (lane >> 4) & 1;
    int pq   = tid & 63;
    int p0   = pq*4;
    int c0   = tid >> 6;
    int orow = warp*16 + (lane >> 2);
    int oc   = (lane & 3)*2;

    for (int tile = blockIdx.x; tile < 1024; tile += gridDim.x) {
        int b   = tile >> 8;
        int hw0 = (tile & 255) << 8;

        __syncthreads();
        for (int idx = tid; idx < 96*64; idx += 512) {
            int k = idx >> 6, pg = idx & 63;
            float4 v = *(const float4*)&x[(b*96 + k)*HW + hw0 + pg*4];
            __nv_bfloat16 h0 = __float2bfloat16_rn(v.x);
            __nv_bfloat16 h1 = __float2bfloat16_rn(v.y);
            __nv_bfloat16 h2 = __float2bfloat16_rn(v.z);
            __nv_bfloat16 h3 = __float2bfloat16_rn(v.w);
            uint32_t hp0 = (uint32_t)__bfloat16_as_ushort(h1) << 16 | __bfloat16_as_ushort(h0);
            uint32_t hp1 = (uint32_t)__bfloat16_as_ushort(h3) << 16 | __bfloat16_as_ushort(h2);
            uint32_t lp0 = packbf2(v.x - __bfloat162float(h0), v.y - __bfloat162float(h1));
            uint32_t lp1 = packbf2(v.z - __bfloat162float(h2), v.w - __bfloat162float(h3));
            *(uint2*)&xhi_s[k*PXPAD + pg*4] = make_uint2(hp0, hp1);
            *(uint2*)&xlo_s[k*PXPAD + pg*4] = make_uint2(lp0, lp1);
        }
        __syncthreads();

        uint32_t ahi[6][4], alo[6][4];
        #pragma unroll
        for (int ks = 0; ks < 6; ks++) {
            LDM_X4T(ahi[ks], smem_u32(&xhi_s[(ks*16 + krow)*PXPAD + apxb]));
            LDM_X4T(alo[ks], smem_u32(&xlo_s[(ks*16 + krow)*PXPAD + apxb]));
        }
        __syncthreads();

        int hwp = hw0 + p0;
        int h_  = hwp >> 8, w_ = hwp & 255;
        int hp  = (h_ + 252) & 255;
        int wp  = (w_ + 252) & 255;
        int wh  = hp >> 3, ww = wp >> 3;
        int win = b*1024 + wh*32 + ww;
        int n   = (hp & 7)*8 + (wp & 7);
        int whn = win*3;

        #pragma unroll 1
        for (int g = 0; g < 3; g++) {
            float acc[12][4];
            #pragma unroll
            for (int nt = 0; nt < 12; nt++)
                #pragma unroll
                for (int j = 0; j < 4; j++) acc[nt][j] = 0.f;

            int n_base = g*96;
            #pragma unroll 1
            for (int ks = 0; ks < 6; ks++) {
                #pragma unroll
                for (int ntp = 0; ntp < 6; ntp++) {
                    int wrow = (n_base + (2*ntp + brsel)*8 + brow4)*WPAD + ks*16 + bcol4;
                    uint32_t bh[4], bl[4];
                    LDM_X4(bh, smem_u32(&whi_s[wrow]));
                    MMA_BF16(acc[2*ntp    ], ahi[ks], bh);
                    MMA_BF16(acc[2*ntp    ], alo[ks], bh);
                    MMA_BF16(acc[2*ntp + 1], ahi[ks], bh + 2);
                    MMA_BF16(acc[2*ntp + 1], alo[ks], bh + 2);
                    LDM_X4(bl, smem_u32(&wlo_s[wrow]));
                    MMA_BF16(acc[2*ntp    ], ahi[ks], bl);
                    MMA_BF16(acc[2*ntp + 1], ahi[ks], bl + 2);
                }
            }

            #pragma unroll
            for (int nt = 0; nt < 12; nt++) {
                out_s[(nt*8 + oc    )*264 + orow    ] = acc[nt][0];
                out_s[(nt*8 + oc + 1)*264 + orow    ] = acc[nt][1];
                out_s[(nt*8 + oc    )*264 + orow + 8] = acc[nt][2];
                out_s[(nt*8 + oc + 1)*264 + orow + 8] = acc[nt][3];
            }
            __syncthreads();

            #pragma unroll 1
            for (int j = 0; j < 12; j++) {
                int c = c0 + j*8;
                int head = c >> 5, d = c & 31;
                float4 v4 = *(const float4*)&out_s[c*264 + p0];
                int gi = ((whn + head)*32 + d)*64 + n;
                if (g == 0) {
                    float bia = bqk[c] * QSCALE;
                    *(float4*)&g_q[gi] = make_float4(v4.x+bia, v4.y+bia, v4.z+bia, v4.w+bia);
                } else if (g == 1) {
                    float bia = bqk[96 + c];
                    *(float4*)&g_k[gi] = make_float4(v4.x+bia, v4.y+bia, v4.z+bia, v4.w+bia);
                } else {
                    float bia = bv[c];
                    float4 vo = make_float4(v4.x+bia, v4.y+bia, v4.z+bia, v4.w+bia);
                    *(float4*)&g_v[gi] = vo;
                    *(float4*)&g_V[(b*96 + c)*HW + hwp] = vo;
                }
            }
            __syncthreads();
        }
    }
}

// ---------------- kernel C: attention, HMMA + register softmax --------------
__device__ __forceinline__ int swin_label(int wh, int ww, int idx) {
    int rh = (wh == 31) ? (1 + (((idx >> 3) >= 4) ? 1 : 0)) : 0;
    int rw = (ww == 31) ? (1 + (((idx & 7)  >= 4) ? 1 : 0)) : 0;
    return rh*3 + rw;
}

#define APAD 72

__global__ __launch_bounds__(128) void attn_kernel()
{
    __shared__ __align__(16) __nv_bfloat16 qhi[32*APAD], qlo[32*APAD];
    __shared__ __align__(16) __nv_bfloat16 khi[32*APAD], klo[32*APAD];
    __shared__ __align__(16) __nv_bfloat16 vhi[32*APAD], vlo[32*APAD];

    int win  = blockIdx.x;
    int head = blockIdx.y;
    int tid  = threadIdx.x;
    int warp = tid >> 5, lane = tid & 31;
    size_t base = (size_t)(win*3 + head) * 2048;

    const float4* qg = (const float4*)(g_q + base);
    const float4* kg = (const float4*)(g_k + base);
    const float4* vg = (const float4*)(g_v + base);
    for (int i = tid; i < 512; i += 128) {
        int d = i >> 4, m4 = (i & 15)*4;
        float4 q4 = qg[i], k4 = kg[i], v4 = vg[i];
        #pragma unroll
        for (int t = 0; t < 3; t++) {
            float4 s4 = (t == 0) ? q4 : (t == 1) ? k4 : v4;
            __nv_bfloat16 h0 = __float2bfloat16_rn(s4.x);
            __nv_bfloat16 h1 = __float2bfloat16_rn(s4.y);
            __nv_bfloat16 h2 = __float2bfloat16_rn(s4.z);
            __nv_bfloat16 h3 = __float2bfloat16_rn(s4.w);
            uint32_t hp0 = (uint32_t)__bfloat16_as_ushort(h1) << 16 | __bfloat16_as_ushort(h0);
            uint32_t hp1 = (uint32_t)__bfloat16_as_ushort(h3) << 16 | __bfloat16_as_ushort(h2);
            uint32_t lp0 = packbf2(s4.x - __bfloat162float(h0), s4.y - __bfloat162float(h1));
            uint32_t lp1 = packbf2(s4.z - __bfloat162float(h2), s4.w - __bfloat162float(h3));
            __nv_bfloat16* dsth = (t == 0) ? qhi : (t == 1) ? khi : vhi;
            __nv_bfloat16* dstl = (t == 0) ? qlo : (t == 1) ? klo : vlo;
            *(uint2*)&dsth[d*APAD + m4] = make_uint2(hp0, hp1);
            *(uint2*)&dstl[d*APAD + m4] = make_uint2(lp0, lp1);
        }
    }
    __syncthreads();

    int idx8 = lane & 7, quad = lane >> 3;
    int n0 = warp*16;

    uint32_t ahi[2][4], alo[2][4];
    {
        int krow = (quad >> 1)*8 + idx8;
        int apx  = n0 + (quad & 1)*8;
        #pragma unroll
        for (int ks = 0; ks < 2; ks++) {
            LDM_X4T(ahi[ks], smem_u32(&qhi[(ks*16 + krow)*APAD + apx]));
            LDM_X4T(alo[ks], smem_u32(&qlo[(ks*16 + krow)*APAD + apx]));
        }
    }

    float acc[8][4];
    #pragma unroll
    for (int j = 0; j < 8; j++)
        #pragma unroll
        for (int r = 0; r < 4; r++) acc[j][r] = 0.f;

    {
        int brow = (quad & 1)*8 + idx8;
        int bcol = (quad >> 1)*8;
        #pragma unroll
        for (int ks = 0; ks < 2; ks++) {
            #pragma unroll
            for (int jp = 0; jp < 4; jp++) {
                uint32_t addr_off = (ks*16 + brow)*APAD + jp*16 + bcol;
                uint32_t bh[4], bl[4];
                LDM_X4T(bh, smem_u32(&khi[addr_off]));
                MMA_BF16(acc[2*jp    ], ahi[ks], bh);
                MMA_BF16(acc[2*jp    ], alo[ks], bh);
                MMA_BF16(acc[2*jp + 1], ahi[ks], bh + 2);
                MMA_BF16(acc[2*jp + 1], alo[ks], bh + 2);
                LDM_X4T(bl, smem_u32(&klo[addr_off]));
                MMA_BF16(acc[2*jp    ], ahi[ks], bl);
                MMA_BF16(acc[2*jp + 1], ahi[ks], bl + 2);
            }
        }
    }

    int wloc = win & 1023;
    int wh = wloc >> 5, ww = wloc & 31;
    bool masked = (wh == 31) || (ww == 31);
    int n1 = n0 + (lane >> 2);
    int n2 = n1 + 8;
    int mq = (lane & 3)*2;
    int labn1 = 0, labn2 = 0;
    if (masked) { labn1 = swin_label(wh, ww, n1); labn2 = swin_label(wh, ww, n2); }

    const float* bb = g_bias + head*4096;
    float lsum1 = 0.f, lsum2 = 0.f;
    uint32_t pahi[4][4], palo[4][4];

    #pragma unroll
    for (int j = 0; j < 8; j++) {
        int m0 = j*8 + mq;
        float2 b1 = *(const float2*)&bb[n1*64 + m0];
        float2 b2 = *(const float2*)&bb[n2*64 + m0];
        float p0 = __expf(acc[j][0] + b1.x);
        float p1 = __expf(acc[j][1] + b1.y);
        float p2 = __expf(acc[j][2] + b2.x);
        float p3 = __expf(acc[j][3] + b2.y);
        if (masked) {
            int lm0 = swin_label(wh, ww, m0);
            int lm1 = swin_label(wh, ww, m0 + 1);
            if (lm0 != labn1) p0 = 0.f;
            if (lm1 != labn1) p1 = 0.f;
            if (lm0 != labn2) p2 = 0.f;
            if (lm1 != labn2) p3 = 0.f;
        }
        lsum1 += p0 + p1;
        lsum2 += p2 + p3;
        int s = j >> 1, half = (j & 1)*2;
        __nv_bfloat16 h0 = __float2bfloat16_rn(p0);
        __nv_bfloat16 h1 = __float2bfloat16_rn(p1);
        __nv_bfloat16 h2 = __float2bfloat16_rn(p2);
        __nv_bfloat16 h3 = __float2bfloat16_rn(p3);
        pahi[s][half]     = ((uint32_t)__bfloat16_as_ushort(h1) << 16) | __bfloat16_as_ushort(h0);
        pahi[s][half + 1] = ((uint32_t)__bfloat16_as_ushort(h3) << 16) | __bfloat16_as_ushort(h2);
        palo[s][half]     = packbf2(p0 - __bfloat162float(h0), p1 - __bfloat162float(h1));
        palo[s][half + 1] = packbf2(p2 - __bfloat162float(h2), p3 - __bfloat162float(h3));
    }
    lsum1 += __shfl_xor_sync(0xFFFFFFFF, lsum1, 1);
    lsum1 += __shfl_xor_sync(0xFFFFFFFF, lsum1, 2);
    lsum2 += __shfl_xor_sync(0xFFFFFFFF, lsum2, 1);
    lsum2 += __shfl_xor_sync(0xFFFFFFFF, lsum2, 2);
    float inv1 = 1.f / lsum1, inv2 = 1.f / lsum2;

    float o[4][4];
    #pragma unroll
    for (int t = 0; t < 4; t++)
        #pragma unroll
        for (int r = 0; r < 4; r++) o[t][r] = 0.f;

    {
        int vrow = (quad >> 1)*8 + idx8;
        int vcol = (quad & 1)*8;
        #pragma unroll
        for (int s = 0; s < 4; s++) {
            #pragma unroll
            for (int tp = 0; tp < 2; tp++) {
                uint32_t addr_off = (tp*16 + vrow)*APAD + s*16 + vcol;
                uint32_t bh[4], bl[4];
                LDM_X4(bh, smem_u32(&vhi[addr_off]));
                MMA_BF16(o[2*tp    ], pahi[s], bh);
                MMA_BF16(o[2*tp    ], palo[s], bh);
                MMA_BF16(o[2*tp + 1], pahi[s], bh + 2);
                MMA_BF16(o[2*tp + 1], palo[s], bh + 2);
                LDM_X4(bl, smem_u32(&vlo[addr_off]));
                MMA_BF16(o[2*tp    ], pahi[s], bl);
                MMA_BF16(o[2*tp + 1], pahi[s], bl + 2);
            }
        }
    }

    // epilogue: channels-first writes (NCHW) for fused consumption by final
    int b = win >> 10;
    int r1 = n1 >> 3, c1 = n1 & 7;
    int r2 = n2 >> 3, c2 = n2 & 7;
    int off1 = (((wh << 3) + r1 + 4) & 255)*256 + (((ww << 3) + c1 + 4) & 255);
    int off2 = (((wh << 3) + r2 + 4) & 255)*256 + (((ww << 3) + c2 + 4) & 255);
    size_t cb = (size_t)(b*96 + head*32 + mq)*HW;
    #pragma unroll
    for (int t = 0; t < 4; t++) {
        size_t cbase = cb + (size_t)(t*8)*HW;
        g_att[cbase            + off1] = o[t][0]*inv1;
        g_att[cbase + HW       + off1] = o[t][1]*inv1;
        g_att[cbase            + off2] = o[t][2]*inv2;
        g_att[cbase + HW       + off2] = o[t][3]*inv2;
    }
}

// ---------------- kernel DW: depthwise 5x5, vectorized halo -----------------
__global__ __launch_bounds__(256) void dw_kernel(const float* __restrict__ Wdw,
                                                 const float* __restrict__ bdw)
{
    __shared__ __align__(16) float s[36][44];
    __shared__ float wk[25];

    int blk  = blockIdx.x;
    int img  = blk >> 6;
    int tile = blk & 63;
    int c    = img % 96;
    int h0   = (tile >> 3) << 5, w0 = (tile & 7) << 5;
    int tid  = threadIdx.x;

    if (tid < 25) wk[tid] = Wdw[c*25 + tid];
    const float* vimg = g_V + (size_t)img * HW;

    bool border = (h0 == 0) || (h0 == 224) || (w0 == 0) || (w0 == 224);
    if (!border) {
        const float* src = vimg + (h0 - 2)*256 + (w0 - 4);
        for (int idx = tid; idx < 36*11; idx += 256) {
            int r = idx / 11, c4 = idx - r*11;
            *(float4*)&s[r][c4*4] = *(const float4*)&src[r*256 + c4*4];
        }
    } else {
        for (int idx = tid; idx < 36*44; idx += 256) {
            int r  = idx / 44, cc = idx % 44;
            int hh = h0 - 2 + r;  hh = (hh < 0) ? -hh : ((hh > 255) ? 510 - hh : hh);
            int wq = w0 - 4 + cc; wq = (wq < 0) ? -wq : ((wq > 255) ? 510 - wq : wq);
            s[r][cc] = vimg[hh*256 + wq];
        }
    }
    __syncthreads();

    int y   = tid >> 3;
    int xq0 = (tid & 7) * 4;
    float b0 = bdw[c];
    float acc[4] = {b0, b0, b0, b0};
    #pragma unroll
    for (int i = 0; i < 5; i++) {
        float4 fa = *(const float4*)&s[y + i][xq0];
        float4 fb = *(const float4*)&s[y + i][xq0 + 4];
        float4 fc = *(const float4*)&s[y + i][xq0 + 8];
        float f[12] = {fa.x, fa.y, fa.z, fa.w, fb.x, fb.y, fb.z, fb.w,
                       fc.x, fc.y, fc.z, fc.w};
        #pragma unroll
        for (int j = 0; j < 5; j++) {
            float wv = wk[i*5 + j];
            acc[0] = fmaf(f[j + 2], wv, acc[0]);
            acc[1] = fmaf(f[j + 3], wv, acc[1]);
            acc[2] = fmaf(f[j + 4], wv, acc[2]);
            acc[3] = fmaf(f[j + 5], wv, acc[3]);
        }
    }
    *(float4*)&g_conv[(size_t)img*HW + (h0 + y)*256 + (w0 + xq0)] =
        make_float4(acc[0], acc[1], acc[2], acc[3]);
}

// ---------------- kernel D: persistent HMMA final GEMM ----------------------
__global__ __launch_bounds__(512, 1) void final_mma_kernel(
    const float* __restrict__ bp, float* __restrict__ outp)
{
    extern __shared__ __align__(16) unsigned char dsm[];
    __nv_bfloat16* phi_s = (__nv_bfloat16*)dsm;            // [96*WPAD]
    __nv_bfloat16* plo_s = phi_s + 96*WPAD;
    __nv_bfloat16* xhi_s = plo_s + 96*WPAD;                // [96][PXPAD]
    __nv_bfloat16* xlo_s = xhi_s + 96*PXPAD;
    float* out_s = (float*)xhi_s;

    int tid  = threadIdx.x;
    int warp = tid >> 5, lane = tid & 31;

    {
        const uint4* s1 = (const uint4*)g_Phi; uint4* d1 = (uint4*)phi_s;
        const uint4* s2 = (const uint4*)g_Plo; uint4* d2 = (uint4*)plo_s;
        #pragma unroll 4
        for (int i = tid; i < 96*WPAD*2/16; i += 512) { d1[i] = s1[i]; d2[i] = s2[i]; }
    }

    int idx8 = lane & 7, quad = lane >> 3;
    int krow = (quad >> 1)*8 + idx8;
    int apxb = warp*16 + (quad & 1)*8;
    int brow4 = lane & 7;
    int bcol4 = ((lane >> 3) & 1)*8;
    int brsel = (lane >> 4) & 1;
    int pq   = tid & 63;
    int p0   = pq*4;
    int c0   = tid >> 6;
    int orow = warp*16 + (lane >> 2);
    int oc   = (lane & 3)*2;

    for (int tile = blockIdx.x; tile < 1024; tile += gridDim.x) {
        int b   = tile >> 8;
        int hw0 = (tile & 255) << 8;

        __syncthreads();
        // fused load: conv + att (both NCHW), sum, bf16 split
        for (int idx = tid; idx < 96*64; idx += 512) {
            int k = idx >> 6, pg = idx & 63;
            size_t gi = (size_t)(b*96 + k)*HW + hw0 + pg*4;
            float4 a = *(const float4*)&g_conv[gi];
            float4 c4 = *(const float4*)&g_att[gi];
            float4 v = make_float4(a.x + c4.x, a.y + c4.y, a.z + c4.z, a.w + c4.w);
            __nv_bfloat16 h0 = __float2bfloat16_rn(v.x);
            __nv_bfloat16 h1 = __float2bfloat16_rn(v.y);
            __nv_bfloat16 h2 = __float2bfloat16_rn(v.z);
            __nv_bfloat16 h3 = __float2bfloat16_rn(v.w);
            uint32_t hp0 = (uint32_t)__bfloat16_as_ushort(h1) << 16 | __bfloat16_as_ushort(h0);
            uint32_t hp1 = (uint32_t)__bfloat16_as_ushort(h3) << 16 | __bfloat16_as_ushort(h2);
            uint32_t lp0 = packbf2(v.x - __bfloat162float(h0), v.y - __bfloat162float(h1));
            uint32_t lp1 = packbf2(v.z - __bfloat162float(h2), v.w - __bfloat162float(h3));
            *(uint2*)&xhi_s[k*PXPAD + pg*4] = make_uint2(hp0, hp1);
            *(uint2*)&xlo_s[k*PXPAD + pg*4] = make_uint2(lp0, lp1);
        }
        __syncthreads();

        uint32_t ahi[6][4], alo[6][4];
        #pragma unroll
        for (int ks = 0; ks < 6; ks++) {
            LDM_X4T(ahi[ks], smem_u32(&xhi_s[(ks*16 + krow)*PXPAD + apxb]));
            LDM_X4T(alo[ks], smem_u32(&xlo_s[(ks*16 + krow)*PXPAD + apxb]));
        }
        __syncthreads();

        float acc[12][4];
        #pragma unroll
        for (int nt = 0; nt < 12; nt++)
            #pragma unroll
            for (int j = 0; j < 4; j++) acc[nt][j] = 0.f;

        #pragma unroll 1
        for (int ks = 0; ks < 6; ks++) {
            #pragma unroll
            for (int ntp = 0; ntp < 6; ntp++) {
                int wrow = ((2*ntp + brsel)*8 + brow4)*WPAD + ks*16 + bcol4;
                uint32_t bh[4], bl[4];
                LDM_X4(bh, smem_u32(&phi_s[wrow]));
                MMA_BF16(acc[2*ntp    ], ahi[ks], bh);
                MMA_BF16(acc[2*ntp    ], alo[ks], bh);
                MMA_BF16(acc[2*ntp + 1], ahi[ks], bh + 2);
                MMA_BF16(acc[2*ntp + 1], alo[ks], bh + 2);
                LDM_X4(bl, smem_u32(&plo_s[wrow]));
                MMA_BF16(acc[2*ntp    ], ahi[ks], bl);
                MMA_BF16(acc[2*ntp + 1], ahi[ks], bl + 2);
            }
        }

        #pragma unroll
        for (int nt = 0; nt < 12; nt++) {
            out_s[(nt*8 + oc    )*264 + orow    ] = acc[nt][0];
            out_s[(nt*8 + oc + 1)*264 + orow    ] = acc[nt][1];
            out_s[(nt*8 + oc    )*264 + orow + 8] = acc[nt][2];
            out_s[(nt*8 + oc + 1)*264 + orow + 8] = acc[nt][3];
        }
        __syncthreads();

        #pragma unroll 1
        for (int j = 0; j < 12; j++) {
            int c = c0 + j*8;
            float4 v4 = *(const float4*)&out_s[c*264 + p0];
            float bo = bp[c];
            *(float4*)&outp[(size_t)(b*96 + c)*HW + hw0 + p0] =
                make_float4(v4.x + bo, v4.y + bo, v4.z + bo, v4.w + bo);
        }
        __syncthreads();
    }
}

// ---------------- launch ------------------------------------------------------
extern "C" void kernel_launch(void* const* d_in, const int* in_sizes, int n_in,
                              void* d_out, int out_size)
{
    const float* x   = (const float*)d_in[0];
    const float* Wv  = (const float*)d_in[1];
    const float* bv  = (const float*)d_in[2];
    const float* Wqk = (const float*)d_in[3];
    const float* bqk = (const float*)d_in[4];
    const float* Wm1 = (const float*)d_in[5];
    const float* bm1 = (const float*)d_in[6];
    const float* Wm2 = (const float*)d_in[7];
    const float* bm2 = (const float*)d_in[8];
    const float* Wdw = (const float*)d_in[9];
    const float* bdw = (const float*)d_in[10];
    const float* Wp  = (const float*)d_in[11];
    const float* bp  = (const float*)d_in[12];
    float* outp = (float*)d_out;

    const int QKV_SMEM = 288*WPAD*2*2 + 96*PXPAD*2*2;
    const int FIN_SMEM = 96*WPAD*2*2 + 96*PXPAD*2*2;
    cudaFuncSetAttribute(qkv_mma_kernel,
                         cudaFuncAttributeMaxDynamicSharedMemorySize, QKV_SMEM);
    cudaFuncSetAttribute(final_mma_kernel,
                         cudaFuncAttributeMaxDynamicSharedMemorySize, FIN_SMEM);

    prep_kernel    <<<(288*WPAD + 255)/256, 256>>>(Wqk, Wv);
    prep2_kernel   <<<(96*WPAD + 255)/256, 256>>>(Wp);
    bias_kernel    <<<16, 256>>>(Wm1, bm1, Wm2, bm2);
    qkv_mma_kernel <<<148, 512, QKV_SMEM>>>(x, bqk, bv);   // profiled slot 4
    attn_kernel    <<<dim3(4096, 3), 128>>>();
    dw_kernel      <<<24576, 256>>>(Wdw, bdw);
    final_mma_kernel<<<148, 512, FIN_SMEM>>>(bp, outp);
}

// round 13
// speedup vs baseline: 2.1952x; 1.1143x over previous
#include <cuda_runtime.h>
#include <cuda_bf16.h>
#include <math.h>
#include <cstdint>

#define BATCH 4
#define CH    96
#define HRES  256
#define WRES  256
#define HW    65536
#define HEADS 3
#define QSCALE 0.17677669529663687f
#define WPAD  104
#define PXPAD 264

// ---------------- mma.sync / ldmatrix helpers (sm_80+ PTX) ------------------
#define LDM_X4(r, addr) \
    asm volatile("ldmatrix.sync.aligned.m8n8.x4.shared.b16 {%0,%1,%2,%3}, [%4];" \
        : "=r"((r)[0]), "=r"((r)[1]), "=r"((r)[2]), "=r"((r)[3]) : "r"(addr))
#define LDM_X4T(r, addr) \
    asm volatile("ldmatrix.sync.aligned.m8n8.x4.trans.shared.b16 {%0,%1,%2,%3}, [%4];" \
        : "=r"((r)[0]), "=r"((r)[1]), "=r"((r)[2]), "=r"((r)[3]) : "r"(addr))
#define MMA_BF16(d, a, b) \
    asm volatile("mma.sync.aligned.m16n8k16.row.col.f32.bf16.bf16.f32 " \
        "{%0,%1,%2,%3}, {%4,%5,%6,%7}, {%8,%9}, {%0,%1,%2,%3};" \
        : "+f"((d)[0]), "+f"((d)[1]), "+f"((d)[2]), "+f"((d)[3]) \
        : "r"((a)[0]), "r"((a)[1]), "r"((a)[2]), "r"((a)[3]), \
          "r"((b)[0]), "r"((b)[1]))

__device__ __forceinline__ uint32_t smem_u32(const void* p) {
    uint32_t a;
    asm("{ .reg .u64 t; cvta.to.shared.u64 t, %1; cvt.u32.u64 %0, t; }"
        : "=r"(a) : "l"(p));
    return a;
}
__device__ __forceinline__ uint32_t packbf2(float x, float y) {
    __nv_bfloat16 bx = __float2bfloat16_rn(x);
    __nv_bfloat16 by = __float2bfloat16_rn(y);
    return ((uint32_t)__bfloat16_as_ushort(by) << 16) | __bfloat16_as_ushort(bx);
}
__device__ __forceinline__ float2 bf2x(uint32_t u) {
    return make_float2(__bfloat162float(__ushort_as_bfloat16((unsigned short)(u & 0xFFFF))),
                       __bfloat162float(__ushort_as_bfloat16((unsigned short)(u >> 16))));
}

// ---------------- scratch ----------------------------------------------------
__device__ float g_V   [BATCH*CH*HW];          // NCHW, input to dw
__device__ float g_conv[BATCH*CH*HW];          // dw output, NCHW
__device__ float g_att [BATCH*CH*HW];          // attention out, NCHW
__device__ float g_bias[HEADS*64*64];          // [head][n][m]
__device__ __align__(16) __nv_bfloat16 g_Whi[288*WPAD];
__device__ __align__(16) __nv_bfloat16 g_Wlo[288*WPAD];
__device__ __align__(16) __nv_bfloat16 g_Phi[96*WPAD];
__device__ __align__(16) __nv_bfloat16 g_Plo[96*WPAD];

// ---------------- prep kernels ----------------------------------------------
__device__ __forceinline__ float wval(const float* Wqk, const float* Wv,
                                      int o, int k) {
    if (k >= 96) return 0.f;
    if (o < 96)       return Wqk[o*96 + k] * QSCALE;
    else if (o < 192) return Wqk[o*96 + k];
    else              return Wv[(o - 192)*96 + k];
}
__global__ void prep_kernel(const float* __restrict__ Wqk,
                            const float* __restrict__ Wv)
{
    int idx = blockIdx.x * 256 + threadIdx.x;
    if (idx >= 288*WPAD) return;
    float w = wval(Wqk, Wv, idx / WPAD, idx % WPAD);
    __nv_bfloat16 hi = __float2bfloat16_rn(w);
    g_Whi[idx] = hi;
    g_Wlo[idx] = __float2bfloat16_rn(w - __bfloat162float(hi));
}
__global__ void prep2_kernel(const float* __restrict__ Wp)
{
    int idx = blockIdx.x * 256 + threadIdx.x;
    if (idx >= 96*WPAD) return;
    int o = idx / WPAD, k = idx % WPAD;
    float w = (k < 96) ? Wp[o*96 + k] : 0.f;
    __nv_bfloat16 hi = __float2bfloat16_rn(w);
    g_Phi[idx] = hi;
    g_Plo[idx] = __float2bfloat16_rn(w - __bfloat162float(hi));
}

// ---------------- bias MLP table ---------------------------------------------
__global__ void bias_kernel(const float* __restrict__ Wm1, const float* __restrict__ bm1,
                            const float* __restrict__ Wm2, const float* __restrict__ bm2)
{
    int gid = blockIdx.x * 256 + threadIdx.x;
    int n = gid >> 6, m = gid & 63;
    float r0 = (float)((n >> 3) - (m >> 3));
    float r1 = (float)((n & 7)  - (m & 7));
    r0 = copysignf(log1pf(fabsf(r0)), r0);
    r1 = copysignf(log1pf(fabsf(r1)), r1);
    float a0 = bm2[0], a1 = bm2[1], a2 = bm2[2];
    for (int j = 0; j < 256; j++) {
        float h = fmaf(r0, Wm1[j], fmaf(r1, Wm1[256 + j], bm1[j]));
        h = fmaxf(h, 0.f);
        a0 = fmaf(h, Wm2[j*3 + 0], a0);
        a1 = fmaf(h, Wm2[j*3 + 1], a1);
        a2 = fmaf(h, Wm2[j*3 + 2], a2);
    }
    g_bias[0*4096 + gid] = a0;
    g_bias[1*4096 + gid] = a1;
    g_bias[2*4096 + gid] = a2;
}

__device__ __forceinline__ int swin_label(int wh, int ww, int idx) {
    int rh = (wh == 31) ? (1 + (((idx >> 3) >= 4) ? 1 : 0)) : 0;
    int rw = (ww == 31) ? (1 + (((idx & 7)  >= 4) ? 1 : 0)) : 0;
    return rh*3 + rw;
}

// ---------------- FUSED: QKV GEMM + windowed attention ----------------------
// Persistent, 512 thr. Tile = 4 complete windows (one window-row quad, 256 px).
// q/k/v never touch DRAM: GEMM epilogue writes bf16 hi/lo staging [win][d][72],
// attention (R11 code) consumes it per head; V reconstructed for dw.
__global__ __launch_bounds__(512, 1) void fused_kernel(
    const float* __restrict__ x,
    const float* __restrict__ bqk, const float* __restrict__ bv)
{
    extern __shared__ __align__(16) unsigned char dsm[];
    __nv_bfloat16* whi_s = (__nv_bfloat16*)dsm;            // [288*WPAD]
    __nv_bfloat16* wlo_s = whi_s + 288*WPAD;
    __nv_bfloat16* stage = wlo_s + 288*WPAD;               // union area
    __nv_bfloat16* xhi_s = stage;                          // [96][PXPAD]
    __nv_bfloat16* xlo_s = stage + 96*PXPAD;
    // attn staging (per head): 6 arrays of [4 win][32 d][72], 9216 elems each
    // order: qhi, qlo, khi, klo, vhi, vlo

    int tid  = threadIdx.x;
    int warp = tid >> 5, lane = tid & 31;

    // W blobs -> smem once per block
    {
        const uint4* s1 = (const uint4*)g_Whi; uint4* d1 = (uint4*)whi_s;
        const uint4* s2 = (const uint4*)g_Wlo; uint4* d2 = (uint4*)wlo_s;
        #pragma unroll 4
        for (int i = tid; i < 288*WPAD*2/16; i += 512) { d1[i] = s1[i]; d2[i] = s2[i]; }
    }

    int idx8 = lane & 7, quad = lane >> 3;
    int krow = (quad >> 1)*8 + idx8;              // X A-frags (trans)
    int apxb = warp*16 + (quad & 1)*8;
    int brow4 = lane & 7;                         // W B-frags (non-trans x4)
    int bcol4 = ((lane >> 3) & 1)*8;
    int brsel = (lane >> 4) & 1;
    int awin = warp >> 2;                         // attention: window for warp
    int n0a  = (warp & 3)*16;                     // attention: q rows

    for (int tile = blockIdx.x; tile < 1024; tile += gridDim.x) {
        int b   = tile >> 8;
        int rem = tile & 255;
        int wh  = rem >> 3;
        int ww0 = (rem & 7)*4;

        __syncthreads();   // staging fully consumed by previous tile
        // ---- x load (window-aligned, rolled) -> bf16 hi/lo [k][px] ----
        for (int idx = tid; idx < 96*64; idx += 512) {
            int k = idx >> 6, g = idx & 63;
            int r = g >> 3, q = g & 7;
            int win = q >> 1, c0 = (q & 1)*4;
            int gh = (wh*8 + r + 4) & 255;
            int gw = ((ww0 + win)*8 + c0 + 4) & 255;
            float4 v = *(const float4*)&x[(size_t)(b*96 + k)*HW + gh*256 + gw];
            int px0 = win*64 + r*8 + c0;
            __nv_bfloat16 h0 = __float2bfloat16_rn(v.x);
            __nv_bfloat16 h1 = __float2bfloat16_rn(v.y);
            __nv_bfloat16 h2 = __float2bfloat16_rn(v.z);
            __nv_bfloat16 h3 = __float2bfloat16_rn(v.w);
            uint32_t hp0 = (uint32_t)__bfloat16_as_ushort(h1) << 16 | __bfloat16_as_ushort(h0);
            uint32_t hp1 = (uint32_t)__bfloat16_as_ushort(h3) << 16 | __bfloat16_as_ushort(h2);
            uint32_t lp0 = packbf2(v.x - __bfloat162float(h0), v.y - __bfloat162float(h1));
            uint32_t lp1 = packbf2(v.z - __bfloat162float(h2), v.w - __bfloat162float(h3));
            *(uint2*)&xhi_s[k*PXPAD + px0] = make_uint2(hp0, hp1);
            *(uint2*)&xlo_s[k*PXPAD + px0] = make_uint2(lp0, lp1);
        }
        __syncthreads();

        // ---- X A-fragments, held through all heads ----
        uint32_t ahi[6][4], alo[6][4];
        #pragma unroll
        for (int ks = 0; ks < 6; ks++) {
            LDM_X4T(ahi[ks], smem_u32(&xhi_s[(ks*16 + krow)*PXPAD + apxb]));
            LDM_X4T(alo[ks], smem_u32(&xlo_s[(ks*16 + krow)*PXPAD + apxb]));
        }
        __syncthreads();   // x area now reusable as attn staging

        #pragma unroll 1
        for (int h = 0; h < 3; h++) {
            // ---- GEMM: q, k, v for head h -> staging ----
            #pragma unroll 1
            for (int t = 0; t < 3; t++) {
                float acc[4][4];
                #pragma unroll
                for (int nt = 0; nt < 4; nt++)
                    #pragma unroll
                    for (int j = 0; j < 4; j++) acc[nt][j] = 0.f;

                int wbase = t*96 + h*32;
                #pragma unroll 1
                for (int ks = 0; ks < 6; ks++) {
                    #pragma unroll
                    for (int ntp = 0; ntp < 2; ntp++) {
                        int wrow = (wbase + (2*ntp + brsel)*8 + brow4)*WPAD + ks*16 + bcol4;
                        uint32_t bh[4], bl[4];
                        LDM_X4(bh, smem_u32(&whi_s[wrow]));
                        MMA_BF16(acc[2*ntp    ], ahi[ks], bh);
                        MMA_BF16(acc[2*ntp    ], alo[ks], bh);
                        MMA_BF16(acc[2*ntp + 1], ahi[ks], bh + 2);
                        MMA_BF16(acc[2*ntp + 1], alo[ks], bh + 2);
                        LDM_X4(bl, smem_u32(&wlo_s[wrow]));
                        MMA_BF16(acc[2*ntp    ], ahi[ks], bl);
                        MMA_BF16(acc[2*ntp + 1], ahi[ks], bl + 2);
                    }
                }

                // epilogue: bias + bf16 hi/lo split -> staging [win][d][72]
                __nv_bfloat16* sth = stage + (t*2    )*9216;
                __nv_bfloat16* stl = stage + (t*2 + 1)*9216;
                int px1 = warp*16 + (lane >> 2);
                int winc = px1 >> 6;
                int m1 = px1 & 63, m2 = m1 + 8;
                int sb = winc*2304;
                #pragma unroll
                for (int nt = 0; nt < 4; nt++) {
                    int d0 = nt*8 + (lane & 3)*2;
                    float bb0, bb1;
                    if (t == 0)      { bb0 = bqk[h*32 + d0]*QSCALE; bb1 = bqk[h*32 + d0 + 1]*QSCALE; }
                    else if (t == 1) { bb0 = bqk[96 + h*32 + d0];   bb1 = bqk[96 + h*32 + d0 + 1]; }
                    else             { bb0 = bv[h*32 + d0];         bb1 = bv[h*32 + d0 + 1]; }
                    float v00 = acc[nt][0] + bb0, v01 = acc[nt][1] + bb1;
                    float v10 = acc[nt][2] + bb0, v11 = acc[nt][3] + bb1;
                    __nv_bfloat16 e00 = __float2bfloat16_rn(v00);
                    __nv_bfloat16 e01 = __float2bfloat16_rn(v01);
                    __nv_bfloat16 e10 = __float2bfloat16_rn(v10);
                    __nv_bfloat16 e11 = __float2bfloat16_rn(v11);
                    sth[sb + d0*72 + m1]       = e00;
                    sth[sb + (d0 + 1)*72 + m1] = e01;
                    sth[sb + d0*72 + m2]       = e10;
                    sth[sb + (d0 + 1)*72 + m2] = e11;
                    stl[sb + d0*72 + m1]       = __float2bfloat16_rn(v00 - __bfloat162float(e00));
                    stl[sb + (d0 + 1)*72 + m1] = __float2bfloat16_rn(v01 - __bfloat162float(e01));
                    stl[sb + d0*72 + m2]       = __float2bfloat16_rn(v10 - __bfloat162float(e10));
                    stl[sb + (d0 + 1)*72 + m2] = __float2bfloat16_rn(v11 - __bfloat162float(e11));
                }
            }
            __syncthreads();   // staging complete for head h

            // ---- attention for head h (R11, verbatim addressing) ----
            {
                const __nv_bfloat16* sqh = stage + 0*9216 + awin*2304;
                const __nv_bfloat16* sql = stage + 1*9216 + awin*2304;
                const __nv_bfloat16* skh = stage + 2*9216 + awin*2304;
                const __nv_bfloat16* skl = stage + 3*9216 + awin*2304;
                const __nv_bfloat16* svh = stage + 4*9216 + awin*2304;
                const __nv_bfloat16* svl = stage + 5*9216 + awin*2304;

                uint32_t aqh[2][4], aql[2][4];
                int krow2 = (quad >> 1)*8 + idx8;
                int apx2  = n0a + (quad & 1)*8;
                #pragma unroll
                for (int ks = 0; ks < 2; ks++) {
                    LDM_X4T(aqh[ks], smem_u32(&sqh[(ks*16 + krow2)*72 + apx2]));
                    LDM_X4T(aql[ks], smem_u32(&sql[(ks*16 + krow2)*72 + apx2]));
                }

                float accq[8][4];
                #pragma unroll
                for (int j = 0; j < 8; j++)
                    #pragma unroll
                    for (int r = 0; r < 4; r++) accq[j][r] = 0.f;

                {
                    int browt = (quad & 1)*8 + idx8;
                    int bcolt = (quad >> 1)*8;
                    #pragma unroll
                    for (int ks = 0; ks < 2; ks++) {
                        #pragma unroll
                        for (int jp = 0; jp < 4; jp++) {
                            uint32_t off = (ks*16 + browt)*72 + jp*16 + bcolt;
                            uint32_t bh[4], bl[4];
                            LDM_X4T(bh, smem_u32(&skh[off]));
                            MMA_BF16(accq[2*jp    ], aqh[ks], bh);
                            MMA_BF16(accq[2*jp    ], aql[ks], bh);
                            MMA_BF16(accq[2*jp + 1], aqh[ks], bh + 2);
                            MMA_BF16(accq[2*jp + 1], aql[ks], bh + 2);
                            LDM_X4T(bl, smem_u32(&skl[off]));
                            MMA_BF16(accq[2*jp    ], aqh[ks], bl);
                            MMA_BF16(accq[2*jp + 1], aqh[ks], bl + 2);
                        }
                    }
                }

                int ww_abs = ww0 + awin;
                bool masked = (wh == 31) || (ww_abs == 31);
                int n1 = n0a + (lane >> 2);
                int n2 = n1 + 8;
                int mq = (lane & 3)*2;
                int labn1 = 0, labn2 = 0;
                if (masked) { labn1 = swin_label(wh, ww_abs, n1); labn2 = swin_label(wh, ww_abs, n2); }

                const float* bb = g_bias + h*4096;
                float lsum1 = 0.f, lsum2 = 0.f;
                uint32_t pahi[4][4], palo[4][4];

                #pragma unroll
                for (int j = 0; j < 8; j++) {
                    int m0 = j*8 + mq;
                    float2 b1 = *(const float2*)&bb[n1*64 + m0];
                    float2 b2 = *(const float2*)&bb[n2*64 + m0];
                    float p0 = __expf(accq[j][0] + b1.x);
                    float p1 = __expf(accq[j][1] + b1.y);
                    float p2 = __expf(accq[j][2] + b2.x);
                    float p3 = __expf(accq[j][3] + b2.y);
                    if (masked) {
                        int lm0 = swin_label(wh, ww_abs, m0);
                        int lm1 = swin_label(wh, ww_abs, m0 + 1);
                        if (lm0 != labn1) p0 = 0.f;
                        if (lm1 != labn1) p1 = 0.f;
                        if (lm0 != labn2) p2 = 0.f;
                        if (lm1 != labn2) p3 = 0.f;
                    }
                    lsum1 += p0 + p1;
                    lsum2 += p2 + p3;
                    int s = j >> 1, half = (j & 1)*2;
                    __nv_bfloat16 e0 = __float2bfloat16_rn(p0);
                    __nv_bfloat16 e1 = __float2bfloat16_rn(p1);
                    __nv_bfloat16 e2 = __float2bfloat16_rn(p2);
                    __nv_bfloat16 e3 = __float2bfloat16_rn(p3);
                    pahi[s][half]     = ((uint32_t)__bfloat16_as_ushort(e1) << 16) | __bfloat16_as_ushort(e0);
                    pahi[s][half + 1] = ((uint32_t)__bfloat16_as_ushort(e3) << 16) | __bfloat16_as_ushort(e2);
                    palo[s][half]     = packbf2(p0 - __bfloat162float(e0), p1 - __bfloat162float(e1));
                    palo[s][half + 1] = packbf2(p2 - __bfloat162float(e2), p3 - __bfloat162float(e3));
                }
                lsum1 += __shfl_xor_sync(0xFFFFFFFF, lsum1, 1);
                lsum1 += __shfl_xor_sync(0xFFFFFFFF, lsum1, 2);
                lsum2 += __shfl_xor_sync(0xFFFFFFFF, lsum2, 1);
                lsum2 += __shfl_xor_sync(0xFFFFFFFF, lsum2, 2);
                float inv1 = 1.f / lsum1, inv2 = 1.f / lsum2;

                float o[4][4];
                #pragma unroll
                for (int t = 0; t < 4; t++)
                    #pragma unroll
                    for (int r = 0; r < 4; r++) o[t][r] = 0.f;

                {
                    int vrow = (quad >> 1)*8 + idx8;
                    int vcol = (quad & 1)*8;
                    #pragma unroll
                    for (int s = 0; s < 4; s++) {
                        #pragma unroll
                        for (int tp = 0; tp < 2; tp++) {
                            uint32_t off = (tp*16 + vrow)*72 + s*16 + vcol;
                            uint32_t bh[4], bl[4];
                            LDM_X4(bh, smem_u32(&svh[off]));
                            MMA_BF16(o[2*tp    ], pahi[s], bh);
                            MMA_BF16(o[2*tp    ], palo[s], bh);
                            MMA_BF16(o[2*tp + 1], pahi[s], bh + 2);
                            MMA_BF16(o[2*tp + 1], palo[s], bh + 2);
                            LDM_X4(bl, smem_u32(&svl[off]));
                            MMA_BF16(o[2*tp    ], pahi[s], bl);
                            MMA_BF16(o[2*tp + 1], pahi[s], bl + 2);
                        }
                    }
                }

                // g_att NCHW writes
                int r1 = n1 >> 3, c1 = n1 & 7;
                int r2 = n2 >> 3, c2 = n2 & 7;
                int off1 = (((wh << 3) + r1 + 4) & 255)*256 + (((ww_abs << 3) + c1 + 4) & 255);
                int off2 = (((wh << 3) + r2 + 4) & 255)*256 + (((ww_abs << 3) + c2 + 4) & 255);
                size_t cb = (size_t)(b*96 + h*32 + mq)*HW;
                #pragma unroll
                for (int t = 0; t < 4; t++) {
                    size_t cbase = cb + (size_t)(t*8)*HW;
                    g_att[cbase      + off1] = o[t][0]*inv1;
                    g_att[cbase + HW + off1] = o[t][1]*inv1;
                    g_att[cbase      + off2] = o[t][2]*inv2;
                    g_att[cbase + HW + off2] = o[t][3]*inv2;
                }
            }

            // ---- V reconstruct -> g_V (NCHW) for depthwise ----
            for (int idx2 = tid; idx2 < 2048; idx2 += 512) {
                int d = idx2 >> 6, g = idx2 & 63;
                int r = g >> 3, q = g & 7;
                int win = q >> 1, c0 = (q & 1)*4;
                const __nv_bfloat16* svh = stage + 4*9216 + win*2304;
                const __nv_bfloat16* svl = stage + 5*9216 + win*2304;
                int si = d*72 + r*8 + c0;
                uint2 uh = *(const uint2*)&svh[si];
                uint2 ul = *(const uint2*)&svl[si];
                float2 h0 = bf2x(uh.x), h1 = bf2x(uh.y);
                float2 l0 = bf2x(ul.x), l1 = bf2x(ul.y);
                int gh = (wh*8 + r + 4) & 255;
                int gw = ((ww0 + win)*8 + c0 + 4) & 255;
                *(float4*)&g_V[(size_t)(b*96 + h*32 + d)*HW + gh*256 + gw] =
                    make_float4(h0.x + l0.x, h0.y + l0.y, h1.x + l1.x, h1.y + l1.y);
            }
            __syncthreads();   // staging free for next head
        }
    }
}

// ---------------- kernel DW: depthwise 5x5, vectorized halo -----------------
__global__ __launch_bounds__(256) void dw_kernel(const float* __restrict__ Wdw,
                                                 const float* __restrict__ bdw)
{
    __shared__ __align__(16) float s[36][44];
    __shared__ float wk[25];

    int blk  = blockIdx.x;
    int img  = blk >> 6;
    int tile = blk & 63;
    int c    = img % 96;
    int h0   = (tile >> 3) << 5, w0 = (tile & 7) << 5;
    int tid  = threadIdx.x;

    if (tid < 25) wk[tid] = Wdw[c*25 + tid];
    const float* vimg = g_V + (size_t)img * HW;

    bool border = (h0 == 0) || (h0 == 224) || (w0 == 0) || (w0 == 224);
    if (!border) {
        const float* src = vimg + (h0 - 2)*256 + (w0 - 4);
        for (int idx = tid; idx < 36*11; idx += 256) {
            int r = idx / 11, c4 = idx - r*11;
            *(float4*)&s[r][c4*4] = *(const float4*)&src[r*256 + c4*4];
        }
    } else {
        for (int idx = tid; idx < 36*44; idx += 256) {
            int r  = idx / 44, cc = idx % 44;
            int hh = h0 - 2 + r;  hh = (hh < 0) ? -hh : ((hh > 255) ? 510 - hh : hh);
            int wq = w0 - 4 + cc; wq = (wq < 0) ? -wq : ((wq > 255) ? 510 - wq : wq);
            s[r][cc] = vimg[hh*256 + wq];
        }
    }
    __syncthreads();

    int y   = tid >> 3;
    int xq0 = (tid & 7) * 4;
    float b0 = bdw[c];
    float acc[4] = {b0, b0, b0, b0};
    #pragma unroll
    for (int i = 0; i < 5; i++) {
        float4 fa = *(const float4*)&s[y + i][xq0];
        float4 fb = *(const float4*)&s[y + i][xq0 + 4];
        float4 fc = *(const float4*)&s[y + i][xq0 + 8];
        float f[12] = {fa.x, fa.y, fa.z, fa.w, fb.x, fb.y, fb.z, fb.w,
                       fc.x, fc.y, fc.z, fc.w};
        #pragma unroll
        for (int j = 0; j < 5; j++) {
            float wv = wk[i*5 + j];
            acc[0] = fmaf(f[j + 2], wv, acc[0]);
            acc[1] = fmaf(f[j + 3], wv, acc[1]);
            acc[2] = fmaf(f[j + 4], wv, acc[2]);
            acc[3] = fmaf(f[j + 5], wv, acc[3]);
        }
    }
    *(float4*)&g_conv[(size_t)img*HW + (h0 + y)*256 + (w0 + xq0)] =
        make_float4(acc[0], acc[1], acc[2], acc[3]);
}

// ---------------- kernel D: persistent HMMA final GEMM ----------------------
__global__ __launch_bounds__(512, 1) void final_mma_kernel(
    const float* __restrict__ bp, float* __restrict__ outp)
{
    extern __shared__ __align__(16) unsigned char dsm[];
    __nv_bfloat16* phi_s = (__nv_bfloat16*)dsm;
    __nv_bfloat16* plo_s = phi_s + 96*WPAD;
    __nv_bfloat16* xhi_s = plo_s + 96*WPAD;
    __nv_bfloat16* xlo_s = xhi_s + 96*PXPAD;
    float* out_s = (float*)xhi_s;

    int tid  = threadIdx.x;
    int warp = tid >> 5, lane = tid & 31;

    {
        const uint4* s1 = (const uint4*)g_Phi; uint4* d1 = (uint4*)phi_s;
        const uint4* s2 = (const uint4*)g_Plo; uint4* d2 = (uint4*)plo_s;
        #pragma unroll 4
        for (int i = tid; i < 96*WPAD*2/16; i += 512) { d1[i] = s1[i]; d2[i] = s2[i]; }
    }

    int idx8 = lane & 7, quad = lane >> 3;
    int krow = (quad >> 1)*8 + idx8;
    int apxb = warp*16 + (quad & 1)*8;
    int brow4 = lane & 7;
    int bcol4 = ((lane >> 3) & 1)*8;
    int brsel = (lane >> 4) & 1;
    int pq   = tid & 63;
    int p0   = pq*4;
    int c0   = tid >> 6;
    int orow = warp*16 + (lane >> 2);
    int oc   = (lane & 3)*2;

    for (int tile = blockIdx.x; tile < 1024; tile += gridDim.x) {
        int b   = tile >> 8;
        int hw0 = (tile & 255) << 8;

        __syncthreads();
        for (int idx = tid; idx < 96*64; idx += 512) {
            int k = idx >> 6, pg = idx & 63;
            size_t gi = (size_t)(b*96 + k)*HW + hw0 + pg*4;
            float4 a = *(const float4*)&g_conv[gi];
            float4 c4 = *(const float4*)&g_att[gi];
            float4 v = make_float4(a.x + c4.x, a.y + c4.y, a.z + c4.z, a.w + c4.w);
            __nv_bfloat16 h0 = __float2bfloat16_rn(v.x);
            __nv_bfloat16 h1 = __float2bfloat16_rn(v.y);
            __nv_bfloat16 h2 = __float2bfloat16_rn(v.z);
            __nv_bfloat16 h3 = __float2bfloat16_rn(v.w);
            uint32_t hp0 = (uint32_t)__bfloat16_as_ushort(h1) << 16 | __bfloat16_as_ushort(h0);
            uint32_t hp1 = (uint32_t)__bfloat16_as_ushort(h3) << 16 | __bfloat16_as_ushort(h2);
            uint32_t lp0 = packbf2(v.x - __bfloat162float(h0), v.y - __bfloat162float(h1));
            uint32_t lp1 = packbf2(v.z - __bfloat162float(h2), v.w - __bfloat162float(h3));
            *(uint2*)&xhi_s[k*PXPAD + pg*4] = make_uint2(hp0, hp1);
            *(uint2*)&xlo_s[k*PXPAD + pg*4] = make_uint2(lp0, lp1);
        }
        __syncthreads();

        uint32_t ahi[6][4], alo[6][4];
        #pragma unroll
        for (int ks = 0; ks < 6; ks++) {
            LDM_X4T(ahi[ks], smem_u32(&xhi_s[(ks*16 + krow)*PXPAD + apxb]));
            LDM_X4T(alo[ks], smem_u32(&xlo_s[(ks*16 + krow)*PXPAD + apxb]));
        }
        __syncthreads();

        float acc[12][4];
        #pragma unroll
        for (int nt = 0; nt < 12; nt++)
            #pragma unroll
            for (int j = 0; j < 4; j++) acc[nt][j] = 0.f;

        #pragma unroll 1
        for (int ks = 0; ks < 6; ks++) {
            #pragma unroll
            for (int ntp = 0; ntp < 6; ntp++) {
                int wrow = ((2*ntp + brsel)*8 + brow4)*WPAD + ks*16 + bcol4;
                uint32_t bh[4], bl[4];
                LDM_X4(bh, smem_u32(&phi_s[wrow]));
                MMA_BF16(acc[2*ntp    ], ahi[ks], bh);
                MMA_BF16(acc[2*ntp    ], alo[ks], bh);
                MMA_BF16(acc[2*ntp + 1], ahi[ks], bh + 2);
                MMA_BF16(acc[2*ntp + 1], alo[ks], bh + 2);
                LDM_X4(bl, smem_u32(&plo_s[wrow]));
                MMA_BF16(acc[2*ntp    ], ahi[ks], bl);
                MMA_BF16(acc[2*ntp + 1], ahi[ks], bl + 2);
            }
        }

        #pragma unroll
        for (int nt = 0; nt < 12; nt++) {
            out_s[(nt*8 + oc    )*264 + orow    ] = acc[nt][0];
            out_s[(nt*8 + oc + 1)*264 + orow    ] = acc[nt][1];
            out_s[(nt*8 + oc    )*264 + orow + 8] = acc[nt][2];
            out_s[(nt*8 + oc + 1)*264 + orow + 8] = acc[nt][3];
        }
        __syncthreads();

        #pragma unroll 1
        for (int j = 0; j < 12; j++) {
            int c = c0 + j*8;
            float4 v4 = *(const float4*)&out_s[c*264 + p0];
            float bo = bp[c];
            *(float4*)&outp[(size_t)(b*96 + c)*HW + hw0 + p0] =
                make_float4(v4.x + bo, v4.y + bo, v4.z + bo, v4.w + bo);
        }
        __syncthreads();
    }
}

// ---------------- launch ------------------------------------------------------
extern "C" void kernel_launch(void* const* d_in, const int* in_sizes, int n_in,
                              void* d_out, int out_size)
{
    const float* x   = (const float*)d_in[0];
    const float* Wv  = (const float*)d_in[1];
    const float* bv  = (const float*)d_in[2];
    const float* Wqk = (const float*)d_in[3];
    const float* bqk = (const float*)d_in[4];
    const float* Wm1 = (const float*)d_in[5];
    const float* bm1 = (const float*)d_in[6];
    const float* Wm2 = (const float*)d_in[7];
    const float* bm2 = (const float*)d_in[8];
    const float* Wdw = (const float*)d_in[9];
    const float* bdw = (const float*)d_in[10];
    const float* Wp  = (const float*)d_in[11];
    const float* bp  = (const float*)d_in[12];
    float* outp = (float*)d_out;

    const int FUSED_SMEM = 288*WPAD*2*2 + 6*9216*2;        // 119808 + 110592 = 230400
    const int FIN_SMEM   = 96*WPAD*2*2 + 96*PXPAD*2*2;
    cudaFuncSetAttribute(fused_kernel,
                         cudaFuncAttributeMaxDynamicSharedMemorySize, FUSED_SMEM);
    cudaFuncSetAttribute(final_mma_kernel,
                         cudaFuncAttributeMaxDynamicSharedMemorySize, FIN_SMEM);

    prep_kernel    <<<(288*WPAD + 255)/256, 256>>>(Wqk, Wv);
    prep2_kernel   <<<(96*WPAD + 255)/256, 256>>>(Wp);
    bias_kernel    <<<16, 256>>>(Wm1, bm1, Wm2, bm2);
    fused_kernel   <<<148, 512, FUSED_SMEM>>>(x, bqk, bv); // profiled slot 4
    dw_kernel      <<<24576, 256>>>(Wdw, bdw);
    final_mma_kernel<<<148, 512, FIN_SMEM>>>(bp, outp);
}

// round 14
// speedup vs baseline: 2.2046x; 1.0043x over previous
#include <cuda_runtime.h>
#include <cuda_bf16.h>
#include <math.h>
#include <cstdint>

#define BATCH 4
#define CH    96
#define HRES  256
#define WRES  256
#define HW    65536
#define HEADS 3
#define QSCALE 0.17677669529663687f
#define WPAD  104
#define PXPAD 264

// ---------------- mma.sync / ldmatrix helpers (sm_80+ PTX) ------------------
#define LDM_X4(r, addr) \
    asm volatile("ldmatrix.sync.aligned.m8n8.x4.shared.b16 {%0,%1,%2,%3}, [%4];" \
        : "=r"((r)[0]), "=r"((r)[1]), "=r"((r)[2]), "=r"((r)[3]) : "r"(addr))
#define LDM_X4T(r, addr) \
    asm volatile("ldmatrix.sync.aligned.m8n8.x4.trans.shared.b16 {%0,%1,%2,%3}, [%4];" \
        : "=r"((r)[0]), "=r"((r)[1]), "=r"((r)[2]), "=r"((r)[3]) : "r"(addr))
#define MMA_BF16(d, a, b) \
    asm volatile("mma.sync.aligned.m16n8k16.row.col.f32.bf16.bf16.f32 " \
        "{%0,%1,%2,%3}, {%4,%5,%6,%7}, {%8,%9}, {%0,%1,%2,%3};" \
        : "+f"((d)[0]), "+f"((d)[1]), "+f"((d)[2]), "+f"((d)[3]) \
        : "r"((a)[0]), "r"((a)[1]), "r"((a)[2]), "r"((a)[3]), \
          "r"((b)[0]), "r"((b)[1]))

__device__ __forceinline__ uint32_t smem_u32(const void* p) {
    uint32_t a;
    asm("{ .reg .u64 t; cvta.to.shared.u64 t, %1; cvt.u32.u64 %0, t; }"
        : "=r"(a) : "l"(p));
    return a;
}
__device__ __forceinline__ uint32_t packbf2(float x, float y) {
    __nv_bfloat16 bx = __float2bfloat16_rn(x);
    __nv_bfloat16 by = __float2bfloat16_rn(y);
    return ((uint32_t)__bfloat16_as_ushort(by) << 16) | __bfloat16_as_ushort(bx);
}

// ---------------- scratch ----------------------------------------------------
__device__ float g_V   [BATCH*CH*HW];          // NCHW, input to dw
__device__ float g_conv[BATCH*CH*HW];          // dw output, NCHW
__device__ float g_att [BATCH*CH*HW];          // attention out, NCHW
__device__ float g_bias[HEADS*64*64];          // [head][n][m]
__device__ __align__(16) __nv_bfloat16 g_Whi[288*WPAD];
__device__ __align__(16) __nv_bfloat16 g_Wlo[288*WPAD];
__device__ __align__(16) __nv_bfloat16 g_Phi[96*WPAD];
__device__ __align__(16) __nv_bfloat16 g_Plo[96*WPAD];

// ---------------- merged prep + bias kernel ----------------------------------
__device__ __forceinline__ float wval(const float* Wqk, const float* Wv,
                                      int o, int k) {
    if (k >= 96) return 0.f;
    if (o < 96)       return Wqk[o*96 + k] * QSCALE;
    else if (o < 192) return Wqk[o*96 + k];
    else              return Wv[(o - 192)*96 + k];
}
__global__ void prepbias_kernel(
    const float* __restrict__ Wqk, const float* __restrict__ Wv,
    const float* __restrict__ Wp,
    const float* __restrict__ Wm1, const float* __restrict__ bm1,
    const float* __restrict__ Wm2, const float* __restrict__ bm2)
{
    int blk = blockIdx.x;
    int tid = threadIdx.x;
    if (blk < 117) {                           // W qkv blobs
        int idx = blk*256 + tid;
        if (idx >= 288*WPAD) return;
        float w = wval(Wqk, Wv, idx / WPAD, idx % WPAD);
        __nv_bfloat16 hi = __float2bfloat16_rn(w);
        g_Whi[idx] = hi;
        g_Wlo[idx] = __float2bfloat16_rn(w - __bfloat162float(hi));
    } else if (blk < 156) {                    // Wp blobs
        int idx = (blk - 117)*256 + tid;
        if (idx >= 96*WPAD) return;
        int o = idx / WPAD, k = idx % WPAD;
        float w = (k < 96) ? Wp[o*96 + k] : 0.f;
        __nv_bfloat16 hi = __float2bfloat16_rn(w);
        g_Phi[idx] = hi;
        g_Plo[idx] = __float2bfloat16_rn(w - __bfloat162float(hi));
    } else {                                   // bias MLP table
        int gid = (blk - 156)*256 + tid;
        int n = gid >> 6, m = gid & 63;
        float r0 = (float)((n >> 3) - (m >> 3));
        float r1 = (float)((n & 7)  - (m & 7));
        r0 = copysignf(log1pf(fabsf(r0)), r0);
        r1 = copysignf(log1pf(fabsf(r1)), r1);
        float a0 = bm2[0], a1 = bm2[1], a2 = bm2[2];
        for (int j = 0; j < 256; j++) {
            float h = fmaf(r0, Wm1[j], fmaf(r1, Wm1[256 + j], bm1[j]));
            h = fmaxf(h, 0.f);
            a0 = fmaf(h, Wm2[j*3 + 0], a0);
            a1 = fmaf(h, Wm2[j*3 + 1], a1);
            a2 = fmaf(h, Wm2[j*3 + 2], a2);
        }
        g_bias[0*4096 + gid] = a0;
        g_bias[1*4096 + gid] = a1;
        g_bias[2*4096 + gid] = a2;
    }
}

__device__ __forceinline__ int swin_label(int wh, int ww, int idx) {
    int rh = (wh == 31) ? (1 + (((idx >> 3) >= 4) ? 1 : 0)) : 0;
    int rw = (ww == 31) ? (1 + (((idx & 7)  >= 4) ? 1 : 0)) : 0;
    return rh*3 + rw;
}

// ---------------- FUSED: QKV GEMM (A=W, B=x) + windowed attention -----------
__global__ __launch_bounds__(512, 1) void fused_kernel(
    const float* __restrict__ x,
    const float* __restrict__ bqk, const float* __restrict__ bv)
{
    extern __shared__ __align__(16) unsigned char dsm[];
    __nv_bfloat16* whi_s = (__nv_bfloat16*)dsm;            // [288*WPAD]
    __nv_bfloat16* wlo_s = whi_s + 288*WPAD;
    __nv_bfloat16* stage = wlo_s + 288*WPAD;               // union area
    __nv_bfloat16* xhi_s = stage;                          // [96][PXPAD]
    __nv_bfloat16* xlo_s = stage + 96*PXPAD;
    // attn staging (per head): 6 arrays of [4 win][32 d][72]: qhi,qlo,khi,klo,vhi,vlo

    int tid  = threadIdx.x;
    int warp = tid >> 5, lane = tid & 31;

    // W blobs -> smem once per block
    {
        const uint4* s1 = (const uint4*)g_Whi; uint4* d1 = (uint4*)whi_s;
        const uint4* s2 = (const uint4*)g_Wlo; uint4* d2 = (uint4*)wlo_s;
        #pragma unroll 4
        for (int i = tid; i < 288*WPAD*2/16; i += 512) { d1[i] = s1[i]; d2[i] = s2[i]; }
    }

    int idx8 = lane & 7, quad = lane >> 3;
    // x B-frags (trans from [k][px])
    int xbrow = (quad & 1)*8 + idx8;
    int xbcol = warp*16 + (quad >> 1)*8;
    // W A-frags (non-trans from [ch][k])
    int warow = (quad & 1)*8 + idx8;
    int wacol = (quad >> 1)*8;
    // epilogue (C-frag: row = ch, col-pair = px)
    int rrow  = lane >> 2;
    int mloc  = (warp & 3)*16 + (lane & 3)*2;
    int sbwin = (warp >> 2)*2304;
    // attention
    int awin = warp >> 2;
    int n0a  = (warp & 3)*16;

    for (int tile = blockIdx.x; tile < 1024; tile += gridDim.x) {
        int b   = tile >> 8;
        int rem = tile & 255;
        int wh  = rem >> 3;
        int ww0 = (rem & 7)*4;

        __syncthreads();   // staging fully consumed by previous tile
        // ---- x load (window-aligned, rolled) -> bf16 hi/lo [k][px] ----
        for (int idx = tid; idx < 96*64; idx += 512) {
            int k = idx >> 6, g = idx & 63;
            int r = g >> 3, q = g & 7;
            int win = q >> 1, c0 = (q & 1)*4;
            int gh = (wh*8 + r + 4) & 255;
            int gw = ((ww0 + win)*8 + c0 + 4) & 255;
            float4 v = *(const float4*)&x[(size_t)(b*96 + k)*HW + gh*256 + gw];
            int px0 = win*64 + r*8 + c0;
            __nv_bfloat16 h0 = __float2bfloat16_rn(v.x);
            __nv_bfloat16 h1 = __float2bfloat16_rn(v.y);
            __nv_bfloat16 h2 = __float2bfloat16_rn(v.z);
            __nv_bfloat16 h3 = __float2bfloat16_rn(v.w);
            uint32_t hp0 = (uint32_t)__bfloat16_as_ushort(h1) << 16 | __bfloat16_as_ushort(h0);
            uint32_t hp1 = (uint32_t)__bfloat16_as_ushort(h3) << 16 | __bfloat16_as_ushort(h2);
            uint32_t lp0 = packbf2(v.x - __bfloat162float(h0), v.y - __bfloat162float(h1));
            uint32_t lp1 = packbf2(v.z - __bfloat162float(h2), v.w - __bfloat162float(h3));
            *(uint2*)&xhi_s[k*PXPAD + px0] = make_uint2(hp0, hp1);
            *(uint2*)&xlo_s[k*PXPAD + px0] = make_uint2(lp0, lp1);
        }
        __syncthreads();

        // ---- x B-fragments, held through all heads ----
        uint32_t bxh[6][4], bxl[6][4];
        #pragma unroll
        for (int ks = 0; ks < 6; ks++) {
            LDM_X4T(bxh[ks], smem_u32(&xhi_s[(ks*16 + xbrow)*PXPAD + xbcol]));
            LDM_X4T(bxl[ks], smem_u32(&xlo_s[(ks*16 + xbrow)*PXPAD + xbcol]));
        }
        __syncthreads();   // x area now reusable as attn staging

        #pragma unroll 1
        for (int h = 0; h < 3; h++) {
            // ---- GEMM: q, k, v for head h -> staging ----
            #pragma unroll 1
            for (int t = 0; t < 3; t++) {
                float acc[2][2][4];
                #pragma unroll
                for (int mt = 0; mt < 2; mt++)
                    #pragma unroll
                    for (int nl = 0; nl < 2; nl++)
                        #pragma unroll
                        for (int j = 0; j < 4; j++) acc[mt][nl][j] = 0.f;

                int wbase = t*96 + h*32;
                #pragma unroll 1
                for (int ks = 0; ks < 6; ks++) {
                    #pragma unroll
                    for (int mt = 0; mt < 2; mt++) {
                        int wr = (wbase + mt*16 + warow)*WPAD + ks*16 + wacol;
                        uint32_t awh[4], awl[4];
                        LDM_X4(awh, smem_u32(&whi_s[wr]));
                        MMA_BF16(acc[mt][0], awh, bxh[ks]);
                        MMA_BF16(acc[mt][0], awh, bxl[ks]);
                        MMA_BF16(acc[mt][1], awh, bxh[ks] + 2);
                        MMA_BF16(acc[mt][1], awh, bxl[ks] + 2);
                        LDM_X4(awl, smem_u32(&wlo_s[wr]));
                        MMA_BF16(acc[mt][0], awl, bxh[ks]);
                        MMA_BF16(acc[mt][1], awl, bxh[ks] + 2);
                    }
                }

                // epilogue: bias + hi/lo split -> staging [win][d][72], STS.32
                __nv_bfloat16* sth = stage + (t*2    )*9216;
                __nv_bfloat16* stl = stage + (t*2 + 1)*9216;
                #pragma unroll
                for (int mt = 0; mt < 2; mt++) {
                    int d0 = mt*16 + rrow;           // rows d0 and d0+8
                    float bb0, bb1;
                    if (t == 0)      { bb0 = bqk[h*32 + d0]*QSCALE;  bb1 = bqk[h*32 + d0 + 8]*QSCALE; }
                    else if (t == 1) { bb0 = bqk[96 + h*32 + d0];    bb1 = bqk[96 + h*32 + d0 + 8]; }
                    else             { bb0 = bv[h*32 + d0];          bb1 = bv[h*32 + d0 + 8]; }
                    #pragma unroll
                    for (int nl = 0; nl < 2; nl++) {
                        int m = mloc + nl*8;
                        float v0 = acc[mt][nl][0] + bb0;
                        float v1 = acc[mt][nl][1] + bb0;
                        float v2 = acc[mt][nl][2] + bb1;
                        float v3 = acc[mt][nl][3] + bb1;
                        __nv_bfloat16 e0 = __float2bfloat16_rn(v0);
                        __nv_bfloat16 e1 = __float2bfloat16_rn(v1);
                        __nv_bfloat16 e2 = __float2bfloat16_rn(v2);
                        __nv_bfloat16 e3 = __float2bfloat16_rn(v3);
                        *(uint32_t*)&sth[sbwin + d0*72 + m] =
                            ((uint32_t)__bfloat16_as_ushort(e1) << 16) | __bfloat16_as_ushort(e0);
                        *(uint32_t*)&sth[sbwin + (d0 + 8)*72 + m] =
                            ((uint32_t)__bfloat16_as_ushort(e3) << 16) | __bfloat16_as_ushort(e2);
                        *(uint32_t*)&stl[sbwin + d0*72 + m] =
                            packbf2(v0 - __bfloat162float(e0), v1 - __bfloat162float(e1));
                        *(uint32_t*)&stl[sbwin + (d0 + 8)*72 + m] =
                            packbf2(v2 - __bfloat162float(e2), v3 - __bfloat162float(e3));
                        if (t == 2) {
                            // exact fp32 V -> g_V (NCHW); px pair contiguous
                            int px = warp*16 + nl*8 + (lane & 3)*2;
                            int g = px & 63, winp = px >> 6;
                            int r = g >> 3, c = g & 7;
                            int gh = (wh*8 + r + 4) & 255;
                            int gw = ((ww0 + winp)*8 + c + 4) & 255;
                            size_t cb = (size_t)(b*96 + h*32);
                            *(float2*)&g_V[(cb + d0)*HW + gh*256 + gw]     = make_float2(v0, v1);
                            *(float2*)&g_V[(cb + d0 + 8)*HW + gh*256 + gw] = make_float2(v2, v3);
                        }
                    }
                }
            }
            __syncthreads();   // staging complete for head h

            // ---- attention for head h (proven R11 code) ----
            {
                const __nv_bfloat16* sqh = stage + 0*9216 + awin*2304;
                const __nv_bfloat16* sql = stage + 1*9216 + awin*2304;
                const __nv_bfloat16* skh = stage + 2*9216 + awin*2304;
                const __nv_bfloat16* skl = stage + 3*9216 + awin*2304;
                const __nv_bfloat16* svh = stage + 4*9216 + awin*2304;
                const __nv_bfloat16* svl = stage + 5*9216 + awin*2304;

                uint32_t aqh[2][4], aql[2][4];
                int krow2 = (quad >> 1)*8 + idx8;
                int apx2  = n0a + (quad & 1)*8;
                #pragma unroll
                for (int ks = 0; ks < 2; ks++) {
                    LDM_X4T(aqh[ks], smem_u32(&sqh[(ks*16 + krow2)*72 + apx2]));
                    LDM_X4T(aql[ks], smem_u32(&sql[(ks*16 + krow2)*72 + apx2]));
                }

                float accq[8][4];
                #pragma unroll
                for (int j = 0; j < 8; j++)
                    #pragma unroll
                    for (int r = 0; r < 4; r++) accq[j][r] = 0.f;

                {
                    int browt = (quad & 1)*8 + idx8;
                    int bcolt = (quad >> 1)*8;
                    #pragma unroll
                    for (int ks = 0; ks < 2; ks++) {
                        #pragma unroll
                        for (int jp = 0; jp < 4; jp++) {
                            uint32_t off = (ks*16 + browt)*72 + jp*16 + bcolt;
                            uint32_t bh[4], bl[4];
                            LDM_X4T(bh, smem_u32(&skh[off]));
                            MMA_BF16(accq[2*jp    ], aqh[ks], bh);
                            MMA_BF16(accq[2*jp    ], aql[ks], bh);
                            MMA_BF16(accq[2*jp + 1], aqh[ks], bh + 2);
                            MMA_BF16(accq[2*jp + 1], aql[ks], bh + 2);
                            LDM_X4T(bl, smem_u32(&skl[off]));
                            MMA_BF16(accq[2*jp    ], aqh[ks], bl);
                            MMA_BF16(accq[2*jp + 1], aqh[ks], bl + 2);
                        }
                    }
                }

                int ww_abs = ww0 + awin;
                bool masked = (wh == 31) || (ww_abs == 31);
                int n1 = n0a + (lane >> 2);
                int n2 = n1 + 8;
                int mq = (lane & 3)*2;
                int labn1 = 0, labn2 = 0;
                if (masked) { labn1 = swin_label(wh, ww_abs, n1); labn2 = swin_label(wh, ww_abs, n2); }

                const float* bb = g_bias + h*4096;
                float lsum1 = 0.f, lsum2 = 0.f;
                uint32_t pahi[4][4], palo[4][4];

                #pragma unroll
                for (int j = 0; j < 8; j++) {
                    int m0 = j*8 + mq;
                    float2 b1 = *(const float2*)&bb[n1*64 + m0];
                    float2 b2 = *(const float2*)&bb[n2*64 + m0];
                    float p0 = __expf(accq[j][0] + b1.x);
                    float p1 = __expf(accq[j][1] + b1.y);
                    float p2 = __expf(accq[j][2] + b2.x);
                    float p3 = __expf(accq[j][3] + b2.y);
                    if (masked) {
                        int lm0 = swin_label(wh, ww_abs, m0);
                        int lm1 = swin_label(wh, ww_abs, m0 + 1);
                        if (lm0 != labn1) p0 = 0.f;
                        if (lm1 != labn1) p1 = 0.f;
                        if (lm0 != labn2) p2 = 0.f;
                        if (lm1 != labn2) p3 = 0.f;
                    }
                    lsum1 += p0 + p1;
                    lsum2 += p2 + p3;
                    int s = j >> 1, half = (j & 1)*2;
                    __nv_bfloat16 e0 = __float2bfloat16_rn(p0);
                    __nv_bfloat16 e1 = __float2bfloat16_rn(p1);
                    __nv_bfloat16 e2 = __float2bfloat16_rn(p2);
                    __nv_bfloat16 e3 = __float2bfloat16_rn(p3);
                    pahi[s][half]     = ((uint32_t)__bfloat16_as_ushort(e1) << 16) | __bfloat16_as_ushort(e0);
                    pahi[s][half + 1] = ((uint32_t)__bfloat16_as_ushort(e3) << 16) | __bfloat16_as_ushort(e2);
                    palo[s][half]     = packbf2(p0 - __bfloat162float(e0), p1 - __bfloat162float(e1));
                    palo[s][half + 1] = packbf2(p2 - __bfloat162float(e2), p3 - __bfloat162float(e3));
                }
                lsum1 += __shfl_xor_sync(0xFFFFFFFF, lsum1, 1);
                lsum1 += __shfl_xor_sync(0xFFFFFFFF, lsum1, 2);
                lsum2 += __shfl_xor_sync(0xFFFFFFFF, lsum2, 1);
                lsum2 += __shfl_xor_sync(0xFFFFFFFF, lsum2, 2);
                float inv1 = 1.f / lsum1, inv2 = 1.f / lsum2;

                float o[4][4];
                #pragma unroll
                for (int t = 0; t < 4; t++)
                    #pragma unroll
                    for (int r = 0; r < 4; r++) o[t][r] = 0.f;

                {
                    int vrow = (quad >> 1)*8 + idx8;
                    int vcol = (quad & 1)*8;
                    #pragma unroll
                    for (int s = 0; s < 4; s++) {
                        #pragma unroll
                        for (int tp = 0; tp < 2; tp++) {
                            uint32_t off = (tp*16 + vrow)*72 + s*16 + vcol;
                            uint32_t bh[4], bl[4];
                            LDM_X4(bh, smem_u32(&svh[off]));
                            MMA_BF16(o[2*tp    ], pahi[s], bh);
                            MMA_BF16(o[2*tp    ], palo[s], bh);
                            MMA_BF16(o[2*tp + 1], pahi[s], bh + 2);
                            MMA_BF16(o[2*tp + 1], palo[s], bh + 2);
                            LDM_X4(bl, smem_u32(&svl[off]));
                            MMA_BF16(o[2*tp    ], pahi[s], bl);
                            MMA_BF16(o[2*tp + 1], pahi[s], bl + 2);
                        }
                    }
                }

                int r1 = n1 >> 3, c1 = n1 & 7;
                int r2 = n2 >> 3, c2 = n2 & 7;
                int off1 = (((wh << 3) + r1 + 4) & 255)*256 + (((ww_abs << 3) + c1 + 4) & 255);
                int off2 = (((wh << 3) + r2 + 4) & 255)*256 + (((ww_abs << 3) + c2 + 4) & 255);
                size_t cb = (size_t)(b*96 + h*32 + mq)*HW;
                #pragma unroll
                for (int t = 0; t < 4; t++) {
                    size_t cbase = cb + (size_t)(t*8)*HW;
                    g_att[cbase      + off1] = o[t][0]*inv1;
                    g_att[cbase + HW + off1] = o[t][1]*inv1;
                    g_att[cbase      + off2] = o[t][2]*inv2;
                    g_att[cbase + HW + off2] = o[t][3]*inv2;
                }
            }
            __syncthreads();   // staging free for next head
        }
    }
}

// ---------------- kernel DW: depthwise 5x5, vectorized halo -----------------
__global__ __launch_bounds__(256) void dw_kernel(const float* __restrict__ Wdw,
                                                 const float* __restrict__ bdw)
{
    __shared__ __align__(16) float s[36][44];
    __shared__ float wk[25];

    int blk  = blockIdx.x;
    int img  = blk >> 6;
    int tile = blk & 63;
    int c    = img % 96;
    int h0   = (tile >> 3) << 5, w0 = (tile & 7) << 5;
    int tid  = threadIdx.x;

    if (tid < 25) wk[tid] = Wdw[c*25 + tid];
    const float* vimg = g_V + (size_t)img * HW;

    bool border = (h0 == 0) || (h0 == 224) || (w0 == 0) || (w0 == 224);
    if (!border) {
        const float* src = vimg + (h0 - 2)*256 + (w0 - 4);
        for (int idx = tid; idx < 36*11; idx += 256) {
            int r = idx / 11, c4 = idx - r*11;
            *(float4*)&s[r][c4*4] = *(const float4*)&src[r*256 + c4*4];
        }
    } else {
        for (int idx = tid; idx < 36*44; idx += 256) {
            int r  = idx / 44, cc = idx % 44;
            int hh = h0 - 2 + r;  hh = (hh < 0) ? -hh : ((hh > 255) ? 510 - hh : hh);
            int wq = w0 - 4 + cc; wq = (wq < 0) ? -wq : ((wq > 255) ? 510 - wq : wq);
            s[r][cc] = vimg[hh*256 + wq];
        }
    }
    __syncthreads();

    int y   = tid >> 3;
    int xq0 = (tid & 7) * 4;
    float b0 = bdw[c];
    float acc[4] = {b0, b0, b0, b0};
    #pragma unroll
    for (int i = 0; i < 5; i++) {
        float4 fa = *(const float4*)&s[y + i][xq0];
        float4 fb = *(const float4*)&s[y + i][xq0 + 4];
        float4 fc = *(const float4*)&s[y + i][xq0 + 8];
        float f[12] = {fa.x, fa.y, fa.z, fa.w, fb.x, fb.y, fb.z, fb.w,
                       fc.x, fc.y, fc.z, fc.w};
        #pragma unroll
        for (int j = 0; j < 5; j++) {
            float wv = wk[i*5 + j];
            acc[0] = fmaf(f[j + 2], wv, acc[0]);
            acc[1] = fmaf(f[j + 3], wv, acc[1]);
            acc[2] = fmaf(f[j + 4], wv, acc[2]);
            acc[3] = fmaf(f[j + 5], wv, acc[3]);
        }
    }
    *(float4*)&g_conv[(size_t)img*HW + (h0 + y)*256 + (w0 + xq0)] =
        make_float4(acc[0], acc[1], acc[2], acc[3]);
}

// ---------------- kernel D: persistent HMMA final GEMM ----------------------
__global__ __launch_bounds__(512, 1) void final_mma_kernel(
    const float* __restrict__ bp, float* __restrict__ outp)
{
    extern __shared__ __align__(16) unsigned char dsm[];
    __nv_bfloat16* phi_s = (__nv_bfloat16*)dsm;
    __nv_bfloat16* plo_s = phi_s + 96*WPAD;
    __nv_bfloat16* xhi_s = plo_s + 96*WPAD;
    __nv_bfloat16* xlo_s = xhi_s + 96*PXPAD;
    float* out_s = (float*)xhi_s;

    int tid  = threadIdx.x;
    int warp = tid >> 5, lane = tid & 31;

    {
        const uint4* s1 = (const uint4*)g_Phi; uint4* d1 = (uint4*)phi_s;
        const uint4* s2 = (const uint4*)g_Plo; uint4* d2 = (uint4*)plo_s;
        #pragma unroll 4
        for (int i = tid; i < 96*WPAD*2/16; i += 512) { d1[i] = s1[i]; d2[i] = s2[i]; }
    }

    int idx8 = lane & 7, quad = lane >> 3;
    int krow = (quad >> 1)*8 + idx8;
    int apxb = warp*16 + (quad & 1)*8;
    int brow4 = lane & 7;
    int bcol4 = ((lane >> 3) & 1)*8;
    int brsel = (lane >> 4) & 1;
    int pq   = tid & 63;
    int p0   = pq*4;
    int c0   = tid >> 6;
    int orow = warp*16 + (lane >> 2);
    int oc   = (lane & 3)*2;

    for (int tile = blockIdx.x; tile < 1024; tile += gridDim.x) {
        int b   = tile >> 8;
        int hw0 = (tile & 255) << 8;

        __syncthreads();
        for (int idx = tid; idx < 96*64; idx += 512) {
            int k = idx >> 6, pg = idx & 63;
            size_t gi = (size_t)(b*96 + k)*HW + hw0 + pg*4;
            float4 a = *(const float4*)&g_conv[gi];
            float4 c4 = *(const float4*)&g_att[gi];
            float4 v = make_float4(a.x + c4.x, a.y + c4.y, a.z + c4.z, a.w + c4.w);
            __nv_bfloat16 h0 = __float2bfloat16_rn(v.x);
            __nv_bfloat16 h1 = __float2bfloat16_rn(v.y);
            __nv_bfloat16 h2 = __float2bfloat16_rn(v.z);
            __nv_bfloat16 h3 = __float2bfloat16_rn(v.w);
            uint32_t hp0 = (uint32_t)__bfloat16_as_ushort(h1) << 16 | __bfloat16_as_ushort(h0);
            uint32_t hp1 = (uint32_t)__bfloat16_as_ushort(h3) << 16 | __bfloat16_as_ushort(h2);
            uint32_t lp0 = packbf2(v.x - __bfloat162float(h0), v.y - __bfloat162float(h1));
            uint32_t lp1 = packbf2(v.z - __bfloat162float(h2), v.w - __bfloat162float(h3));
            *(uint2*)&xhi_s[k*PXPAD + pg*4] = make_uint2(hp0, hp1);
            *(uint2*)&xlo_s[k*PXPAD + pg*4] = make_uint2(lp0, lp1);
        }
        __syncthreads();

        uint32_t ahi[6][4], alo[6][4];
        #pragma unroll
        for (int ks = 0; ks < 6; ks++) {
            LDM_X4T(ahi[ks], smem_u32(&xhi_s[(ks*16 + krow)*PXPAD + apxb]));
            LDM_X4T(alo[ks], smem_u32(&xlo_s[(ks*16 + krow)*PXPAD + apxb]));
        }
        __syncthreads();

        float acc[12][4];
        #pragma unroll
        for (int nt = 0; nt < 12; nt++)
            #pragma unroll
            for (int j = 0; j < 4; j++) acc[nt][j] = 0.f;

        #pragma unroll 1
        for (int ks = 0; ks < 6; ks++) {
            #pragma unroll
            for (int ntp = 0; ntp < 6; ntp++) {
                int wrow = ((2*ntp + brsel)*8 + brow4)*WPAD + ks*16 + bcol4;
                uint32_t bh[4], bl[4];
                LDM_X4(bh, smem_u32(&phi_s[wrow]));
                MMA_BF16(acc[2*ntp    ], ahi[ks], bh);
                MMA_BF16(acc[2*ntp    ], alo[ks], bh);
                MMA_BF16(acc[2*ntp + 1], ahi[ks], bh + 2);
                MMA_BF16(acc[2*ntp + 1], alo[ks], bh + 2);
                LDM_X4(bl, smem_u32(&plo_s[wrow]));
                MMA_BF16(acc[2*ntp    ], ahi[ks], bl);
                MMA_BF16(acc[2*ntp + 1], ahi[ks], bl + 2);
            }
        }

        #pragma unroll
        for (int nt = 0; nt < 12; nt++) {
            out_s[(nt*8 + oc    )*264 + orow    ] = acc[nt][0];
            out_s[(nt*8 + oc + 1)*264 + orow    ] = acc[nt][1];
            out_s[(nt*8 + oc    )*264 + orow + 8] = acc[nt][2];
            out_s[(nt*8 + oc + 1)*264 + orow + 8] = acc[nt][3];
        }
        __syncthreads();

        #pragma unroll 1
        for (int j = 0; j < 12; j++) {
            int c = c0 + j*8;
            float4 v4 = *(const float4*)&out_s[c*264 + p0];
            float bo = bp[c];
            *(float4*)&outp[(size_t)(b*96 + c)*HW + hw0 + p0] =
                make_float4(v4.x + bo, v4.y + bo, v4.z + bo, v4.w + bo);
        }
        __syncthreads();
    }
}

// ---------------- launch ------------------------------------------------------
extern "C" void kernel_launch(void* const* d_in, const int* in_sizes, int n_in,
                              void* d_out, int out_size)
{
    const float* x   = (const float*)d_in[0];
    const float* Wv  = (const float*)d_in[1];
    const float* bv  = (const float*)d_in[2];
    const float* Wqk = (const float*)d_in[3];
    const float* bqk = (const float*)d_in[4];
    const float* Wm1 = (const float*)d_in[5];
    const float* bm1 = (const float*)d_in[6];
    const float* Wm2 = (const float*)d_in[7];
    const float* bm2 = (const float*)d_in[8];
    const float* Wdw = (const float*)d_in[9];
    const float* bdw = (const float*)d_in[10];
    const float* Wp  = (const float*)d_in[11];
    const float* bp  = (const float*)d_in[12];
    float* outp = (float*)d_out;

    const int FUSED_SMEM = 288*WPAD*2*2 + 6*9216*2;        // 230400 B
    const int FIN_SMEM   = 96*WPAD*2*2 + 96*PXPAD*2*2;
    cudaFuncSetAttribute(fused_kernel,
                         cudaFuncAttributeMaxDynamicSharedMemorySize, FUSED_SMEM);
    cudaFuncSetAttribute(final_mma_kernel,
                         cudaFuncAttributeMaxDynamicSharedMemorySize, FIN_SMEM);

    prepbias_kernel<<<172, 256>>>(Wqk, Wv, Wp, Wm1, bm1, Wm2, bm2);
    fused_kernel   <<<148, 512, FUSED_SMEM>>>(x, bqk, bv);
    dw_kernel      <<<24576, 256>>>(Wdw, bdw);
    final_mma_kernel<<<148, 512, FIN_SMEM>>>(bp, outp);   // profiled slot 4
}

// round 15
// speedup vs baseline: 2.2549x; 1.0228x over previous
#include <cuda_runtime.h>
#include <cuda_bf16.h>
#include <math.h>
#include <cstdint>

#define BATCH 4
#define CH    96
#define HRES  256
#define WRES  256
#define HW    65536
#define HEADS 3
#define QSCALE 0.17677669529663687f
#define WPAD  104
#define PXPAD 264
#define PX2   136   // final kernel x staging stride (128 px + 8)
#define OUT2  132   // final kernel out staging stride (floats)

// ---------------- mma.sync / ldmatrix helpers (sm_80+ PTX) ------------------
#define LDM_X4(r, addr) \
    asm volatile("ldmatrix.sync.aligned.m8n8.x4.shared.b16 {%0,%1,%2,%3}, [%4];" \
        : "=r"((r)[0]), "=r"((r)[1]), "=r"((r)[2]), "=r"((r)[3]) : "r"(addr))
#define LDM_X4T(r, addr) \
    asm volatile("ldmatrix.sync.aligned.m8n8.x4.trans.shared.b16 {%0,%1,%2,%3}, [%4];" \
        : "=r"((r)[0]), "=r"((r)[1]), "=r"((r)[2]), "=r"((r)[3]) : "r"(addr))
#define MMA_BF16(d, a, b) \
    asm volatile("mma.sync.aligned.m16n8k16.row.col.f32.bf16.bf16.f32 " \
        "{%0,%1,%2,%3}, {%4,%5,%6,%7}, {%8,%9}, {%0,%1,%2,%3};" \
        : "+f"((d)[0]), "+f"((d)[1]), "+f"((d)[2]), "+f"((d)[3]) \
        : "r"((a)[0]), "r"((a)[1]), "r"((a)[2]), "r"((a)[3]), \
          "r"((b)[0]), "r"((b)[1]))

__device__ __forceinline__ uint32_t smem_u32(const void* p) {
    uint32_t a;
    asm("{ .reg .u64 t; cvta.to.shared.u64 t, %1; cvt.u32.u64 %0, t; }"
        : "=r"(a) : "l"(p));
    return a;
}
__device__ __forceinline__ uint32_t packbf2(float x, float y) {
    __nv_bfloat16 bx = __float2bfloat16_rn(x);
    __nv_bfloat16 by = __float2bfloat16_rn(y);
    return ((uint32_t)__bfloat16_as_ushort(by) << 16) | __bfloat16_as_ushort(bx);
}

// ---------------- scratch ----------------------------------------------------
__device__ float g_V   [BATCH*CH*HW];
__device__ float g_conv[BATCH*CH*HW];
__device__ float g_att [BATCH*CH*HW];
__device__ float g_bias[HEADS*64*64];
__device__ __align__(16) __nv_bfloat16 g_Whi[288*WPAD];
__device__ __align__(16) __nv_bfloat16 g_Wlo[288*WPAD];
__device__ __align__(16) __nv_bfloat16 g_Phi[96*WPAD];
__device__ __align__(16) __nv_bfloat16 g_Plo[96*WPAD];

// ---------------- prep kernels ------------------------------------------------
__device__ __forceinline__ float wval(const float* Wqk, const float* Wv,
                                      int o, int k) {
    if (k >= 96) return 0.f;
    if (o < 96)       return Wqk[o*96 + k] * QSCALE;
    else if (o < 192) return Wqk[o*96 + k];
    else              return Wv[(o - 192)*96 + k];
}
__global__ void prepW_kernel(
    const float* __restrict__ Wqk, const float* __restrict__ Wv,
    const float* __restrict__ Wp)
{
    int blk = blockIdx.x, tid = threadIdx.x;
    if (blk < 117) {
        int idx = blk*256 + tid;
        if (idx >= 288*WPAD) return;
        float w = wval(Wqk, Wv, idx / WPAD, idx % WPAD);
        __nv_bfloat16 hi = __float2bfloat16_rn(w);
        g_Whi[idx] = hi;
        g_Wlo[idx] = __float2bfloat16_rn(w - __bfloat162float(hi));
    } else {
        int idx = (blk - 117)*256 + tid;
        if (idx >= 96*WPAD) return;
        int o = idx / WPAD, k = idx % WPAD;
        float w = (k < 96) ? Wp[o*96 + k] : 0.f;
        __nv_bfloat16 hi = __float2bfloat16_rn(w);
        g_Phi[idx] = hi;
        g_Plo[idx] = __float2bfloat16_rn(w - __bfloat162float(hi));
    }
}
__global__ void prepBias_kernel(
    const float* __restrict__ Wm1, const float* __restrict__ bm1,
    const float* __restrict__ Wm2, const float* __restrict__ bm2)
{
    int gid = blockIdx.x*256 + threadIdx.x;
    int n = gid >> 6, m = gid & 63;
    float r0 = (float)((n >> 3) - (m >> 3));
    float r1 = (float)((n & 7)  - (m & 7));
    r0 = copysignf(log1pf(fabsf(r0)), r0);
    r1 = copysignf(log1pf(fabsf(r1)), r1);
    float a0 = bm2[0], a1 = bm2[1], a2 = bm2[2];
    for (int j = 0; j < 256; j++) {
        float h = fmaf(r0, Wm1[j], fmaf(r1, Wm1[256 + j], bm1[j]));
        h = fmaxf(h, 0.f);
        a0 = fmaf(h, Wm2[j*3 + 0], a0);
        a1 = fmaf(h, Wm2[j*3 + 1], a1);
        a2 = fmaf(h, Wm2[j*3 + 2], a2);
    }
    g_bias[0*4096 + gid] = a0;
    g_bias[1*4096 + gid] = a1;
    g_bias[2*4096 + gid] = a2;
}

__device__ __forceinline__ int swin_label(int wh, int ww, int idx) {
    int rh = (wh == 31) ? (1 + (((idx >> 3) >= 4) ? 1 : 0)) : 0;
    int rw = (ww == 31) ? (1 + (((idx & 7)  >= 4) ? 1 : 0)) : 0;
    return rh*3 + rw;
}

// ---------------- FUSED: QKV GEMM (A=W, B=x) + windowed attention -----------
__global__ __launch_bounds__(512, 1) void fused_kernel(
    const float* __restrict__ x,
    const float* __restrict__ bqk, const float* __restrict__ bv)
{
    extern __shared__ __align__(16) unsigned char dsm[];
    __nv_bfloat16* whi_s = (__nv_bfloat16*)dsm;
    __nv_bfloat16* wlo_s = whi_s + 288*WPAD;
    __nv_bfloat16* stage = wlo_s + 288*WPAD;
    __nv_bfloat16* xhi_s = stage;
    __nv_bfloat16* xlo_s = stage + 96*PXPAD;

    int tid  = threadIdx.x;
    int warp = tid >> 5, lane = tid & 31;

    {
        const uint4* s1 = (const uint4*)g_Whi; uint4* d1 = (uint4*)whi_s;
        const uint4* s2 = (const uint4*)g_Wlo; uint4* d2 = (uint4*)wlo_s;
        #pragma unroll 4
        for (int i = tid; i < 288*WPAD*2/16; i += 512) { d1[i] = s1[i]; d2[i] = s2[i]; }
    }

    int idx8 = lane & 7, quad = lane >> 3;
    int xbrow = (quad & 1)*8 + idx8;
    int xbcol = warp*16 + (quad >> 1)*8;
    int warow = (quad & 1)*8 + idx8;
    int wacol = (quad >> 1)*8;
    int rrow  = lane >> 2;
    int mloc  = (warp & 3)*16 + (lane & 3)*2;
    int sbwin = (warp >> 2)*2304;
    int awin = warp >> 2;
    int n0a  = (warp & 3)*16;

    for (int tile = blockIdx.x; tile < 1024; tile += gridDim.x) {
        int b   = tile >> 8;
        int rem = tile & 255;
        int wh  = rem >> 3;
        int ww0 = (rem & 7)*4;

        __syncthreads();
        for (int idx = tid; idx < 96*64; idx += 512) {
            int k = idx >> 6, g = idx & 63;
            int r = g >> 3, q = g & 7;
            int win = q >> 1, c0 = (q & 1)*4;
            int gh = (wh*8 + r + 4) & 255;
            int gw = ((ww0 + win)*8 + c0 + 4) & 255;
            float4 v = *(const float4*)&x[(size_t)(b*96 + k)*HW + gh*256 + gw];
            int px0 = win*64 + r*8 + c0;
            __nv_bfloat16 h0 = __float2bfloat16_rn(v.x);
            __nv_bfloat16 h1 = __float2bfloat16_rn(v.y);
            __nv_bfloat16 h2 = __float2bfloat16_rn(v.z);
            __nv_bfloat16 h3 = __float2bfloat16_rn(v.w);
            uint32_t hp0 = (uint32_t)__bfloat16_as_ushort(h1) << 16 | __bfloat16_as_ushort(h0);
            uint32_t hp1 = (uint32_t)__bfloat16_as_ushort(h3) << 16 | __bfloat16_as_ushort(h2);
            uint32_t lp0 = packbf2(v.x - __bfloat162float(h0), v.y - __bfloat162float(h1));
            uint32_t lp1 = packbf2(v.z - __bfloat162float(h2), v.w - __bfloat162float(h3));
            *(uint2*)&xhi_s[k*PXPAD + px0] = make_uint2(hp0, hp1);
            *(uint2*)&xlo_s[k*PXPAD + px0] = make_uint2(lp0, lp1);
        }
        __syncthreads();

        uint32_t bxh[6][4], bxl[6][4];
        #pragma unroll
        for (int ks = 0; ks < 6; ks++) {
            LDM_X4T(bxh[ks], smem_u32(&xhi_s[(ks*16 + xbrow)*PXPAD + xbcol]));
            LDM_X4T(bxl[ks], smem_u32(&xlo_s[(ks*16 + xbrow)*PXPAD + xbcol]));
        }
        __syncthreads();

        #pragma unroll 1
        for (int h = 0; h < 3; h++) {
            #pragma unroll 1
            for (int t = 0; t < 3; t++) {
                float acc[2][2][4];
                #pragma unroll
                for (int mt = 0; mt < 2; mt++)
                    #pragma unroll
                    for (int nl = 0; nl < 2; nl++)
                        #pragma unroll
                        for (int j = 0; j < 4; j++) acc[mt][nl][j] = 0.f;

                int wbase = t*96 + h*32;
                #pragma unroll 1
                for (int ks = 0; ks < 6; ks++) {
                    #pragma unroll
                    for (int mt = 0; mt < 2; mt++) {
                        int wr = (wbase + mt*16 + warow)*WPAD + ks*16 + wacol;
                        uint32_t awh[4], awl[4];
                        LDM_X4(awh, smem_u32(&whi_s[wr]));
                        MMA_BF16(acc[mt][0], awh, bxh[ks]);
                        MMA_BF16(acc[mt][0], awh, bxl[ks]);
                        MMA_BF16(acc[mt][1], awh, bxh[ks] + 2);
                        MMA_BF16(acc[mt][1], awh, bxl[ks] + 2);
                        LDM_X4(awl, smem_u32(&wlo_s[wr]));
                        MMA_BF16(acc[mt][0], awl, bxh[ks]);
                        MMA_BF16(acc[mt][1], awl, bxh[ks] + 2);
                    }
                }

                __nv_bfloat16* sth = stage + (t*2    )*9216;
                __nv_bfloat16* stl = stage + (t*2 + 1)*9216;
                #pragma unroll
                for (int mt = 0; mt < 2; mt++) {
                    int d0 = mt*16 + rrow;
                    float bb0, bb1;
                    if (t == 0)      { bb0 = bqk[h*32 + d0]*QSCALE;  bb1 = bqk[h*32 + d0 + 8]*QSCALE; }
                    else if (t == 1) { bb0 = bqk[96 + h*32 + d0];    bb1 = bqk[96 + h*32 + d0 + 8]; }
                    else             { bb0 = bv[h*32 + d0];          bb1 = bv[h*32 + d0 + 8]; }
                    #pragma unroll
                    for (int nl = 0; nl < 2; nl++) {
                        int m = mloc + nl*8;
                        float v0 = acc[mt][nl][0] + bb0;
                        float v1 = acc[mt][nl][1] + bb0;
                        float v2 = acc[mt][nl][2] + bb1;
                        float v3 = acc[mt][nl][3] + bb1;
                        __nv_bfloat16 e0 = __float2bfloat16_rn(v0);
                        __nv_bfloat16 e1 = __float2bfloat16_rn(v1);
                        __nv_bfloat16 e2 = __float2bfloat16_rn(v2);
                        __nv_bfloat16 e3 = __float2bfloat16_rn(v3);
                        *(uint32_t*)&sth[sbwin + d0*72 + m] =
                            ((uint32_t)__bfloat16_as_ushort(e1) << 16) | __bfloat16_as_ushort(e0);
                        *(uint32_t*)&sth[sbwin + (d0 + 8)*72 + m] =
                            ((uint32_t)__bfloat16_as_ushort(e3) << 16) | __bfloat16_as_ushort(e2);
                        *(uint32_t*)&stl[sbwin + d0*72 + m] =
                            packbf2(v0 - __bfloat162float(e0), v1 - __bfloat162float(e1));
                        *(uint32_t*)&stl[sbwin + (d0 + 8)*72 + m] =
                            packbf2(v2 - __bfloat162float(e2), v3 - __bfloat162float(e3));
                        if (t == 2) {
                            int px = warp*16 + nl*8 + (lane & 3)*2;
                            int g = px & 63, winp = px >> 6;
                            int r = g >> 3, c = g & 7;
                            int gh = (wh*8 + r + 4) & 255;
                            int gw = ((ww0 + winp)*8 + c + 4) & 255;
                            size_t cb = (size_t)(b*96 + h*32);
                            *(float2*)&g_V[(cb + d0)*HW + gh*256 + gw]     = make_float2(v0, v1);
                            *(float2*)&g_V[(cb + d0 + 8)*HW + gh*256 + gw] = make_float2(v2, v3);
                        }
                    }
                }
            }
            __syncthreads();

            {
                const __nv_bfloat16* sqh = stage + 0*9216 + awin*2304;
                const __nv_bfloat16* sql = stage + 1*9216 + awin*2304;
                const __nv_bfloat16* skh = stage + 2*9216 + awin*2304;
                const __nv_bfloat16* skl = stage + 3*9216 + awin*2304;
                const __nv_bfloat16* svh = stage + 4*9216 + awin*2304;
                const __nv_bfloat16* svl = stage + 5*9216 + awin*2304;

                uint32_t aqh[2][4], aql[2][4];
                int krow2 = (quad >> 1)*8 + idx8;
                int apx2  = n0a + (quad & 1)*8;
                #pragma unroll
                for (int ks = 0; ks < 2; ks++) {
                    LDM_X4T(aqh[ks], smem_u32(&sqh[(ks*16 + krow2)*72 + apx2]));
                    LDM_X4T(aql[ks], smem_u32(&sql[(ks*16 + krow2)*72 + apx2]));
                }

                float accq[8][4];
                #pragma unroll
                for (int j = 0; j < 8; j++)
                    #pragma unroll
                    for (int r = 0; r < 4; r++) accq[j][r] = 0.f;

                {
                    int browt = (quad & 1)*8 + idx8;
                    int bcolt = (quad >> 1)*8;
                    #pragma unroll
                    for (int ks = 0; ks < 2; ks++) {
                        #pragma unroll
                        for (int jp = 0; jp < 4; jp++) {
                            uint32_t off = (ks*16 + browt)*72 + jp*16 + bcolt;
                            uint32_t bh[4], bl[4];
                            LDM_X4T(bh, smem_u32(&skh[off]));
                            MMA_BF16(accq[2*jp    ], aqh[ks], bh);
                            MMA_BF16(accq[2*jp    ], aql[ks], bh);
                            MMA_BF16(accq[2*jp + 1], aqh[ks], bh + 2);
                            MMA_BF16(accq[2*jp + 1], aql[ks], bh + 2);
                            LDM_X4T(bl, smem_u32(&skl[off]));
                            MMA_BF16(accq[2*jp    ], aqh[ks], bl);
                            MMA_BF16(accq[2*jp + 1], aqh[ks], bl + 2);
                        }
                    }
                }

                int ww_abs = ww0 + awin;
                bool masked = (wh == 31) || (ww_abs == 31);
                int n1 = n0a + (lane >> 2);
                int n2 = n1 + 8;
                int mq = (lane & 3)*2;
                int labn1 = 0, labn2 = 0;
                if (masked) { labn1 = swin_label(wh, ww_abs, n1); labn2 = swin_label(wh, ww_abs, n2); }

                const float* bb = g_bias + h*4096;
                float lsum1 = 0.f, lsum2 = 0.f;
                uint32_t pahi[4][4], palo[4][4];

                #pragma unroll
                for (int j = 0; j < 8; j++) {
                    int m0 = j*8 + mq;
                    float2 b1 = *(const float2*)&bb[n1*64 + m0];
                    float2 b2 = *(const float2*)&bb[n2*64 + m0];
                    float p0 = __expf(accq[j][0] + b1.x);
                    float p1 = __expf(accq[j][1] + b1.y);
                    float p2 = __expf(accq[j][2] + b2.x);
                    float p3 = __expf(accq[j][3] + b2.y);
                    if (masked) {
                        int lm0 = swin_label(wh, ww_abs, m0);
                        int lm1 = swin_label(wh, ww_abs, m0 + 1);
                        if (lm0 != labn1) p0 = 0.f;
                        if (lm1 != labn1) p1 = 0.f;
                        if (lm0 != labn2) p2 = 0.f;
                        if (lm1 != labn2) p3 = 0.f;
                    }
                    lsum1 += p0 + p1;
                    lsum2 += p2 + p3;
                    int s = j >> 1, half = (j & 1)*2;
                    __nv_bfloat16 e0 = __float2bfloat16_rn(p0);
                    __nv_bfloat16 e1 = __float2bfloat16_rn(p1);
                    __nv_bfloat16 e2 = __float2bfloat16_rn(p2);
                    __nv_bfloat16 e3 = __float2bfloat16_rn(p3);
                    pahi[s][half]     = ((uint32_t)__bfloat16_as_ushort(e1) << 16) | __bfloat16_as_ushort(e0);
                    pahi[s][half + 1] = ((uint32_t)__bfloat16_as_ushort(e3) << 16) | __bfloat16_as_ushort(e2);
                    palo[s][half]     = packbf2(p0 - __bfloat162float(e0), p1 - __bfloat162float(e1));
                    palo[s][half + 1] = packbf2(p2 - __bfloat162float(e2), p3 - __bfloat162float(e3));
                }
                lsum1 += __shfl_xor_sync(0xFFFFFFFF, lsum1, 1);
                lsum1 += __shfl_xor_sync(0xFFFFFFFF, lsum1, 2);
                lsum2 += __shfl_xor_sync(0xFFFFFFFF, lsum2, 1);
                lsum2 += __shfl_xor_sync(0xFFFFFFFF, lsum2, 2);
                float inv1 = 1.f / lsum1, inv2 = 1.f / lsum2;

                float o[4][4];
                #pragma unroll
                for (int t = 0; t < 4; t++)
                    #pragma unroll
                    for (int r = 0; r < 4; r++) o[t][r] = 0.f;

                {
                    int vrow = (quad >> 1)*8 + idx8;
                    int vcol = (quad & 1)*8;
                    #pragma unroll
                    for (int s = 0; s < 4; s++) {
                        #pragma unroll
                        for (int tp = 0; tp < 2; tp++) {
                            uint32_t off = (tp*16 + vrow)*72 + s*16 + vcol;
                            uint32_t bh[4], bl[4];
                            LDM_X4(bh, smem_u32(&svh[off]));
                            MMA_BF16(o[2*tp    ], pahi[s], bh);
                            MMA_BF16(o[2*tp    ], palo[s], bh);
                            MMA_BF16(o[2*tp + 1], pahi[s], bh + 2);
                            MMA_BF16(o[2*tp + 1], palo[s], bh + 2);
                            LDM_X4(bl, smem_u32(&svl[off]));
                            MMA_BF16(o[2*tp    ], pahi[s], bl);
                            MMA_BF16(o[2*tp + 1], pahi[s], bl + 2);
                        }
                    }
                }

                int r1 = n1 >> 3, c1 = n1 & 7;
                int r2 = n2 >> 3, c2 = n2 & 7;
                int off1 = (((wh << 3) + r1 + 4) & 255)*256 + (((ww_abs << 3) + c1 + 4) & 255);
                int off2 = (((wh << 3) + r2 + 4) & 255)*256 + (((ww_abs << 3) + c2 + 4) & 255);
                size_t cb = (size_t)(b*96 + h*32 + mq)*HW;
                #pragma unroll
                for (int t = 0; t < 4; t++) {
                    size_t cbase = cb + (size_t)(t*8)*HW;
                    g_att[cbase      + off1] = o[t][0]*inv1;
                    g_att[cbase + HW + off1] = o[t][1]*inv1;
                    g_att[cbase      + off2] = o[t][2]*inv2;
                    g_att[cbase + HW + off2] = o[t][3]*inv2;
                }
            }
            __syncthreads();
        }
    }
}

// ---------------- kernel DW: depthwise 5x5, vectorized halo -----------------
__global__ __launch_bounds__(256) void dw_kernel(const float* __restrict__ Wdw,
                                                 const float* __restrict__ bdw)
{
    __shared__ __align__(16) float s[36][44];
    __shared__ float wk[25];

    int blk  = blockIdx.x;
    int img  = blk >> 6;
    int tile = blk & 63;
    int c    = img % 96;
    int h0   = (tile >> 3) << 5, w0 = (tile & 7) << 5;
    int tid  = threadIdx.x;

    if (tid < 25) wk[tid] = Wdw[c*25 + tid];
    const float* vimg = g_V + (size_t)img * HW;

    bool border = (h0 == 0) || (h0 == 224) || (w0 == 0) || (w0 == 224);
    if (!border) {
        const float* src = vimg + (h0 - 2)*256 + (w0 - 4);
        for (int idx = tid; idx < 36*11; idx += 256) {
            int r = idx / 11, c4 = idx - r*11;
            *(float4*)&s[r][c4*4] = *(const float4*)&src[r*256 + c4*4];
        }
    } else {
        for (int idx = tid; idx < 36*44; idx += 256) {
            int r  = idx / 44, cc = idx % 44;
            int hh = h0 - 2 + r;  hh = (hh < 0) ? -hh : ((hh > 255) ? 510 - hh : hh);
            int wq = w0 - 4 + cc; wq = (wq < 0) ? -wq : ((wq > 255) ? 510 - wq : wq);
            s[r][cc] = vimg[hh*256 + wq];
        }
    }
    __syncthreads();

    int y   = tid >> 3;
    int xq0 = (tid & 7) * 4;
    float b0 = bdw[c];
    float acc[4] = {b0, b0, b0, b0};
    #pragma unroll
    for (int i = 0; i < 5; i++) {
        float4 fa = *(const float4*)&s[y + i][xq0];
        float4 fb = *(const float4*)&s[y + i][xq0 + 4];
        float4 fc = *(const float4*)&s[y + i][xq0 + 8];
        float f[12] = {fa.x, fa.y, fa.z, fa.w, fb.x, fb.y, fb.z, fb.w,
                       fc.x, fc.y, fc.z, fc.w};
        #pragma unroll
        for (int j = 0; j < 5; j++) {
            float wv = wk[i*5 + j];
            acc[0] = fmaf(f[j + 2], wv, acc[0]);
            acc[1] = fmaf(f[j + 3], wv, acc[1]);
            acc[2] = fmaf(f[j + 4], wv, acc[2]);
            acc[3] = fmaf(f[j + 5], wv, acc[3]);
        }
    }
    *(float4*)&g_conv[(size_t)img*HW + (h0 + y)*256 + (w0 + xq0)] =
        make_float4(acc[0], acc[1], acc[2], acc[3]);
}

// ---------------- kernel D: HMMA final GEMM, 2 blocks/SM ---------------------
__global__ __launch_bounds__(256, 2) void final_mma_kernel(
    const float* __restrict__ bp, float* __restrict__ outp)
{
    extern __shared__ __align__(16) unsigned char dsm[];
    __nv_bfloat16* phi_s = (__nv_bfloat16*)dsm;
    __nv_bfloat16* plo_s = phi_s + 96*WPAD;
    __nv_bfloat16* xhi_s = plo_s + 96*WPAD;
    __nv_bfloat16* xlo_s = xhi_s + 96*PX2;
    float* out_s = (float*)xhi_s;

    int tid  = threadIdx.x;
    int warp = tid >> 5, lane = tid & 31;

    {
        const uint4* s1 = (const uint4*)g_Phi; uint4* d1 = (uint4*)phi_s;
        const uint4* s2 = (const uint4*)g_Plo; uint4* d2 = (uint4*)plo_s;
        #pragma unroll 4
        for (int i = tid; i < 96*WPAD*2/16; i += 256) { d1[i] = s1[i]; d2[i] = s2[i]; }
    }

    int idx8 = lane & 7, quad = lane >> 3;
    int krow = (quad >> 1)*8 + idx8;
    int apxb = warp*16 + (quad & 1)*8;
    int brow4 = lane & 7;
    int bcol4 = ((lane >> 3) & 1)*8;
    int brsel = (lane >> 4) & 1;
    int pq   = tid & 31;
    int p0   = pq*4;
    int c0   = tid >> 5;
    int orow = warp*16 + (lane >> 2);
    int oc   = (lane & 3)*2;

    for (int tile = blockIdx.x; tile < 2048; tile += gridDim.x) {
        int b   = tile >> 9;
        int hw0 = (tile & 511) << 7;   // 128 px

        __syncthreads();
        for (int idx = tid; idx < 96*32; idx += 256) {
            int k = idx >> 5, pg = idx & 31;
            size_t gi = (size_t)(b*96 + k)*HW + hw0 + pg*4;
            float4 a = *(const float4*)&g_conv[gi];
            float4 c4 = *(const float4*)&g_att[gi];
            float4 v = make_float4(a.x + c4.x, a.y + c4.y, a.z + c4.z, a.w + c4.w);
            __nv_bfloat16 h0 = __float2bfloat16_rn(v.x);
            __nv_bfloat16 h1 = __float2bfloat16_rn(v.y);
            __nv_bfloat16 h2 = __float2bfloat16_rn(v.z);
            __nv_bfloat16 h3 = __float2bfloat16_rn(v.w);
            uint32_t hp0 = (uint32_t)__bfloat16_as_ushort(h1) << 16 | __bfloat16_as_ushort(h0);
            uint32_t hp1 = (uint32_t)__bfloat16_as_ushort(h3) << 16 | __bfloat16_as_ushort(h2);
            uint32_t lp0 = packbf2(v.x - __bfloat162float(h0), v.y - __bfloat162float(h1));
            uint32_t lp1 = packbf2(v.z - __bfloat162float(h2), v.w - __bfloat162float(h3));
            *(uint2*)&xhi_s[k*PX2 + pg*4] = make_uint2(hp0, hp1);
            *(uint2*)&xlo_s[k*PX2 + pg*4] = make_uint2(lp0, lp1);
        }
        __syncthreads();

        uint32_t ahi[6][4], alo[6][4];
        #pragma unroll
        for (int ks = 0; ks < 6; ks++) {
            LDM_X4T(ahi[ks], smem_u32(&xhi_s[(ks*16 + krow)*PX2 + apxb]));
            LDM_X4T(alo[ks], smem_u32(&xlo_s[(ks*16 + krow)*PX2 + apxb]));
        }
        __syncthreads();

        float acc[12][4];
        #pragma unroll
        for (int nt = 0; nt < 12; nt++)
            #pragma unroll
            for (int j = 0; j < 4; j++) acc[nt][j] = 0.f;

        #pragma unroll 1
        for (int ks = 0; ks < 6; ks++) {
            #pragma unroll
            for (int ntp = 0; ntp < 6; ntp++) {
                int wrow = ((2*ntp + brsel)*8 + brow4)*WPAD + ks*16 + bcol4;
                uint32_t bh[4], bl[4];
                LDM_X4(bh, smem_u32(&phi_s[wrow]));
                MMA_BF16(acc[2*ntp    ], ahi[ks], bh);
                MMA_BF16(acc[2*ntp    ], alo[ks], bh);
                MMA_BF16(acc[2*ntp + 1], ahi[ks], bh + 2);
                MMA_BF16(acc[2*ntp + 1], alo[ks], bh + 2);
                LDM_X4(bl, smem_u32(&plo_s[wrow]));
                MMA_BF16(acc[2*ntp    ], ahi[ks], bl);
                MMA_BF16(acc[2*ntp + 1], ahi[ks], bl + 2);
            }
        }

        #pragma unroll
        for (int nt = 0; nt < 12; nt++) {
            out_s[(nt*8 + oc    )*OUT2 + orow    ] = acc[nt][0];
            out_s[(nt*8 + oc + 1)*OUT2 + orow    ] = acc[nt][1];
            out_s[(nt*8 + oc    )*OUT2 + orow + 8] = acc[nt][2];
            out_s[(nt*8 + oc + 1)*OUT2 + orow + 8] = acc[nt][3];
        }
        __syncthreads();

        #pragma unroll 1
        for (int j = 0; j < 12; j++) {
            int c = c0 + j*8;
            float4 v4 = *(const float4*)&out_s[c*OUT2 + p0];
            float bo = bp[c];
            *(float4*)&outp[(size_t)(b*96 + c)*HW + hw0 + p0] =
                make_float4(v4.x + bo, v4.y + bo, v4.z + bo, v4.w + bo);
        }
        __syncthreads();
    }
}

// ---------------- launch ------------------------------------------------------
extern "C" void kernel_launch(void* const* d_in, const int* in_sizes, int n_in,
                              void* d_out, int out_size)
{
    const float* x   = (const float*)d_in[0];
    const float* Wv  = (const float*)d_in[1];
    const float* bv  = (const float*)d_in[2];
    const float* Wqk = (const float*)d_in[3];
    const float* bqk = (const float*)d_in[4];
    const float* Wm1 = (const float*)d_in[5];
    const float* bm1 = (const float*)d_in[6];
    const float* Wm2 = (const float*)d_in[7];
    const float* bm2 = (const float*)d_in[8];
    const float* Wdw = (const float*)d_in[9];
    const float* bdw = (const float*)d_in[10];
    const float* Wp  = (const float*)d_in[11];
    const float* bp  = (const float*)d_in[12];
    float* outp = (float*)d_out;

    const int FUSED_SMEM = 288*WPAD*2*2 + 6*9216*2;            // 230400 B
    const int FIN_SMEM   = 96*WPAD*2*2 + 96*PX2*2*2;           // 92160 B
    cudaFuncSetAttribute(fused_kernel,
                         cudaFuncAttributeMaxDynamicSharedMemorySize, FUSED_SMEM);
    cudaFuncSetAttribute(final_mma_kernel,
                         cudaFuncAttributeMaxDynamicSharedMemorySize, FIN_SMEM);

    prepW_kernel   <<<156, 256>>>(Wqk, Wv, Wp);
    prepBias_kernel<<<16, 256>>>(Wm1, bm1, Wm2, bm2);
    fused_kernel   <<<148, 512, FUSED_SMEM>>>(x, bqk, bv);
    dw_kernel      <<<24576, 256>>>(Wdw, bdw);               // profiled slot 4
    final_mma_kernel<<<296, 256, FIN_SMEM>>>(bp, outp);
}

// round 17
// speedup vs baseline: 2.3248x; 1.0310x over previous
#include <cuda_runtime.h>
#include <cuda_bf16.h>
#include <math.h>
#include <cstdint>

#define BATCH 4
#define CH    96
#define HRES  256
#define WRES  256
#define HW    65536
#define HEADS 3
#define QSCALE 0.17677669529663687f
#define WPAD  104
#define PXPAD 264
#define PX2   136
#define OUT2  132

// ---------------- mma.sync / ldmatrix helpers (sm_80+ PTX) ------------------
#define LDM_X4(r, addr) \
    asm volatile("ldmatrix.sync.aligned.m8n8.x4.shared.b16 {%0,%1,%2,%3}, [%4];" \
        : "=r"((r)[0]), "=r"((r)[1]), "=r"((r)[2]), "=r"((r)[3]) : "r"(addr))
#define LDM_X4T(r, addr) \
    asm volatile("ldmatrix.sync.aligned.m8n8.x4.trans.shared.b16 {%0,%1,%2,%3}, [%4];" \
        : "=r"((r)[0]), "=r"((r)[1]), "=r"((r)[2]), "=r"((r)[3]) : "r"(addr))
#define MMA_BF16(d, a, b) \
    asm volatile("mma.sync.aligned.m16n8k16.row.col.f32.bf16.bf16.f32 " \
        "{%0,%1,%2,%3}, {%4,%5,%6,%7}, {%8,%9}, {%0,%1,%2,%3};" \
        : "+f"((d)[0]), "+f"((d)[1]), "+f"((d)[2]), "+f"((d)[3]) \
        : "r"((a)[0]), "r"((a)[1]), "r"((a)[2]), "r"((a)[3]), \
          "r"((b)[0]), "r"((b)[1]))
#define BAR_GRP(id) asm volatile("bar.sync %0, 128;" :: "r"(id) : "memory")

__device__ __forceinline__ uint32_t smem_u32(const void* p) {
    uint32_t a;
    asm("{ .reg .u64 t; cvta.to.shared.u64 t, %1; cvt.u32.u64 %0, t; }"
        : "=r"(a) : "l"(p));
    return a;
}
__device__ __forceinline__ uint32_t packbf2(float x, float y) {
    __nv_bfloat16 bx = __float2bfloat16_rn(x);
    __nv_bfloat16 by = __float2bfloat16_rn(y);
    return ((uint32_t)__bfloat16_as_ushort(by) << 16) | __bfloat16_as_ushort(bx);
}

// ---------------- scratch ----------------------------------------------------
__device__ float g_V   [BATCH*CH*HW];
__device__ float g_conv[BATCH*CH*HW];
__device__ float g_att [BATCH*CH*HW];
__device__ float g_bias[HEADS*64*64];
__device__ __align__(16) __nv_bfloat16 g_Whi[288*WPAD];
__device__ __align__(16) __nv_bfloat16 g_Wlo[288*WPAD];
__device__ __align__(16) __nv_bfloat16 g_Phi[96*WPAD];
__device__ __align__(16) __nv_bfloat16 g_Plo[96*WPAD];

// ---------------- prep kernels ------------------------------------------------
__device__ __forceinline__ float wval(const float* Wqk, const float* Wv,
                                      int o, int k) {
    if (k >= 96) return 0.f;
    if (o < 96)       return Wqk[o*96 + k] * QSCALE;
    else if (o < 192) return Wqk[o*96 + k];
    else              return Wv[(o - 192)*96 + k];
}
__global__ void prepW_kernel(
    const float* __restrict__ Wqk, const float* __restrict__ Wv,
    const float* __restrict__ Wp)
{
    int blk = blockIdx.x, tid = threadIdx.x;
    if (blk < 117) {
        int idx = blk*256 + tid;
        if (idx >= 288*WPAD) return;
        float w = wval(Wqk, Wv, idx / WPAD, idx % WPAD);
        __nv_bfloat16 hi = __float2bfloat16_rn(w);
        g_Whi[idx] = hi;
        g_Wlo[idx] = __float2bfloat16_rn(w - __bfloat162float(hi));
    } else {
        int idx = (blk - 117)*256 + tid;
        if (idx >= 96*WPAD) return;
        int o = idx / WPAD, k = idx % WPAD;
        float w = (k < 96) ? Wp[o*96 + k] : 0.f;
        __nv_bfloat16 hi = __float2bfloat16_rn(w);
        g_Phi[idx] = hi;
        g_Plo[idx] = __float2bfloat16_rn(w - __bfloat162float(hi));
    }
}
__global__ void prepBias_kernel(
    const float* __restrict__ Wm1, const float* __restrict__ bm1,
    const float* __restrict__ Wm2, const float* __restrict__ bm2)
{
    int gid = blockIdx.x*256 + threadIdx.x;
    int n = gid >> 6, m = gid & 63;
    float r0 = (float)((n >> 3) - (m >> 3));
    float r1 = (float)((n & 7)  - (m & 7));
    r0 = copysignf(log1pf(fabsf(r0)), r0);
    r1 = copysignf(log1pf(fabsf(r1)), r1);
    float a0 = bm2[0], a1 = bm2[1], a2 = bm2[2];
    for (int j = 0; j < 256; j++) {
        float h = fmaf(r0, Wm1[j], fmaf(r1, Wm1[256 + j], bm1[j]));
        h = fmaxf(h, 0.f);
        a0 = fmaf(h, Wm2[j*3 + 0], a0);
        a1 = fmaf(h, Wm2[j*3 + 1], a1);
        a2 = fmaf(h, Wm2[j*3 + 2], a2);
    }
    g_bias[0*4096 + gid] = a0;
    g_bias[1*4096 + gid] = a1;
    g_bias[2*4096 + gid] = a2;
}

__device__ __forceinline__ int swin_label(int wh, int ww, int idx) {
    int rh = (wh == 31) ? (1 + (((idx >> 3) >= 4) ? 1 : 0)) : 0;
    int rw = (ww == 31) ? (1 + (((idx & 7)  >= 4) ? 1 : 0)) : 0;
    return rh*3 + rw;
}

// ---------------- FUSED: QKV GEMM + attention, per-group barriers -----------
__global__ __launch_bounds__(512, 1) void fused_kernel(
    const float* __restrict__ x,
    const float* __restrict__ bqk, const float* __restrict__ bv)
{
    extern __shared__ __align__(16) unsigned char dsm[];
    __nv_bfloat16* whi_s = (__nv_bfloat16*)dsm;
    __nv_bfloat16* wlo_s = whi_s + 288*WPAD;
    __nv_bfloat16* stage = wlo_s + 288*WPAD;
    __nv_bfloat16* xhi_s = stage;
    __nv_bfloat16* xlo_s = stage + 96*PXPAD;

    int tid  = threadIdx.x;
    int warp = tid >> 5, lane = tid & 31;

    {
        const uint4* s1 = (const uint4*)g_Whi; uint4* d1 = (uint4*)whi_s;
        const uint4* s2 = (const uint4*)g_Wlo; uint4* d2 = (uint4*)wlo_s;
        #pragma unroll 4
        for (int i = tid; i < 288*WPAD*2/16; i += 512) { d1[i] = s1[i]; d2[i] = s2[i]; }
    }

    int idx8 = lane & 7, quad = lane >> 3;
    int xbrow = (quad & 1)*8 + idx8;
    int xbcol = warp*16 + (quad >> 1)*8;
    int warow = (quad & 1)*8 + idx8;
    int wacol = (quad >> 1)*8;
    int rrow  = lane >> 2;
    int mloc  = (warp & 3)*16 + (lane & 3)*2;
    int sbwin = (warp >> 2)*2304;
    int awin = warp >> 2;
    int gbar = 1 + awin;
    int n0a  = (warp & 3)*16;

    for (int tile = blockIdx.x; tile < 1024; tile += gridDim.x) {
        int b   = tile >> 8;
        int rem = tile & 255;
        int wh  = rem >> 3;
        int ww0 = (rem & 7)*4;

        __syncthreads();
        for (int idx = tid; idx < 96*64; idx += 512) {
            int k = idx >> 6, g = idx & 63;
            int r = g >> 3, q = g & 7;
            int win = q >> 1, c0 = (q & 1)*4;
            int gh = (wh*8 + r + 4) & 255;
            int gw = ((ww0 + win)*8 + c0 + 4) & 255;
            float4 v = *(const float4*)&x[(size_t)(b*96 + k)*HW + gh*256 + gw];
            int px0 = win*64 + r*8 + c0;
            __nv_bfloat16 h0 = __float2bfloat16_rn(v.x);
            __nv_bfloat16 h1 = __float2bfloat16_rn(v.y);
            __nv_bfloat16 h2 = __float2bfloat16_rn(v.z);
            __nv_bfloat16 h3 = __float2bfloat16_rn(v.w);
            uint32_t hp0 = (uint32_t)__bfloat16_as_ushort(h1) << 16 | __bfloat16_as_ushort(h0);
            uint32_t hp1 = (uint32_t)__bfloat16_as_ushort(h3) << 16 | __bfloat16_as_ushort(h2);
            uint32_t lp0 = packbf2(v.x - __bfloat162float(h0), v.y - __bfloat162float(h1));
            uint32_t lp1 = packbf2(v.z - __bfloat162float(h2), v.w - __bfloat162float(h3));
            *(uint2*)&xhi_s[k*PXPAD + px0] = make_uint2(hp0, hp1);
            *(uint2*)&xlo_s[k*PXPAD + px0] = make_uint2(lp0, lp1);
        }
        __syncthreads();

        uint32_t bxh[6][4], bxl[6][4];
        #pragma unroll
        for (int ks = 0; ks < 6; ks++) {
            LDM_X4T(bxh[ks], smem_u32(&xhi_s[(ks*16 + xbrow)*PXPAD + xbcol]));
            LDM_X4T(bxl[ks], smem_u32(&xlo_s[(ks*16 + xbrow)*PXPAD + xbcol]));
        }
        __syncthreads();

        #pragma unroll 1
        for (int h = 0; h < 3; h++) {
            #pragma unroll 1
            for (int t = 0; t < 3; t++) {
                float acc[2][2][4];
                #pragma unroll
                for (int mt = 0; mt < 2; mt++)
                    #pragma unroll
                    for (int nl = 0; nl < 2; nl++)
                        #pragma unroll
                        for (int j = 0; j < 4; j++) acc[mt][nl][j] = 0.f;

                int wbase = t*96 + h*32;
                #pragma unroll 1
                for (int ks = 0; ks < 6; ks++) {
                    #pragma unroll
                    for (int mt = 0; mt < 2; mt++) {
                        int wr = (wbase + mt*16 + warow)*WPAD + ks*16 + wacol;
                        uint32_t awh[4], awl[4];
                        LDM_X4(awh, smem_u32(&whi_s[wr]));
                        MMA_BF16(acc[mt][0], awh, bxh[ks]);
                        MMA_BF16(acc[mt][0], awh, bxl[ks]);
                        MMA_BF16(acc[mt][1], awh, bxh[ks] + 2);
                        MMA_BF16(acc[mt][1], awh, bxl[ks] + 2);
                        LDM_X4(awl, smem_u32(&wlo_s[wr]));
                        MMA_BF16(acc[mt][0], awl, bxh[ks]);
                        MMA_BF16(acc[mt][1], awl, bxh[ks] + 2);
                    }
                }

                __nv_bfloat16* sth = stage + (t*2    )*9216;
                __nv_bfloat16* stl = stage + (t*2 + 1)*9216;
                #pragma unroll
                for (int mt = 0; mt < 2; mt++) {
                    int d0 = mt*16 + rrow;
                    float bb0, bb1;
                    if (t == 0)      { bb0 = bqk[h*32 + d0]*QSCALE;  bb1 = bqk[h*32 + d0 + 8]*QSCALE; }
                    else if (t == 1) { bb0 = bqk[96 + h*32 + d0];    bb1 = bqk[96 + h*32 + d0 + 8]; }
                    else             { bb0 = bv[h*32 + d0];          bb1 = bv[h*32 + d0 + 8]; }
                    #pragma unroll
                    for (int nl = 0; nl < 2; nl++) {
                        int m = mloc + nl*8;
                        float v0 = acc[mt][nl][0] + bb0;
                        float v1 = acc[mt][nl][1] + bb0;
                        float v2 = acc[mt][nl][2] + bb1;
                        float v3 = acc[mt][nl][3] + bb1;
                        __nv_bfloat16 e0 = __float2bfloat16_rn(v0);
                        __nv_bfloat16 e1 = __float2bfloat16_rn(v1);
                        __nv_bfloat16 e2 = __float2bfloat16_rn(v2);
                        __nv_bfloat16 e3 = __float2bfloat16_rn(v3);
                        *(uint32_t*)&sth[sbwin + d0*72 + m] =
                            ((uint32_t)__bfloat16_as_ushort(e1) << 16) | __bfloat16_as_ushort(e0);
                        *(uint32_t*)&sth[sbwin + (d0 + 8)*72 + m] =
                            ((uint32_t)__bfloat16_as_ushort(e3) << 16) | __bfloat16_as_ushort(e2);
                        *(uint32_t*)&stl[sbwin + d0*72 + m] =
                            packbf2(v0 - __bfloat162float(e0), v1 - __bfloat162float(e1));
                        *(uint32_t*)&stl[sbwin + (d0 + 8)*72 + m] =
                            packbf2(v2 - __bfloat162float(e2), v3 - __bfloat162float(e3));
                        if (t == 2) {
                            int px = warp*16 + nl*8 + (lane & 3)*2;
                            int g = px & 63, winp = px >> 6;
                            int r = g >> 3, c = g & 7;
                            int gh = (wh*8 + r + 4) & 255;
                            int gw = ((ww0 + winp)*8 + c + 4) & 255;
                            size_t cb = (size_t)(b*96 + h*32);
                            *(float2*)&g_V[(cb + d0)*HW + gh*256 + gw]     = make_float2(v0, v1);
                            *(float2*)&g_V[(cb + d0 + 8)*HW + gh*256 + gw] = make_float2(v2, v3);
                        }
                    }
                }
            }
            BAR_GRP(gbar);   // group-local: staging complete for head h

            {
                const __nv_bfloat16* sqh = stage + 0*9216 + awin*2304;
                const __nv_bfloat16* sql = stage + 1*9216 + awin*2304;
                const __nv_bfloat16* skh = stage + 2*9216 + awin*2304;
                const __nv_bfloat16* skl = stage + 3*9216 + awin*2304;
                const __nv_bfloat16* svh = stage + 4*9216 + awin*2304;
                const __nv_bfloat16* svl = stage + 5*9216 + awin*2304;

                uint32_t aqh[2][4], aql[2][4];
                int krow2 = (quad >> 1)*8 + idx8;
                int apx2  = n0a + (quad & 1)*8;
                #pragma unroll
                for (int ks = 0; ks < 2; ks++) {
                    LDM_X4T(aqh[ks], smem_u32(&sqh[(ks*16 + krow2)*72 + apx2]));
                    LDM_X4T(aql[ks], smem_u32(&sql[(ks*16 + krow2)*72 + apx2]));
                }

                float accq[8][4];
                #pragma unroll
                for (int j = 0; j < 8; j++)
                    #pragma unroll
                    for (int r = 0; r < 4; r++) accq[j][r] = 0.f;

                {
                    int browt = (quad & 1)*8 + idx8;
                    int bcolt = (quad >> 1)*8;
                    #pragma unroll
                    for (int ks = 0; ks < 2; ks++) {
                        #pragma unroll
                        for (int jp = 0; jp < 4; jp++) {
                            uint32_t off = (ks*16 + browt)*72 + jp*16 + bcolt;
                            uint32_t bh[4], bl[4];
                            LDM_X4T(bh, smem_u32(&skh[off]));
                            MMA_BF16(accq[2*jp    ], aqh[ks], bh);
                            MMA_BF16(accq[2*jp    ], aql[ks], bh);
                            MMA_BF16(accq[2*jp + 1], aqh[ks], bh + 2);
                            MMA_BF16(accq[2*jp + 1], aql[ks], bh + 2);
                            LDM_X4T(bl, smem_u32(&skl[off]));
                            MMA_BF16(accq[2*jp    ], aqh[ks], bl);
                            MMA_BF16(accq[2*jp + 1], aqh[ks], bl + 2);
                        }
                    }
                }

                int ww_abs = ww0 + awin;
                bool masked = (wh == 31) || (ww_abs == 31);
                int n1 = n0a + (lane >> 2);
                int n2 = n1 + 8;
                int mq = (lane & 3)*2;
                int labn1 = 0, labn2 = 0;
                if (masked) { labn1 = swin_label(wh, ww_abs, n1); labn2 = swin_label(wh, ww_abs, n2); }

                const float* bb = g_bias + h*4096;
                float lsum1 = 0.f, lsum2 = 0.f;
                uint32_t pahi[4][4], palo[4][4];

                #pragma unroll
                for (int j = 0; j < 8; j++) {
                    int m0 = j*8 + mq;
                    float2 b1 = *(const float2*)&bb[n1*64 + m0];
                    float2 b2 = *(const float2*)&bb[n2*64 + m0];
                    float p0 = __expf(accq[j][0] + b1.x);
                    float p1 = __expf(accq[j][1] + b1.y);
                    float p2 = __expf(accq[j][2] + b2.x);
                    float p3 = __expf(accq[j][3] + b2.y);
                    if (masked) {
                        int lm0 = swin_label(wh, ww_abs, m0);
                        int lm1 = swin_label(wh, ww_abs, m0 + 1);
                        if (lm0 != labn1) p0 = 0.f;
                        if (lm1 != labn1) p1 = 0.f;
                        if (lm0 != labn2) p2 = 0.f;
                        if (lm1 != labn2) p3 = 0.f;
                    }
                    lsum1 += p0 + p1;
                    lsum2 += p2 + p3;
                    int s = j >> 1, half = (j & 1)*2;
                    __nv_bfloat16 e0 = __float2bfloat16_rn(p0);
                    __nv_bfloat16 e1 = __float2bfloat16_rn(p1);
                    __nv_bfloat16 e2 = __float2bfloat16_rn(p2);
                    __nv_bfloat16 e3 = __float2bfloat16_rn(p3);
                    pahi[s][half]     = ((uint32_t)__bfloat16_as_ushort(e1) << 16) | __bfloat16_as_ushort(e0);
                    pahi[s][half + 1] = ((uint32_t)__bfloat16_as_ushort(e3) << 16) | __bfloat16_as_ushort(e2);
                    palo[s][half]     = packbf2(p0 - __bfloat162float(e0), p1 - __bfloat162float(e1));
                    palo[s][half + 1] = packbf2(p2 - __bfloat162float(e2), p3 - __bfloat162float(e3));
                }
                lsum1 += __shfl_xor_sync(0xFFFFFFFF, lsum1, 1);
                lsum1 += __shfl_xor_sync(0xFFFFFFFF, lsum1, 2);
                lsum2 += __shfl_xor_sync(0xFFFFFFFF, lsum2, 1);
                lsum2 += __shfl_xor_sync(0xFFFFFFFF, lsum2, 2);
                float inv1 = 1.f / lsum1, inv2 = 1.f / lsum2;

                float o[4][4];
                #pragma unroll
                for (int t = 0; t < 4; t++)
                    #pragma unroll
                    for (int r = 0; r < 4; r++) o[t][r] = 0.f;

                {
                    int vrow = (quad >> 1)*8 + idx8;
                    int vcol = (quad & 1)*8;
                    #pragma unroll
                    for (int s = 0; s < 4; s++) {
                        #pragma unroll
                        for (int tp = 0; tp < 2; tp++) {
                            uint32_t off = (tp*16 + vrow)*72 + s*16 + vcol;
                            uint32_t bh[4], bl[4];
                            LDM_X4(bh, smem_u32(&svh[off]));
                            MMA_BF16(o[2*tp    ], pahi[s], bh);
                            MMA_BF16(o[2*tp    ], palo[s], bh);
                            MMA_BF16(o[2*tp + 1], pahi[s], bh + 2);
                            MMA_BF16(o[2*tp + 1], palo[s], bh + 2);
                            LDM_X4(bl, smem_u32(&svl[off]));
                            MMA_BF16(o[2*tp    ], pahi[s], bl);
                            MMA_BF16(o[2*tp + 1], pahi[s], bl + 2);
                        }
                    }
                }

                int r1 = n1 >> 3, c1 = n1 & 7;
                int r2 = n2 >> 3, c2 = n2 & 7;
                int off1 = (((wh << 3) + r1 + 4) & 255)*256 + (((ww_abs << 3) + c1 + 4) & 255);
                int off2 = (((wh << 3) + r2 + 4) & 255)*256 + (((ww_abs << 3) + c2 + 4) & 255);
                size_t cb = (size_t)(b*96 + h*32 + mq)*HW;
                #pragma unroll
                for (int t = 0; t < 4; t++) {
                    size_t cbase = cb + (size_t)(t*8)*HW;
                    g_att[cbase      + off1] = o[t][0]*inv1;
                    g_att[cbase + HW + off1] = o[t][1]*inv1;
                    g_att[cbase      + off2] = o[t][2]*inv2;
                    g_att[cbase + HW + off2] = o[t][3]*inv2;
                }
            }
            BAR_GRP(gbar);   // group-local: attention reads done before next head
        }
    }
}

// ---------------- kernel DW: depthwise 5x5, 8 px/thread (FIXED taps) --------
__global__ __launch_bounds__(256) void dw_kernel(const float* __restrict__ Wdw,
                                                 const float* __restrict__ bdw)
{
    __shared__ __align__(16) float s[36][76];   // rows h0-2..+33, cols w0-4..w0+67
    __shared__ float wk[25];

    int blk  = blockIdx.x;
    int img  = blk >> 5;
    int tile = blk & 31;
    int c    = img % 96;
    int h0   = (tile >> 2) << 5;
    int w0   = (tile & 3) << 6;
    int tid  = threadIdx.x;

    if (tid < 25) wk[tid] = Wdw[c*25 + tid];
    const float* vimg = g_V + (size_t)img * HW;

    bool border = (h0 == 0) || (h0 == 224) || (w0 == 0) || (w0 == 192);
    if (!border) {
        const float* src = vimg + (h0 - 2)*256 + (w0 - 4);
        for (int idx = tid; idx < 36*18; idx += 256) {
            int r = idx / 18, c4 = idx - r*18;
            *(float4*)&s[r][c4*4] = *(const float4*)&src[r*256 + c4*4];
        }
    } else {
        for (int idx = tid; idx < 36*72; idx += 256) {
            int r  = idx / 72, cc = idx % 72;
            int hh = h0 - 2 + r;  hh = (hh < 0) ? -hh : ((hh > 255) ? 510 - hh : hh);
            int wq = w0 - 4 + cc; wq = (wq < 0) ? -wq : ((wq > 255) ? 510 - wq : wq);
            s[r][cc] = vimg[hh*256 + wq];
        }
    }
    __syncthreads();

    int y   = tid >> 3;
    int xq0 = (tid & 7) * 8;
    float b0 = bdw[c];
    float acc[8];
    #pragma unroll
    for (int j = 0; j < 8; j++) acc[j] = b0;
    #pragma unroll
    for (int i = 0; i < 5; i++) {
        float4 fa = *(const float4*)&s[y + i][xq0];
        float4 fb = *(const float4*)&s[y + i][xq0 + 4];
        float4 fc = *(const float4*)&s[y + i][xq0 + 8];
        float4 fd = *(const float4*)&s[y + i][xq0 + 12];
        float f[16] = {fa.x, fa.y, fa.z, fa.w, fb.x, fb.y, fb.z, fb.w,
                       fc.x, fc.y, fc.z, fc.w, fd.x, fd.y, fd.z, fd.w};
        #pragma unroll
        for (int jj = 0; jj < 5; jj++) {
            float wv = wk[i*5 + jj];
            #pragma unroll
            for (int j = 0; j < 8; j++)
                acc[j] = fmaf(f[j + jj + 2], wv, acc[j]);   // taps centered: +2
        }
    }
    float* op = &g_conv[(size_t)img*HW + (h0 + y)*256 + (w0 + xq0)];
    *(float4*)op       = make_float4(acc[0], acc[1], acc[2], acc[3]);
    *(float4*)(op + 4) = make_float4(acc[4], acc[5], acc[6], acc[7]);
}

// ---------------- kernel D: HMMA final GEMM, 2 blocks/SM ---------------------
__global__ __launch_bounds__(256, 2) void final_mma_kernel(
    const float* __restrict__ bp, float* __restrict__ outp)
{
    extern __shared__ __align__(16) unsigned char dsm[];
    __nv_bfloat16* phi_s = (__nv_bfloat16*)dsm;
    __nv_bfloat16* plo_s = phi_s + 96*WPAD;
    __nv_bfloat16* xhi_s = plo_s + 96*WPAD;
    __nv_bfloat16* xlo_s = xhi_s + 96*PX2;
    float* out_s = (float*)xhi_s;

    int tid  = threadIdx.x;
    int warp = tid >> 5, lane = tid & 31;

    {
        const uint4* s1 = (const uint4*)g_Phi; uint4* d1 = (uint4*)phi_s;
        const uint4* s2 = (const uint4*)g_Plo; uint4* d2 = (uint4*)plo_s;
        #pragma unroll 4
        for (int i = tid; i < 96*WPAD*2/16; i += 256) { d1[i] = s1[i]; d2[i] = s2[i]; }
    }

    int idx8 = lane & 7, quad = lane >> 3;
    int krow = (quad >> 1)*8 + idx8;
    int apxb = warp*16 + (quad & 1)*8;
    int brow4 = lane & 7;
    int bcol4 = ((lane >> 3) & 1)*8;
    int brsel = (lane >> 4) & 1;
    int pq   = tid & 31;
    int p0   = pq*4;
    int c0   = tid >> 5;
    int orow = warp*16 + (lane >> 2);
    int oc   = (lane & 3)*2;

    for (int tile = blockIdx.x; tile < 2048; tile += gridDim.x) {
        int b   = tile >> 9;
        int hw0 = (tile & 511) << 7;

        __syncthreads();
        for (int idx = tid; idx < 96*32; idx += 256) {
            int k = idx >> 5, pg = idx & 31;
            size_t gi = (size_t)(b*96 + k)*HW + hw0 + pg*4;
            float4 a = *(const float4*)&g_conv[gi];
            float4 c4 = *(const float4*)&g_att[gi];
            float4 v = make_float4(a.x + c4.x, a.y + c4.y, a.z + c4.z, a.w + c4.w);
            __nv_bfloat16 h0 = __float2bfloat16_rn(v.x);
            __nv_bfloat16 h1 = __float2bfloat16_rn(v.y);
            __nv_bfloat16 h2 = __float2bfloat16_rn(v.z);
            __nv_bfloat16 h3 = __float2bfloat16_rn(v.w);
            uint32_t hp0 = (uint32_t)__bfloat16_as_ushort(h1) << 16 | __bfloat16_as_ushort(h0);
            uint32_t hp1 = (uint32_t)__bfloat16_as_ushort(h3) << 16 | __bfloat16_as_ushort(h2);
            uint32_t lp0 = packbf2(v.x - __bfloat162float(h0), v.y - __bfloat162float(h1));
            uint32_t lp1 = packbf2(v.z - __bfloat162float(h2), v.w - __bfloat162float(h3));
            *(uint2*)&xhi_s[k*PX2 + pg*4] = make_uint2(hp0, hp1);
            *(uint2*)&xlo_s[k*PX2 + pg*4] = make_uint2(lp0, lp1);
        }
        __syncthreads();

        uint32_t ahi[6][4], alo[6][4];
        #pragma unroll
        for (int ks = 0; ks < 6; ks++) {
            LDM_X4T(ahi[ks], smem_u32(&xhi_s[(ks*16 + krow)*PX2 + apxb]));
            LDM_X4T(alo[ks], smem_u32(&xlo_s[(ks*16 + krow)*PX2 + apxb]));
        }
        __syncthreads();

        float acc[12][4];
        #pragma unroll
        for (int nt = 0; nt < 12; nt++)
            #pragma unroll
            for (int j = 0; j < 4; j++) acc[nt][j] = 0.f;

        #pragma unroll 1
        for (int ks = 0; ks < 6; ks++) {
            #pragma unroll
            for (int ntp = 0; ntp < 6; ntp++) {
                int wrow = ((2*ntp + brsel)*8 + brow4)*WPAD + ks*16 + bcol4;
                uint32_t bh[4], bl[4];
                LDM_X4(bh, smem_u32(&phi_s[wrow]));
                MMA_BF16(acc[2*ntp    ], ahi[ks], bh);
                MMA_BF16(acc[2*ntp    ], alo[ks], bh);
                MMA_BF16(acc[2*ntp + 1], ahi[ks], bh + 2);
                MMA_BF16(acc[2*ntp + 1], alo[ks], bh + 2);
                LDM_X4(bl, smem_u32(&plo_s[wrow]));
                MMA_BF16(acc[2*ntp    ], ahi[ks], bl);
                MMA_BF16(acc[2*ntp + 1], ahi[ks], bl + 2);
            }
        }

        #pragma unroll
        for (int nt = 0; nt < 12; nt++) {
            out_s[(nt*8 + oc    )*OUT2 + orow    ] = acc[nt][0];
            out_s[(nt*8 + oc + 1)*OUT2 + orow    ] = acc[nt][1];
            out_s[(nt*8 + oc    )*OUT2 + orow + 8] = acc[nt][2];
            out_s[(nt*8 + oc + 1)*OUT2 + orow + 8] = acc[nt][3];
        }
        __syncthreads();

        #pragma unroll 1
        for (int j = 0; j < 12; j++) {
            int c = c0 + j*8;
            float4 v4 = *(const float4*)&out_s[c*OUT2 + p0];
            float bo = bp[c];
            *(float4*)&outp[(size_t)(b*96 + c)*HW + hw0 + p0] =
                make_float4(v4.x + bo, v4.y + bo, v4.z + bo, v4.w + bo);
        }
        __syncthreads();
    }
}

// ---------------- launch ------------------------------------------------------
extern "C" void kernel_launch(void* const* d_in, const int* in_sizes, int n_in,
                              void* d_out, int out_size)
{
    const float* x   = (const float*)d_in[0];
    const float* Wv  = (const float*)d_in[1];
    const float* bv  = (const float*)d_in[2];
    const float* Wqk = (const float*)d_in[3];
    const float* bqk = (const float*)d_in[4];
    const float* Wm1 = (const float*)d_in[5];
    const float* bm1 = (const float*)d_in[6];
    const float* Wm2 = (const float*)d_in[7];
    const float* bm2 = (const float*)d_in[8];
    const float* Wdw = (const float*)d_in[9];
    const float* bdw = (const float*)d_in[10];
    const float* Wp  = (const float*)d_in[11];
    const float* bp  = (const float*)d_in[12];
    float* outp = (float*)d_out;

    const int FUSED_SMEM = 288*WPAD*2*2 + 6*9216*2;            // 230400 B
    const int FIN_SMEM   = 96*WPAD*2*2 + 96*PX2*2*2;           // 92160 B
    cudaFuncSetAttribute(fused_kernel,
                         cudaFuncAttributeMaxDynamicSharedMemorySize, FUSED_SMEM);
    cudaFuncSetAttribute(final_mma_kernel,
                         cudaFuncAttributeMaxDynamicSharedMemorySize, FIN_SMEM);

    prepW_kernel   <<<156, 256>>>(Wqk, Wv, Wp);
    prepBias_kernel<<<16, 256>>>(Wm1, bm1, Wm2, bm2);
    fused_kernel   <<<148, 512, FUSED_SMEM>>>(x, bqk, bv);
    dw_kernel      <<<12288, 256>>>(Wdw, bdw);                // profiled slot 4
    final_mma_kernel<<<296, 256, FIN_SMEM>>>(bp, outp);
}